// round 1
// baseline (speedup 1.0000x reference)
#include <cuda_runtime.h>
#include <cuda_bf16.h>
#include <math.h>

#define B_    4
#define S_V_  768
#define S_E_  64
#define S_    832
#define W_V_  2048
#define W_E_  1024
#define H_    8
#define DH_   256
#define MLPV_ 16384
#define MLPE_ 4096
#define EPS_  1e-6f
#define SCALE_ 0.0625f  // 256^-0.5

// ---------------- scratch (device globals; no allocations) ----------------
__device__ float g_hv   [B_*S_V_*W_V_];       // rms1 output vlm / reused for nv
__device__ float g_he   [B_*S_E_*W_E_];       // rms1 output exp / reused for ne
__device__ float g_mod1 [B_*3*W_E_];
__device__ float g_mod2 [B_*3*W_E_];
__device__ float g_q    [(long long)B_*S_*H_*DH_];   // (B,S,H,DH)
__device__ float g_qt   [(long long)B_*H_*S_*DH_];   // (B,H,S,DH)
__device__ float g_k    [B_*S_*DH_];
__device__ float g_v    [B_*S_*DH_];
__device__ float g_logits[(long long)B_*H_*S_*S_];   // logits / probs in-place
__device__ float g_attnt[(long long)B_*H_*S_*DH_];
__device__ float g_attn [(long long)B_*S_*H_*DH_];
__device__ float g_hv1  [B_*S_V_*W_V_];
__device__ float g_he1  [B_*S_E_*W_E_];
__device__ float g_mg   [(long long)B_*S_V_*MLPV_];
__device__ float g_mu   [(long long)B_*S_V_*MLPV_];
__device__ float g_tmp  [B_*S_V_*W_V_];
__device__ float g_eg   [B_*S_E_*MLPE_];
__device__ float g_eu   [B_*S_E_*MLPE_];
__device__ float g_etmp [B_*S_E_*W_E_];

// ---------------- generic batched fp32 GEMM: C = A * B(^T) ----------------
// A: (M,K) row-major, lda=K. TB==0: B (K,N) row-major. TB==1: B (N,K) row-major.
// Batch z: A += z*sA, B += (z/bInner)*sB, C += z*sC.
// Requires: K % 8 == 0, N % 4 == 0 (true for all call sites).
template<int TB>
__global__ __launch_bounds__(256)
void gemm128(const float* __restrict__ A, const float* __restrict__ Bm,
             float* __restrict__ C, int M, int N, int K,
             long long sA, long long sB, long long sC, int bInner)
{
    int z = blockIdx.z;
    A  += (long long)z * sA;
    Bm += (long long)(z / bInner) * sB;
    C  += (long long)z * sC;

    __shared__ float As[8][128];
    __shared__ float Bs[8][128];

    int tid = threadIdx.x;
    int bm = blockIdx.y * 128, bn = blockIdx.x * 128;
    int arow = tid >> 1;            // 0..127
    int acol = (tid & 1) * 4;       // 0 or 4
    int ty = tid >> 4, tx = tid & 15;

    float acc[8][8];
#pragma unroll
    for (int i = 0; i < 8; i++)
#pragma unroll
        for (int j = 0; j < 8; j++) acc[i][j] = 0.f;

    for (int kt = 0; kt < K; kt += 8) {
        // load A tile (128 x 8), store transposed
        {
            int gm = bm + arow;
            float4 va = make_float4(0.f, 0.f, 0.f, 0.f);
            if (gm < M) va = *(const float4*)(A + (long long)gm * K + kt + acol);
            As[acol + 0][arow] = va.x; As[acol + 1][arow] = va.y;
            As[acol + 2][arow] = va.z; As[acol + 3][arow] = va.w;
        }
        if (TB) {  // B is (N,K): tile 128 n-rows x 8 k-cols
            int gn = bn + arow;
            float4 vb = make_float4(0.f, 0.f, 0.f, 0.f);
            if (gn < N) vb = *(const float4*)(Bm + (long long)gn * K + kt + acol);
            Bs[acol + 0][arow] = vb.x; Bs[acol + 1][arow] = vb.y;
            Bs[acol + 2][arow] = vb.z; Bs[acol + 3][arow] = vb.w;
        } else {   // B is (K,N): tile 8 k-rows x 128 n-cols
            int gk = kt + (tid >> 5);
            int gn = bn + (tid & 31) * 4;
            float4 vb = make_float4(0.f, 0.f, 0.f, 0.f);
            if (gn < N) vb = *(const float4*)(Bm + (long long)gk * N + gn);
            *(float4*)&Bs[tid >> 5][(tid & 31) * 4] = vb;
        }
        __syncthreads();
#pragma unroll
        for (int k = 0; k < 8; k++) {
            float a[8], b[8];
            *(float4*)&a[0] = *(float4*)&As[k][ty * 8];
            *(float4*)&a[4] = *(float4*)&As[k][ty * 8 + 4];
            *(float4*)&b[0] = *(float4*)&Bs[k][tx * 8];
            *(float4*)&b[4] = *(float4*)&Bs[k][tx * 8 + 4];
#pragma unroll
            for (int i = 0; i < 8; i++)
#pragma unroll
                for (int j = 0; j < 8; j++) acc[i][j] += a[i] * b[j];
        }
        __syncthreads();
    }
#pragma unroll
    for (int i = 0; i < 8; i++) {
        int gm = bm + ty * 8 + i;
        if (gm >= M) continue;
#pragma unroll
        for (int j = 0; j < 8; j += 4) {
            int gn = bn + tx * 8 + j;
            if (gn < N) {  // N%4==0 and gn%4==0 => full float4 in range
                float4 v = make_float4(acc[i][j], acc[i][j+1], acc[i][j+2], acc[i][j+3]);
                *(float4*)(C + (long long)gm * N + gn) = v;
            }
        }
    }
}

// ---------------- row kernels ----------------
__device__ __forceinline__ float blockReduceSum(float v) {
    __shared__ float red[256];
    int t = threadIdx.x;
    red[t] = v; __syncthreads();
    for (int s = 128; s > 0; s >>= 1) {
        if (t < s) red[t] += red[t + s];
        __syncthreads();
    }
    return red[0];
}

// out = rms(x) * (1 + w)
__global__ void rms_scale(const float* __restrict__ x, const float* __restrict__ w,
                          float* __restrict__ out, int W)
{
    long long base = (long long)blockIdx.x * W;
    float ss = 0.f;
    for (int c = threadIdx.x; c < W; c += 256) { float t = x[base + c]; ss += t * t; }
    float tot = blockReduceSum(ss);
    float inv = rsqrtf(tot / (float)W + EPS_);
    for (int c = threadIdx.x; c < W; c += 256)
        out[base + c] = x[base + c] * inv * (1.f + w[c]);
}

// out = rms(x) * (1 + mod[b, c]) + mod[b, W + c]
__global__ void rms_mod(const float* __restrict__ x, const float* __restrict__ mod,
                        float* __restrict__ out, int W, int rowsPerB)
{
    long long base = (long long)blockIdx.x * W;
    int b = blockIdx.x / rowsPerB;
    const float* m = mod + (long long)b * 3 * W;
    float ss = 0.f;
    for (int c = threadIdx.x; c < W; c += 256) { float t = x[base + c]; ss += t * t; }
    float tot = blockReduceSum(ss);
    float inv = rsqrtf(tot / (float)W + EPS_);
    for (int c = threadIdx.x; c < W; c += 256)
        out[base + c] = x[base + c] * inv * (1.f + m[c]) + m[W + c];
}

// mod = cond @ W + bias   (B x W_E) @ (W_E x 3W_E)
__global__ void modmm(const float* __restrict__ cond, const float* __restrict__ W,
                      const float* __restrict__ bias, float* __restrict__ out)
{
    int idx = blockIdx.x * blockDim.x + threadIdx.x;
    int NT = 3 * W_E_;
    if (idx >= B_ * NT) return;
    int b = idx / NT, c = idx % NT;
    float s = bias[c];
    const float* cv = cond + b * W_E_;
    for (int k = 0; k < W_E_; k++) s += cv[k] * W[(long long)k * NT + c];
    out[idx] = s;
}

// in-place RoPE on x laid out (B,S,nh,256)
__global__ void rope_kernel(float* __restrict__ x, const int* __restrict__ pos, int nh)
{
    int idx = blockIdx.x * blockDim.x + threadIdx.x;
    int total = B_ * S_ * nh * 128;
    if (idx >= total) return;
    int d = idx & 127;
    int h = (idx >> 7) % nh;
    int s = (idx / (128 * nh)) % S_;
    int b = idx / (128 * nh * S_);
    float p = (float)pos[b * S_ + s];
    float ang = p * powf(10000.f, -(float)(2 * d) / 256.f);
    float sn, cs; sincosf(ang, &sn, &cs);
    float* base = x + (((long long)(b * S_ + s) * nh + h) << 8);
    float x1 = base[d], x2 = base[d + 128];
    base[d]       = x1 * cs - x2 * sn;
    base[d + 128] = x2 * cs + x1 * sn;
}

// (B,S,H,D) -> (B,H,S,D)
__global__ void q_to_bhsd(const float* __restrict__ q, float* __restrict__ qt)
{
    long long idx = (long long)blockIdx.x * blockDim.x + threadIdx.x;
    long long total = (long long)B_ * H_ * S_ * DH_;
    if (idx >= total) return;
    int d = idx & 255;
    int s = (idx >> 8) % S_;
    int h = (idx / ((long long)256 * S_)) % H_;
    int b = (int)(idx / ((long long)256 * S_ * H_));
    qt[idx] = q[(((long long)(b * S_ + s) * H_ + h) << 8) + d];
}

// (B,H,S,D) -> (B,S,H,D)
__global__ void bhsd_to_bshd(const float* __restrict__ a, float* __restrict__ o)
{
    long long idx = (long long)blockIdx.x * blockDim.x + threadIdx.x;
    long long total = (long long)B_ * H_ * S_ * DH_;
    if (idx >= total) return;
    int d = idx & 255;
    int h = (idx >> 8) % H_;
    int s = (idx / ((long long)256 * H_)) % S_;
    int b = (int)(idx / ((long long)256 * H_ * S_));
    o[idx] = a[(((long long)(b * H_ + h) * S_ + s) << 8) + d];
}

// softmax over last axis with scale & mask, in-place. grid = B*H*S rows.
__global__ void softmax_mask(float* __restrict__ logits, const float* __restrict__ mask)
{
    int rowid = blockIdx.x;
    int b = rowid / (H_ * S_);
    int q = rowid % S_;
    float* row = logits + (long long)rowid * S_;
    const float* m = mask + ((long long)b * S_ + q) * S_;
    int t = threadIdx.x;
    float v[4];
    float mx = -1e30f;
#pragma unroll
    for (int j = 0; j < 4; j++) {
        int i = t + j * 256;
        v[j] = -1e30f;
        if (i < S_) { v[j] = row[i] * SCALE_ + m[i]; mx = fmaxf(mx, v[j]); }
    }
    __shared__ float red[256];
    red[t] = mx; __syncthreads();
    for (int s = 128; s > 0; s >>= 1) { if (t < s) red[t] = fmaxf(red[t], red[t + s]); __syncthreads(); }
    mx = red[0]; __syncthreads();
    float sum = 0.f;
#pragma unroll
    for (int j = 0; j < 4; j++) {
        int i = t + j * 256;
        if (i < S_) { v[j] = __expf(v[j] - mx); sum += v[j]; }
    }
    red[t] = sum; __syncthreads();
    for (int s = 128; s > 0; s >>= 1) { if (t < s) red[t] += red[t + s]; __syncthreads(); }
    float inv = 1.f / red[0];
#pragma unroll
    for (int j = 0; j < 4; j++) {
        int i = t + j * 256;
        if (i < S_) row[i] = v[j] * inv;
    }
}

// y += x
__global__ void ew_add(float* __restrict__ y, const float* __restrict__ x, int n)
{
    int i = blockIdx.x * blockDim.x + threadIdx.x;
    if (i < n) y[i] += x[i];
}

// y = x + y * mod[b, 2W + c]   (exp residual with gate), W = W_E
__global__ void ew_gate_res(float* __restrict__ y, const float* __restrict__ x,
                            const float* __restrict__ mod, int n)
{
    int i = blockIdx.x * blockDim.x + threadIdx.x;
    if (i >= n) return;
    int b = i / (S_E_ * W_E_);
    int c = i % W_E_;
    float g = mod[(long long)b * 3 * W_E_ + 2 * W_E_ + c];
    y[i] = x[i] + y[i] * g;
}

// g = gelu_tanh(g) * u
__global__ void gelu_mul(float* __restrict__ g, const float* __restrict__ u, long long n)
{
    long long i = (long long)blockIdx.x * blockDim.x + threadIdx.x;
    if (i >= n) return;
    float x = g[i];
    float t = 0.5f * x * (1.f + tanhf(0.7978845608028654f * (x + 0.044715f * x * x * x)));
    g[i] = t * u[i];
}

// out = a + b
__global__ void ew_final_v(float* __restrict__ out, const float* __restrict__ a,
                           const float* __restrict__ b, int n)
{
    int i = blockIdx.x * blockDim.x + threadIdx.x;
    if (i < n) out[i] = a[i] + b[i];
}

// out = a + b * mod[bb, 2W + c]
__global__ void ew_final_e(float* __restrict__ out, const float* __restrict__ a,
                           const float* __restrict__ b, const float* __restrict__ mod, int n)
{
    int i = blockIdx.x * blockDim.x + threadIdx.x;
    if (i >= n) return;
    int bb = i / (S_E_ * W_E_);
    int c = i % W_E_;
    float g = mod[(long long)bb * 3 * W_E_ + 2 * W_E_ + c];
    out[i] = a[i] + b[i] * g;
}

// ---------------- host launch ----------------
#define GETSYM(var, sym) do { void* p__; cudaGetSymbolAddress(&p__, sym); var = (float*)p__; } while (0)

extern "C" void kernel_launch(void* const* d_in, const int* in_sizes, int n_in,
                              void* d_out, int out_size)
{
    const float *embeds_vlm, *embeds_exp, *cond, *attn_mask;
    const int* pos;
    const float *vlm_ln1_w, *vlm_ln2_w, *vlm_q_w, *vlm_k_w, *vlm_v_w, *vlm_o_w;
    const float *vlm_gate_w, *vlm_up_w, *vlm_down_w;
    const float *exp_ln1_dw, *exp_ln1_db, *exp_ln2_dw, *exp_ln2_db;
    const float *exp_q_w, *exp_k_w, *exp_v_w, *exp_o_w, *exp_gate_w, *exp_up_w, *exp_down_w;

    if (in_sizes[3] == B_ * S_) {
        // reference-signature order
        embeds_vlm = (const float*)d_in[0];  embeds_exp = (const float*)d_in[1];
        cond       = (const float*)d_in[2];  pos        = (const int*)  d_in[3];
        attn_mask  = (const float*)d_in[4];
        vlm_ln1_w  = (const float*)d_in[5];  vlm_ln2_w  = (const float*)d_in[6];
        vlm_q_w    = (const float*)d_in[7];  vlm_k_w    = (const float*)d_in[8];
        vlm_v_w    = (const float*)d_in[9];  vlm_o_w    = (const float*)d_in[10];
        vlm_gate_w = (const float*)d_in[11]; vlm_up_w   = (const float*)d_in[12];
        vlm_down_w = (const float*)d_in[13];
        exp_ln1_dw = (const float*)d_in[14]; exp_ln1_db = (const float*)d_in[15];
        exp_ln2_dw = (const float*)d_in[16]; exp_ln2_db = (const float*)d_in[17];
        exp_q_w    = (const float*)d_in[18]; exp_k_w    = (const float*)d_in[19];
        exp_v_w    = (const float*)d_in[20]; exp_o_w    = (const float*)d_in[21];
        exp_gate_w = (const float*)d_in[22]; exp_up_w   = (const float*)d_in[23];
        exp_down_w = (const float*)d_in[24];
    } else {
        // setup_inputs dict order
        embeds_vlm = (const float*)d_in[0];  embeds_exp = (const float*)d_in[1];
        cond       = (const float*)d_in[2];
        vlm_ln1_w  = (const float*)d_in[3];  vlm_ln2_w  = (const float*)d_in[4];
        vlm_q_w    = (const float*)d_in[5];  vlm_k_w    = (const float*)d_in[6];
        vlm_v_w    = (const float*)d_in[7];  vlm_o_w    = (const float*)d_in[8];
        vlm_gate_w = (const float*)d_in[9];  vlm_up_w   = (const float*)d_in[10];
        vlm_down_w = (const float*)d_in[11];
        exp_ln1_dw = (const float*)d_in[12]; exp_ln1_db = (const float*)d_in[13];
        exp_ln2_dw = (const float*)d_in[14]; exp_ln2_db = (const float*)d_in[15];
        exp_q_w    = (const float*)d_in[16]; exp_k_w    = (const float*)d_in[17];
        exp_v_w    = (const float*)d_in[18]; exp_o_w    = (const float*)d_in[19];
        exp_gate_w = (const float*)d_in[20]; exp_up_w   = (const float*)d_in[21];
        exp_down_w = (const float*)d_in[22];
        pos        = (const int*)  d_in[23];
        attn_mask  = (const float*)d_in[24];
    }

    float *hv, *he, *mod1, *mod2, *q, *qt, *k, *v, *logits, *attnt, *attn;
    float *hv1, *he1, *mg, *mu, *tmp, *eg, *eu, *etmp;
    GETSYM(hv, g_hv);   GETSYM(he, g_he);   GETSYM(mod1, g_mod1); GETSYM(mod2, g_mod2);
    GETSYM(q, g_q);     GETSYM(qt, g_qt);   GETSYM(k, g_k);       GETSYM(v, g_v);
    GETSYM(logits, g_logits); GETSYM(attnt, g_attnt); GETSYM(attn, g_attn);
    GETSYM(hv1, g_hv1); GETSYM(he1, g_he1); GETSYM(mg, g_mg);     GETSYM(mu, g_mu);
    GETSYM(tmp, g_tmp); GETSYM(eg, g_eg);   GETSYM(eu, g_eu);     GETSYM(etmp, g_etmp);

    float* out_v = (float*)d_out;
    float* out_e = (float*)d_out + (long long)B_ * S_V_ * W_V_;

    // 1) pre-attention norms + modulation
    rms_scale<<<B_ * S_V_, 256>>>(embeds_vlm, vlm_ln1_w, hv, W_V_);
    modmm<<<(B_ * 3 * W_E_ + 255) / 256, 256>>>(cond, exp_ln1_dw, exp_ln1_db, mod1);
    rms_mod<<<B_ * S_E_, 256>>>(embeds_exp, mod1, he, W_E_, S_E_);

    // 2) QKV projections (batched over B to interleave vlm/exp rows into (B,S,...))
    {
        long long sHv = (long long)S_V_ * W_V_, sHe = (long long)S_E_ * W_E_;
        long long sQ = (long long)S_ * H_ * DH_, sK = (long long)S_ * DH_;
        gemm128<0><<<dim3(16, 6, B_), 256>>>(hv, vlm_q_w, q, S_V_, H_ * DH_, W_V_, sHv, 0, sQ, 1);
        gemm128<0><<<dim3(16, 1, B_), 256>>>(he, exp_q_w, q + (long long)S_V_ * H_ * DH_, S_E_, H_ * DH_, W_E_, sHe, 0, sQ, 1);
        gemm128<0><<<dim3(2, 6, B_), 256>>>(hv, vlm_k_w, k, S_V_, DH_, W_V_, sHv, 0, sK, 1);
        gemm128<0><<<dim3(2, 1, B_), 256>>>(he, exp_k_w, k + S_V_ * DH_, S_E_, DH_, W_E_, sHe, 0, sK, 1);
        gemm128<0><<<dim3(2, 6, B_), 256>>>(hv, vlm_v_w, v, S_V_, DH_, W_V_, sHv, 0, sK, 1);
        gemm128<0><<<dim3(2, 1, B_), 256>>>(he, exp_v_w, v + S_V_ * DH_, S_E_, DH_, W_E_, sHe, 0, sK, 1);
    }

    // 3) RoPE
    rope_kernel<<<(B_ * S_ * H_ * 128 + 255) / 256, 256>>>(q, pos, H_);
    rope_kernel<<<(B_ * S_ * 1 * 128 + 255) / 256, 256>>>(k, pos, 1);

    // 4) attention
    {
        long long nq = (long long)B_ * H_ * S_ * DH_;
        q_to_bhsd<<<(int)((nq + 255) / 256), 256>>>(q, qt);
        long long sQ = (long long)S_ * DH_, sKV = (long long)S_ * DH_, sL = (long long)S_ * S_;
        // logits = qt @ k^T  (batched over B*H, k broadcast over H)
        gemm128<1><<<dim3(7, 7, B_ * H_), 256>>>(qt, k, logits, S_, S_, DH_, sQ, sKV, sL, H_);
        softmax_mask<<<B_ * H_ * S_, 256>>>(logits, attn_mask);
        // attn = probs @ v
        gemm128<0><<<dim3(2, 7, B_ * H_), 256>>>(logits, v, attnt, S_, DH_, S_, sL, sKV, sQ, H_);
        bhsd_to_bshd<<<(int)((nq + 255) / 256), 256>>>(attnt, attn);
    }

    // 5) output projections + residual
    {
        long long sA = (long long)S_ * H_ * DH_;
        gemm128<0><<<dim3(16, 6, B_), 256>>>(attn, vlm_o_w, hv1, S_V_, W_V_, H_ * DH_, sA, 0, (long long)S_V_ * W_V_, 1);
        ew_add<<<(B_ * S_V_ * W_V_ + 255) / 256, 256>>>(hv1, embeds_vlm, B_ * S_V_ * W_V_);
        gemm128<0><<<dim3(8, 1, B_), 256>>>(attn + (long long)S_V_ * H_ * DH_, exp_o_w, he1, S_E_, W_E_, H_ * DH_, sA, 0, (long long)S_E_ * W_E_, 1);
        ew_gate_res<<<(B_ * S_E_ * W_E_ + 255) / 256, 256>>>(he1, embeds_exp, mod1, B_ * S_E_ * W_E_);
    }

    // 6) pre-MLP norms + modulation
    rms_scale<<<B_ * S_V_, 256>>>(hv1, vlm_ln2_w, hv, W_V_);     // nv -> hv (reuse)
    modmm<<<(B_ * 3 * W_E_ + 255) / 256, 256>>>(cond, exp_ln2_dw, exp_ln2_db, mod2);
    rms_mod<<<B_ * S_E_, 256>>>(he1, mod2, he, W_E_, S_E_);      // ne -> he (reuse)

    // 7) VLM MLP
    {
        int M = B_ * S_V_;
        gemm128<0><<<dim3(128, 24, 1), 256>>>(hv, vlm_gate_w, mg, M, MLPV_, W_V_, 0, 0, 0, 1);
        gemm128<0><<<dim3(128, 24, 1), 256>>>(hv, vlm_up_w,   mu, M, MLPV_, W_V_, 0, 0, 0, 1);
        long long n = (long long)M * MLPV_;
        gelu_mul<<<(int)((n + 255) / 256), 256>>>(mg, mu, n);
        gemm128<0><<<dim3(16, 24, 1), 256>>>(mg, vlm_down_w, tmp, M, W_V_, MLPV_, 0, 0, 0, 1);
        ew_final_v<<<(B_ * S_V_ * W_V_ + 255) / 256, 256>>>(out_v, hv1, tmp, B_ * S_V_ * W_V_);
    }

    // 8) expert MLP
    {
        int M = B_ * S_E_;
        gemm128<0><<<dim3(32, 2, 1), 256>>>(he, exp_gate_w, eg, M, MLPE_, W_E_, 0, 0, 0, 1);
        gemm128<0><<<dim3(32, 2, 1), 256>>>(he, exp_up_w,   eu, M, MLPE_, W_E_, 0, 0, 0, 1);
        long long n = (long long)M * MLPE_;
        gelu_mul<<<(int)((n + 255) / 256), 256>>>(eg, eu, n);
        gemm128<0><<<dim3(8, 2, 1), 256>>>(eg, exp_down_w, etmp, M, W_E_, MLPE_, 0, 0, 0, 1);
        ew_final_e<<<(B_ * S_E_ * W_E_ + 255) / 256, 256>>>(out_e, he1, etmp, mod2, B_ * S_E_ * W_E_);
    }
}

// round 2
// speedup vs baseline: 3.2009x; 3.2009x over previous
#include <cuda_runtime.h>
#include <cuda_bf16.h>
#include <math.h>

#define B_    4
#define S_V_  768
#define S_E_  64
#define S_    832
#define W_V_  2048
#define W_E_  1024
#define H_    8
#define DH_   256
#define MLPV_ 16384
#define MLPE_ 4096
#define EPS_  1e-6f
#define SCALE_ 0.0625f  // 256^-0.5

// ---------------- scratch (device globals; no allocations) ----------------
__device__ float g_hv   [B_*S_V_*W_V_];
__device__ float g_he   [B_*S_E_*W_E_];
__device__ float g_mod1 [B_*3*W_E_];
__device__ float g_mod2 [B_*3*W_E_];
__device__ float g_q    [(long long)B_*S_*H_*DH_];
__device__ float g_qt   [(long long)B_*H_*S_*DH_];
__device__ float g_k    [B_*S_*DH_];
__device__ float g_v    [B_*S_*DH_];
__device__ float g_logits[(long long)B_*H_*S_*S_];
__device__ float g_attnt[(long long)B_*H_*S_*DH_];
__device__ float g_attn [(long long)B_*S_*H_*DH_];
__device__ float g_hv1  [B_*S_V_*W_V_];
__device__ float g_he1  [B_*S_E_*W_E_];
__device__ float g_mg   [(long long)B_*S_V_*MLPV_];
__device__ float g_mu   [(long long)B_*S_V_*MLPV_];
__device__ float g_tmp  [B_*S_V_*W_V_];
__device__ float g_eg   [B_*S_E_*MLPE_];
__device__ float g_eu   [B_*S_E_*MLPE_];
__device__ float g_etmp [B_*S_E_*W_E_];

// ---------------- tf32 helpers ----------------
__device__ __forceinline__ unsigned f2tf32(float f) {
    unsigned r;
    asm("cvt.rna.tf32.f32 %0, %1;" : "=r"(r) : "f"(f));
    return r;
}

__device__ __forceinline__ void mma_tf32(float* c, const unsigned* a, const unsigned* b) {
    asm volatile(
        "mma.sync.aligned.m16n8k8.row.col.f32.tf32.tf32.f32 "
        "{%0,%1,%2,%3}, {%4,%5,%6,%7}, {%8,%9}, {%0,%1,%2,%3};\n"
        : "+f"(c[0]), "+f"(c[1]), "+f"(c[2]), "+f"(c[3])
        : "r"(a[0]), "r"(a[1]), "r"(a[2]), "r"(a[3]), "r"(b[0]), "r"(b[1]));
}

// ---------------- tensor-core tf32 GEMM: C = A * B(^T) ----------------
// A: (M,K) row-major. TB==0: B (K,N) row-major. TB==1: B (N,K) row-major.
// Batch z: A += z*sA, B += (z/bInner)*sB, C += z*sC.
// Requires K % 16 == 0, N % 2 == 0 (true for all call sites).
// Block: 256 thr (8 warps), tile 128x128, warp tile 64x32, K-tile 16.
#define AS_PAD 20
#define BS_PAD 132
template<int TB>
__global__ __launch_bounds__(256)
void gemm_tc(const float* __restrict__ A, const float* __restrict__ Bm,
             float* __restrict__ C, int M, int N, int K,
             long long sA, long long sB, long long sC, int bInner)
{
    const int z = blockIdx.z;
    A  += (long long)z * sA;
    Bm += (long long)(z / bInner) * sB;
    C  += (long long)z * sC;

    __shared__ unsigned As[2][128][AS_PAD];   // [m][k], padded
    __shared__ unsigned Bs[2][16][BS_PAD];    // [k][n], padded

    const int tid  = threadIdx.x;
    const int lane = tid & 31;
    const int wid  = tid >> 5;
    const int wm   = (wid & 1) * 64;
    const int wn   = (wid >> 1) * 32;
    const int bm   = blockIdx.y * 128;
    const int bn   = blockIdx.x * 128;

    // A staging indices: thread covers 2 float4s of the 128x16 tile
    const int am0 = (tid * 4) / 16;     // row (+64 for i=1)
    const int ak0 = (tid * 4) % 16;     // col
    // B staging indices
    const int bk0 = (tid * 4) / 128;    // TB=0: k row (+8 for i=1)
    const int bn0 = (tid * 4) % 128;    // TB=0: n col
    const int tn0 = tid / 4;            // TB=1: n row (+64 for i=1)
    const int tk0 = (tid % 4) * 4;      // TB=1: k col

    float c[4][4][4];
#pragma unroll
    for (int i = 0; i < 4; i++)
#pragma unroll
        for (int j = 0; j < 4; j++)
#pragma unroll
            for (int l = 0; l < 4; l++) c[i][j][l] = 0.f;

    auto loadA = [&](int ktE, int i) -> float4 {
        int gm = bm + am0 + i * 64;
        float4 v = make_float4(0.f, 0.f, 0.f, 0.f);
        if (gm < M) v = *(const float4*)(A + (long long)gm * K + ktE + ak0);
        return v;
    };
    auto storeA = [&](int buf, int i, float4 v) {
        unsigned* p = &As[buf][am0 + i * 64][ak0];
        p[0] = f2tf32(v.x); p[1] = f2tf32(v.y); p[2] = f2tf32(v.z); p[3] = f2tf32(v.w);
    };
    auto loadB = [&](int ktE, int i) -> float4 {
        float4 v = make_float4(0.f, 0.f, 0.f, 0.f);
        if (TB) {
            int gn = bn + tn0 + i * 64;
            if (gn < N) v = *(const float4*)(Bm + (long long)gn * K + ktE + tk0);
        } else {
            int gn = bn + bn0;
            if (gn < N) v = *(const float4*)(Bm + (long long)(ktE + bk0 + i * 8) * N + gn);
        }
        return v;
    };
    auto storeB = [&](int buf, int i, float4 v) {
        if (TB) {
            int n = tn0 + i * 64;
            Bs[buf][tk0 + 0][n] = f2tf32(v.x);
            Bs[buf][tk0 + 1][n] = f2tf32(v.y);
            Bs[buf][tk0 + 2][n] = f2tf32(v.z);
            Bs[buf][tk0 + 3][n] = f2tf32(v.w);
        } else {
            unsigned* p = &Bs[buf][bk0 + i * 8][bn0];
            p[0] = f2tf32(v.x); p[1] = f2tf32(v.y); p[2] = f2tf32(v.z); p[3] = f2tf32(v.w);
        }
    };

    // prologue: tile 0
    storeA(0, 0, loadA(0, 0));
    storeA(0, 1, loadA(0, 1));
    storeB(0, 0, loadB(0, 0));
    storeB(0, 1, loadB(0, 1));
    __syncthreads();

    const int nk = K / 16;
    int buf = 0;
    const int row = lane >> 2, col = lane & 3;

    for (int kt = 0; kt < nk; kt++) {
        float4 ra0, ra1, rb0, rb1;
        const bool more = (kt + 1 < nk);
        if (more) {
            int ktE = (kt + 1) * 16;
            ra0 = loadA(ktE, 0); ra1 = loadA(ktE, 1);
            rb0 = loadB(ktE, 0); rb1 = loadB(ktE, 1);
        }
#pragma unroll
        for (int ks = 0; ks < 2; ks++) {
            const int k8 = ks * 8;
            unsigned af[4][4], bf[4][2];
#pragma unroll
            for (int mt = 0; mt < 4; mt++) {
                int m0 = wm + mt * 16;
                af[mt][0] = As[buf][m0 + row    ][k8 + col    ];
                af[mt][1] = As[buf][m0 + row + 8][k8 + col    ];
                af[mt][2] = As[buf][m0 + row    ][k8 + col + 4];
                af[mt][3] = As[buf][m0 + row + 8][k8 + col + 4];
            }
#pragma unroll
            for (int nt = 0; nt < 4; nt++) {
                int n0 = wn + nt * 8 + row;
                bf[nt][0] = Bs[buf][k8 + col    ][n0];
                bf[nt][1] = Bs[buf][k8 + col + 4][n0];
            }
#pragma unroll
            for (int mt = 0; mt < 4; mt++)
#pragma unroll
                for (int nt = 0; nt < 4; nt++)
                    mma_tf32(c[mt][nt], af[mt], bf[nt]);
        }
        if (more) {
            storeA(buf ^ 1, 0, ra0); storeA(buf ^ 1, 1, ra1);
            storeB(buf ^ 1, 0, rb0); storeB(buf ^ 1, 1, rb1);
        }
        __syncthreads();
        buf ^= 1;
    }

    // epilogue
#pragma unroll
    for (int mt = 0; mt < 4; mt++) {
#pragma unroll
        for (int nt = 0; nt < 4; nt++) {
            int gm = bm + wm + mt * 16 + row;
            int gn = bn + wn + nt * 8 + col * 2;
            if (gn < N) {
                if (gm < M)
                    *(float2*)(C + (long long)gm * N + gn) = make_float2(c[mt][nt][0], c[mt][nt][1]);
                if (gm + 8 < M)
                    *(float2*)(C + (long long)(gm + 8) * N + gn) = make_float2(c[mt][nt][2], c[mt][nt][3]);
            }
        }
    }
}

// ---------------- row kernels ----------------
__device__ __forceinline__ float blockReduceSum(float v) {
    __shared__ float red[256];
    int t = threadIdx.x;
    red[t] = v; __syncthreads();
    for (int s = 128; s > 0; s >>= 1) {
        if (t < s) red[t] += red[t + s];
        __syncthreads();
    }
    return red[0];
}

__global__ void rms_scale(const float* __restrict__ x, const float* __restrict__ w,
                          float* __restrict__ out, int W)
{
    long long base = (long long)blockIdx.x * W;
    float ss = 0.f;
    for (int c = threadIdx.x; c < W; c += 256) { float t = x[base + c]; ss += t * t; }
    float tot = blockReduceSum(ss);
    float inv = rsqrtf(tot / (float)W + EPS_);
    for (int c = threadIdx.x; c < W; c += 256)
        out[base + c] = x[base + c] * inv * (1.f + w[c]);
}

__global__ void rms_mod(const float* __restrict__ x, const float* __restrict__ mod,
                        float* __restrict__ out, int W, int rowsPerB)
{
    long long base = (long long)blockIdx.x * W;
    int b = blockIdx.x / rowsPerB;
    const float* m = mod + (long long)b * 3 * W;
    float ss = 0.f;
    for (int c = threadIdx.x; c < W; c += 256) { float t = x[base + c]; ss += t * t; }
    float tot = blockReduceSum(ss);
    float inv = rsqrtf(tot / (float)W + EPS_);
    for (int c = threadIdx.x; c < W; c += 256)
        out[base + c] = x[base + c] * inv * (1.f + m[c]) + m[W + c];
}

__global__ void modmm(const float* __restrict__ cond, const float* __restrict__ W,
                      const float* __restrict__ bias, float* __restrict__ out)
{
    int idx = blockIdx.x * blockDim.x + threadIdx.x;
    int NT = 3 * W_E_;
    if (idx >= B_ * NT) return;
    int b = idx / NT, c = idx % NT;
    float s = bias[c];
    const float* cv = cond + b * W_E_;
    for (int k = 0; k < W_E_; k++) s += cv[k] * W[(long long)k * NT + c];
    out[idx] = s;
}

__global__ void rope_kernel(float* __restrict__ x, const int* __restrict__ pos, int nh)
{
    int idx = blockIdx.x * blockDim.x + threadIdx.x;
    int total = B_ * S_ * nh * 128;
    if (idx >= total) return;
    int d = idx & 127;
    int h = (idx >> 7) % nh;
    int s = (idx / (128 * nh)) % S_;
    int b = idx / (128 * nh * S_);
    float p = (float)pos[b * S_ + s];
    float ang = p * powf(10000.f, -(float)(2 * d) / 256.f);
    float sn, cs; sincosf(ang, &sn, &cs);
    float* base = x + (((long long)(b * S_ + s) * nh + h) << 8);
    float x1 = base[d], x2 = base[d + 128];
    base[d]       = x1 * cs - x2 * sn;
    base[d + 128] = x2 * cs + x1 * sn;
}

__global__ void q_to_bhsd(const float* __restrict__ q, float* __restrict__ qt)
{
    long long idx = (long long)blockIdx.x * blockDim.x + threadIdx.x;
    long long total = (long long)B_ * H_ * S_ * DH_;
    if (idx >= total) return;
    int d = idx & 255;
    int s = (idx >> 8) % S_;
    int h = (idx / ((long long)256 * S_)) % H_;
    int b = (int)(idx / ((long long)256 * S_ * H_));
    qt[idx] = q[(((long long)(b * S_ + s) * H_ + h) << 8) + d];
}

__global__ void bhsd_to_bshd(const float* __restrict__ a, float* __restrict__ o)
{
    long long idx = (long long)blockIdx.x * blockDim.x + threadIdx.x;
    long long total = (long long)B_ * H_ * S_ * DH_;
    if (idx >= total) return;
    int d = idx & 255;
    int h = (idx >> 8) % H_;
    int s = (idx / ((long long)256 * H_)) % S_;
    int b = (int)(idx / ((long long)256 * H_ * S_));
    o[idx] = a[(((long long)(b * H_ + h) * S_ + s) << 8) + d];
}

__global__ void softmax_mask(float* __restrict__ logits, const float* __restrict__ mask)
{
    int rowid = blockIdx.x;
    int b = rowid / (H_ * S_);
    int q = rowid % S_;
    float* row = logits + (long long)rowid * S_;
    const float* m = mask + ((long long)b * S_ + q) * S_;
    int t = threadIdx.x;
    float v[4];
    float mx = -1e30f;
#pragma unroll
    for (int j = 0; j < 4; j++) {
        int i = t + j * 256;
        v[j] = -1e30f;
        if (i < S_) { v[j] = row[i] * SCALE_ + m[i]; mx = fmaxf(mx, v[j]); }
    }
    __shared__ float red[256];
    red[t] = mx; __syncthreads();
    for (int s = 128; s > 0; s >>= 1) { if (t < s) red[t] = fmaxf(red[t], red[t + s]); __syncthreads(); }
    mx = red[0]; __syncthreads();
    float sum = 0.f;
#pragma unroll
    for (int j = 0; j < 4; j++) {
        int i = t + j * 256;
        if (i < S_) { v[j] = __expf(v[j] - mx); sum += v[j]; }
    }
    red[t] = sum; __syncthreads();
    for (int s = 128; s > 0; s >>= 1) { if (t < s) red[t] += red[t + s]; __syncthreads(); }
    float inv = 1.f / red[0];
#pragma unroll
    for (int j = 0; j < 4; j++) {
        int i = t + j * 256;
        if (i < S_) row[i] = v[j] * inv;
    }
}

__global__ void ew_add(float* __restrict__ y, const float* __restrict__ x, int n)
{
    int i = blockIdx.x * blockDim.x + threadIdx.x;
    if (i < n) y[i] += x[i];
}

__global__ void ew_gate_res(float* __restrict__ y, const float* __restrict__ x,
                            const float* __restrict__ mod, int n)
{
    int i = blockIdx.x * blockDim.x + threadIdx.x;
    if (i >= n) return;
    int b = i / (S_E_ * W_E_);
    int c = i % W_E_;
    float g = mod[(long long)b * 3 * W_E_ + 2 * W_E_ + c];
    y[i] = x[i] + y[i] * g;
}

__global__ void gelu_mul(float* __restrict__ g, const float* __restrict__ u, long long n)
{
    long long i = (long long)blockIdx.x * blockDim.x + threadIdx.x;
    if (i >= n) return;
    float x = g[i];
    float t = 0.5f * x * (1.f + tanhf(0.7978845608028654f * (x + 0.044715f * x * x * x)));
    g[i] = t * u[i];
}

__global__ void ew_final_v(float* __restrict__ out, const float* __restrict__ a,
                           const float* __restrict__ b, int n)
{
    int i = blockIdx.x * blockDim.x + threadIdx.x;
    if (i < n) out[i] = a[i] + b[i];
}

__global__ void ew_final_e(float* __restrict__ out, const float* __restrict__ a,
                           const float* __restrict__ b, const float* __restrict__ mod, int n)
{
    int i = blockIdx.x * blockDim.x + threadIdx.x;
    if (i >= n) return;
    int bb = i / (S_E_ * W_E_);
    int c = i % W_E_;
    float g = mod[(long long)bb * 3 * W_E_ + 2 * W_E_ + c];
    out[i] = a[i] + b[i] * g;
}

// ---------------- host launch ----------------
#define GETSYM(var, sym) do { void* p__; cudaGetSymbolAddress(&p__, sym); var = (float*)p__; } while (0)

extern "C" void kernel_launch(void* const* d_in, const int* in_sizes, int n_in,
                              void* d_out, int out_size)
{
    const float *embeds_vlm, *embeds_exp, *cond, *attn_mask;
    const int* pos;
    const float *vlm_ln1_w, *vlm_ln2_w, *vlm_q_w, *vlm_k_w, *vlm_v_w, *vlm_o_w;
    const float *vlm_gate_w, *vlm_up_w, *vlm_down_w;
    const float *exp_ln1_dw, *exp_ln1_db, *exp_ln2_dw, *exp_ln2_db;
    const float *exp_q_w, *exp_k_w, *exp_v_w, *exp_o_w, *exp_gate_w, *exp_up_w, *exp_down_w;

    if (in_sizes[3] == B_ * S_) {
        embeds_vlm = (const float*)d_in[0];  embeds_exp = (const float*)d_in[1];
        cond       = (const float*)d_in[2];  pos        = (const int*)  d_in[3];
        attn_mask  = (const float*)d_in[4];
        vlm_ln1_w  = (const float*)d_in[5];  vlm_ln2_w  = (const float*)d_in[6];
        vlm_q_w    = (const float*)d_in[7];  vlm_k_w    = (const float*)d_in[8];
        vlm_v_w    = (const float*)d_in[9];  vlm_o_w    = (const float*)d_in[10];
        vlm_gate_w = (const float*)d_in[11]; vlm_up_w   = (const float*)d_in[12];
        vlm_down_w = (const float*)d_in[13];
        exp_ln1_dw = (const float*)d_in[14]; exp_ln1_db = (const float*)d_in[15];
        exp_ln2_dw = (const float*)d_in[16]; exp_ln2_db = (const float*)d_in[17];
        exp_q_w    = (const float*)d_in[18]; exp_k_w    = (const float*)d_in[19];
        exp_v_w    = (const float*)d_in[20]; exp_o_w    = (const float*)d_in[21];
        exp_gate_w = (const float*)d_in[22]; exp_up_w   = (const float*)d_in[23];
        exp_down_w = (const float*)d_in[24];
    } else {
        embeds_vlm = (const float*)d_in[0];  embeds_exp = (const float*)d_in[1];
        cond       = (const float*)d_in[2];
        vlm_ln1_w  = (const float*)d_in[3];  vlm_ln2_w  = (const float*)d_in[4];
        vlm_q_w    = (const float*)d_in[5];  vlm_k_w    = (const float*)d_in[6];
        vlm_v_w    = (const float*)d_in[7];  vlm_o_w    = (const float*)d_in[8];
        vlm_gate_w = (const float*)d_in[9];  vlm_up_w   = (const float*)d_in[10];
        vlm_down_w = (const float*)d_in[11];
        exp_ln1_dw = (const float*)d_in[12]; exp_ln1_db = (const float*)d_in[13];
        exp_ln2_dw = (const float*)d_in[14]; exp_ln2_db = (const float*)d_in[15];
        exp_q_w    = (const float*)d_in[16]; exp_k_w    = (const float*)d_in[17];
        exp_v_w    = (const float*)d_in[18]; exp_o_w    = (const float*)d_in[19];
        exp_gate_w = (const float*)d_in[20]; exp_up_w   = (const float*)d_in[21];
        exp_down_w = (const float*)d_in[22];
        pos        = (const int*)  d_in[23];
        attn_mask  = (const float*)d_in[24];
    }

    float *hv, *he, *mod1, *mod2, *q, *qt, *k, *v, *logits, *attnt, *attn;
    float *hv1, *he1, *mg, *mu, *tmp, *eg, *eu, *etmp;
    GETSYM(hv, g_hv);   GETSYM(he, g_he);   GETSYM(mod1, g_mod1); GETSYM(mod2, g_mod2);
    GETSYM(q, g_q);     GETSYM(qt, g_qt);   GETSYM(k, g_k);       GETSYM(v, g_v);
    GETSYM(logits, g_logits); GETSYM(attnt, g_attnt); GETSYM(attn, g_attn);
    GETSYM(hv1, g_hv1); GETSYM(he1, g_he1); GETSYM(mg, g_mg);     GETSYM(mu, g_mu);
    GETSYM(tmp, g_tmp); GETSYM(eg, g_eg);   GETSYM(eu, g_eu);     GETSYM(etmp, g_etmp);

    float* out_v = (float*)d_out;
    float* out_e = (float*)d_out + (long long)B_ * S_V_ * W_V_;

    // 1) pre-attention norms + modulation
    rms_scale<<<B_ * S_V_, 256>>>(embeds_vlm, vlm_ln1_w, hv, W_V_);
    modmm<<<(B_ * 3 * W_E_ + 255) / 256, 256>>>(cond, exp_ln1_dw, exp_ln1_db, mod1);
    rms_mod<<<B_ * S_E_, 256>>>(embeds_exp, mod1, he, W_E_, S_E_);

    // 2) QKV projections
    {
        long long sHv = (long long)S_V_ * W_V_, sHe = (long long)S_E_ * W_E_;
        long long sQ = (long long)S_ * H_ * DH_, sK = (long long)S_ * DH_;
        gemm_tc<0><<<dim3(16, 6, B_), 256>>>(hv, vlm_q_w, q, S_V_, H_ * DH_, W_V_, sHv, 0, sQ, 1);
        gemm_tc<0><<<dim3(16, 1, B_), 256>>>(he, exp_q_w, q + (long long)S_V_ * H_ * DH_, S_E_, H_ * DH_, W_E_, sHe, 0, sQ, 1);
        gemm_tc<0><<<dim3(2, 6, B_), 256>>>(hv, vlm_k_w, k, S_V_, DH_, W_V_, sHv, 0, sK, 1);
        gemm_tc<0><<<dim3(2, 1, B_), 256>>>(he, exp_k_w, k + S_V_ * DH_, S_E_, DH_, W_E_, sHe, 0, sK, 1);
        gemm_tc<0><<<dim3(2, 6, B_), 256>>>(hv, vlm_v_w, v, S_V_, DH_, W_V_, sHv, 0, sK, 1);
        gemm_tc<0><<<dim3(2, 1, B_), 256>>>(he, exp_v_w, v + S_V_ * DH_, S_E_, DH_, W_E_, sHe, 0, sK, 1);
    }

    // 3) RoPE
    rope_kernel<<<(B_ * S_ * H_ * 128 + 255) / 256, 256>>>(q, pos, H_);
    rope_kernel<<<(B_ * S_ * 1 * 128 + 255) / 256, 256>>>(k, pos, 1);

    // 4) attention
    {
        long long nq = (long long)B_ * H_ * S_ * DH_;
        q_to_bhsd<<<(int)((nq + 255) / 256), 256>>>(q, qt);
        long long sQ = (long long)S_ * DH_, sKV = (long long)S_ * DH_, sL = (long long)S_ * S_;
        gemm_tc<1><<<dim3(7, 7, B_ * H_), 256>>>(qt, k, logits, S_, S_, DH_, sQ, sKV, sL, H_);
        softmax_mask<<<B_ * H_ * S_, 256>>>(logits, attn_mask);
        gemm_tc<0><<<dim3(2, 7, B_ * H_), 256>>>(logits, v, attnt, S_, DH_, S_, sL, sKV, sQ, H_);
        bhsd_to_bshd<<<(int)((nq + 255) / 256), 256>>>(attnt, attn);
    }

    // 5) output projections + residual
    {
        long long sA = (long long)S_ * H_ * DH_;
        gemm_tc<0><<<dim3(16, 6, B_), 256>>>(attn, vlm_o_w, hv1, S_V_, W_V_, H_ * DH_, sA, 0, (long long)S_V_ * W_V_, 1);
        ew_add<<<(B_ * S_V_ * W_V_ + 255) / 256, 256>>>(hv1, embeds_vlm, B_ * S_V_ * W_V_);
        gemm_tc<0><<<dim3(8, 1, B_), 256>>>(attn + (long long)S_V_ * H_ * DH_, exp_o_w, he1, S_E_, W_E_, H_ * DH_, sA, 0, (long long)S_E_ * W_E_, 1);
        ew_gate_res<<<(B_ * S_E_ * W_E_ + 255) / 256, 256>>>(he1, embeds_exp, mod1, B_ * S_E_ * W_E_);
    }

    // 6) pre-MLP norms + modulation
    rms_scale<<<B_ * S_V_, 256>>>(hv1, vlm_ln2_w, hv, W_V_);
    modmm<<<(B_ * 3 * W_E_ + 255) / 256, 256>>>(cond, exp_ln2_dw, exp_ln2_db, mod2);
    rms_mod<<<B_ * S_E_, 256>>>(he1, mod2, he, W_E_, S_E_);

    // 7) VLM MLP
    {
        int M = B_ * S_V_;
        gemm_tc<0><<<dim3(128, 24, 1), 256>>>(hv, vlm_gate_w, mg, M, MLPV_, W_V_, 0, 0, 0, 1);
        gemm_tc<0><<<dim3(128, 24, 1), 256>>>(hv, vlm_up_w,   mu, M, MLPV_, W_V_, 0, 0, 0, 1);
        long long n = (long long)M * MLPV_;
        gelu_mul<<<(int)((n + 255) / 256), 256>>>(mg, mu, n);
        gemm_tc<0><<<dim3(16, 24, 1), 256>>>(mg, vlm_down_w, tmp, M, W_V_, MLPV_, 0, 0, 0, 1);
        ew_final_v<<<(B_ * S_V_ * W_V_ + 255) / 256, 256>>>(out_v, hv1, tmp, B_ * S_V_ * W_V_);
    }

    // 8) expert MLP
    {
        int M = B_ * S_E_;
        gemm_tc<0><<<dim3(32, 2, 1), 256>>>(he, exp_gate_w, eg, M, MLPE_, W_E_, 0, 0, 0, 1);
        gemm_tc<0><<<dim3(32, 2, 1), 256>>>(he, exp_up_w,   eu, M, MLPE_, W_E_, 0, 0, 0, 1);
        long long n = (long long)M * MLPE_;
        gelu_mul<<<(int)((n + 255) / 256), 256>>>(eg, eu, n);
        gemm_tc<0><<<dim3(8, 2, 1), 256>>>(eg, exp_down_w, etmp, M, W_E_, MLPE_, 0, 0, 0, 1);
        ew_final_e<<<(B_ * S_E_ * W_E_ + 255) / 256, 256>>>(out_e, he1, etmp, mod2, B_ * S_E_ * W_E_);
    }
}

// round 3
// speedup vs baseline: 3.4230x; 1.0694x over previous
#include <cuda_runtime.h>
#include <cuda_bf16.h>
#include <math.h>

#define B_    4
#define S_V_  768
#define S_E_  64
#define S_    832
#define W_V_  2048
#define W_E_  1024
#define H_    8
#define DH_   256
#define MLPV_ 16384
#define MLPE_ 4096
#define EPS_  1e-6f
#define SCALE_ 0.0625f  // 256^-0.5

// ---------------- scratch (device globals; no allocations) ----------------
__device__ float g_hv   [B_*S_V_*W_V_];
__device__ float g_he   [B_*S_E_*W_E_];
__device__ float g_mod1 [B_*3*W_E_];
__device__ float g_mod2 [B_*3*W_E_];
__device__ float g_q    [(long long)B_*S_*H_*DH_];
__device__ float g_qt   [(long long)B_*H_*S_*DH_];
__device__ float g_k    [B_*S_*DH_];
__device__ float g_v    [B_*S_*DH_];
__device__ float g_logits[(long long)B_*H_*S_*S_];
__device__ float g_attnt[(long long)B_*H_*S_*DH_];
__device__ float g_attn [(long long)B_*S_*H_*DH_];
__device__ float g_hv1  [B_*S_V_*W_V_];
__device__ float g_he1  [B_*S_E_*W_E_];
__device__ float g_mg   [(long long)B_*S_V_*MLPV_];
__device__ float g_mu   [(long long)B_*S_V_*MLPV_];
__device__ float g_tmp  [B_*S_V_*W_V_];
__device__ float g_eg   [B_*S_E_*MLPE_];
__device__ float g_eu   [B_*S_E_*MLPE_];
__device__ float g_etmp [B_*S_E_*W_E_];
__device__ float g_wbuf [127401984];   // tf32-rounded weights

// ---------------- tf32 helpers ----------------
__device__ __forceinline__ float tf32r(float x) {
    unsigned u;
    asm("cvt.rna.tf32.f32 %0, %1;" : "=r"(u) : "f"(x));
    return __uint_as_float(u);
}

__device__ __forceinline__ void mma_tf32(float* c, const unsigned* a, const unsigned* b) {
    asm volatile(
        "mma.sync.aligned.m16n8k8.row.col.f32.tf32.tf32.f32 "
        "{%0,%1,%2,%3}, {%4,%5,%6,%7}, {%8,%9}, {%0,%1,%2,%3};\n"
        : "+f"(c[0]), "+f"(c[1]), "+f"(c[2]), "+f"(c[3])
        : "r"(a[0]), "r"(a[1]), "r"(a[2]), "r"(a[3]), "r"(b[0]), "r"(b[1]));
}

// ---------------- cp.async tf32 GEMM ----------------
// C(M,N) = A(M,K) * B.  TB==0: B (K,N) row-major. TB==1: B (N,K) row-major.
// Inputs must already be tf32-rounded fp32. RND: round C to tf32 on store.
// Block 128x256, 8 warps (2m x 4n) of 64x64 warp tiles, K-tile 16, 4 stages.
// Requires K%16==0, N%4==0.
#define ASTG (128*20)
template<int TB, int RND>
__global__ __launch_bounds__(256, 1)
void gemm_cp(const float* __restrict__ A, const float* __restrict__ Bm,
             float* __restrict__ C, int M, int N, int K,
             long long sA, long long sB, long long sC, int bInner)
{
    constexpr int BSTG = TB ? 256*20 : 16*264;
    extern __shared__ __align__(16) float sm[];
    float* Abase = sm;
    float* Bbase = sm + 4*ASTG;

    const int z = blockIdx.z;
    A  += (long long)z * sA;
    Bm += (long long)(z / bInner) * sB;
    C  += (long long)z * sC;

    const int tid  = threadIdx.x;
    const int lane = tid & 31;
    const int wid  = tid >> 5;
    const int wm   = (wid & 1) * 64;
    const int wn   = (wid >> 1) * 64;
    const int bm   = blockIdx.y * 128;
    const int bn   = blockIdx.x * 256;
    const int row  = lane >> 2, col = lane & 3;

    unsigned sbase = (unsigned)__cvta_generic_to_shared(sm);

    auto issue = [&](int st) {
        const int ktE  = st * 16;
        const int slot = st & 3;
#pragma unroll
        for (int j = 0; j < 2; j++) {            // A: 128x16
            int id = tid + j * 256;
            int r = id >> 2, kc = (id & 3) << 2;
            int gm = bm + r;
            const float* gp = A + (long long)(gm < M ? gm : M - 1) * K + ktE + kc;
            unsigned dst = sbase + (unsigned)(slot * ASTG + r * 20 + kc) * 4u;
            int zf = (gm < M) ? 16 : 0;
            asm volatile("cp.async.cg.shared.global [%0], [%1], 16, %2;\n"
                         :: "r"(dst), "l"(gp), "r"(zf));
        }
#pragma unroll
        for (int j = 0; j < 4; j++) {            // B: 16x256 (or 256x16)
            int id = tid + j * 256;
            unsigned dst; const float* gp; int zf;
            if (TB) {
                int n = id >> 2, kc = (id & 3) << 2;
                int gn = bn + n;
                gp  = Bm + (long long)(gn < N ? gn : N - 1) * K + ktE + kc;
                dst = sbase + (unsigned)(4 * ASTG + slot * BSTG + n * 20 + kc) * 4u;
                zf  = (gn < N) ? 16 : 0;
            } else {
                int kr = id >> 6, nc = (id & 63) << 2;
                int gn = bn + nc;
                gp  = Bm + (long long)(ktE + kr) * N + (gn < N ? gn : N - 4);
                dst = sbase + (unsigned)(4 * ASTG + slot * BSTG + kr * 264 + nc) * 4u;
                zf  = (gn < N) ? 16 : 0;
            }
            asm volatile("cp.async.cg.shared.global [%0], [%1], 16, %2;\n"
                         :: "r"(dst), "l"(gp), "r"(zf));
        }
    };

    float c[4][8][4];
#pragma unroll
    for (int i = 0; i < 4; i++)
#pragma unroll
        for (int j = 0; j < 8; j++)
#pragma unroll
            for (int l = 0; l < 4; l++) c[i][j][l] = 0.f;

    const int nk = K / 16;
#pragma unroll 1
    for (int s = 0; s < 3; s++) {
        issue(s);
        asm volatile("cp.async.commit_group;\n");
    }

#pragma unroll 1
    for (int kt = 0; kt < nk; kt++) {
        asm volatile("cp.async.wait_group 2;\n");
        __syncthreads();
        if (kt + 3 < nk) issue(kt + 3);
        asm volatile("cp.async.commit_group;\n");

        const float* Ab = Abase + (kt & 3) * ASTG;
        const float* Bb = Bbase + (kt & 3) * BSTG;
#pragma unroll
        for (int ks = 0; ks < 2; ks++) {
            const int k8 = ks * 8;
            unsigned af[4][4], bf[8][2];
#pragma unroll
            for (int mt = 0; mt < 4; mt++) {
                const float* p = Ab + (wm + mt * 16 + row) * 20 + k8 + col;
                af[mt][0] = __float_as_uint(p[0]);
                af[mt][1] = __float_as_uint(p[8 * 20]);
                af[mt][2] = __float_as_uint(p[4]);
                af[mt][3] = __float_as_uint(p[8 * 20 + 4]);
            }
#pragma unroll
            for (int nt = 0; nt < 8; nt++) {
                int n0 = wn + nt * 8 + row;
                if (TB) {
                    const float* p = Bb + n0 * 20 + k8 + col;
                    bf[nt][0] = __float_as_uint(p[0]);
                    bf[nt][1] = __float_as_uint(p[4]);
                } else {
                    const float* p = Bb + (k8 + col) * 264 + n0;
                    bf[nt][0] = __float_as_uint(p[0]);
                    bf[nt][1] = __float_as_uint(p[4 * 264]);
                }
            }
#pragma unroll
            for (int mt = 0; mt < 4; mt++)
#pragma unroll
                for (int nt = 0; nt < 8; nt++)
                    mma_tf32(c[mt][nt], af[mt], bf[nt]);
        }
    }

#pragma unroll
    for (int mt = 0; mt < 4; mt++) {
#pragma unroll
        for (int nt = 0; nt < 8; nt++) {
            int gm = bm + wm + mt * 16 + row;
            int gn = bn + wn + nt * 8 + col * 2;
            if (gn < N) {
                float2 v0 = make_float2(c[mt][nt][0], c[mt][nt][1]);
                float2 v1 = make_float2(c[mt][nt][2], c[mt][nt][3]);
                if (RND) {
                    v0.x = tf32r(v0.x); v0.y = tf32r(v0.y);
                    v1.x = tf32r(v1.x); v1.y = tf32r(v1.y);
                }
                if (gm < M)     *(float2*)(C + (long long)gm * N + gn) = v0;
                if (gm + 8 < M) *(float2*)(C + (long long)(gm + 8) * N + gn) = v1;
            }
        }
    }
}

// ---------------- weight tf32 pre-round ----------------
__global__ void round4(const float4* __restrict__ s, float4* __restrict__ d, int n4)
{
    int i = blockIdx.x * 256 + threadIdx.x;
    if (i >= n4) return;
    float4 v = s[i];
    v.x = tf32r(v.x); v.y = tf32r(v.y); v.z = tf32r(v.z); v.w = tf32r(v.w);
    d[i] = v;
}

// ---------------- row kernels (outputs tf32-rounded where they feed GEMMs) --
__device__ __forceinline__ float blockReduceSum(float v) {
    __shared__ float red[256];
    int t = threadIdx.x;
    red[t] = v; __syncthreads();
    for (int s = 128; s > 0; s >>= 1) {
        if (t < s) red[t] += red[t + s];
        __syncthreads();
    }
    return red[0];
}

__global__ void rms_scale(const float* __restrict__ x, const float* __restrict__ w,
                          float* __restrict__ out, int W)
{
    long long base = (long long)blockIdx.x * W;
    float ss = 0.f;
    for (int c = threadIdx.x; c < W; c += 256) { float t = x[base + c]; ss += t * t; }
    float tot = blockReduceSum(ss);
    float inv = rsqrtf(tot / (float)W + EPS_);
    for (int c = threadIdx.x; c < W; c += 256)
        out[base + c] = tf32r(x[base + c] * inv * (1.f + w[c]));
}

__global__ void rms_mod(const float* __restrict__ x, const float* __restrict__ mod,
                        float* __restrict__ out, int W, int rowsPerB)
{
    long long base = (long long)blockIdx.x * W;
    int b = blockIdx.x / rowsPerB;
    const float* m = mod + (long long)b * 3 * W;
    float ss = 0.f;
    for (int c = threadIdx.x; c < W; c += 256) { float t = x[base + c]; ss += t * t; }
    float tot = blockReduceSum(ss);
    float inv = rsqrtf(tot / (float)W + EPS_);
    for (int c = threadIdx.x; c < W; c += 256)
        out[base + c] = tf32r(x[base + c] * inv * (1.f + m[c]) + m[W + c]);
}

__global__ void modmm(const float* __restrict__ cond, const float* __restrict__ W,
                      const float* __restrict__ bias, float* __restrict__ out)
{
    int idx = blockIdx.x * blockDim.x + threadIdx.x;
    int NT = 3 * W_E_;
    if (idx >= B_ * NT) return;
    int b = idx / NT, c = idx % NT;
    float s = bias[c];
    const float* cv = cond + b * W_E_;
    for (int k = 0; k < W_E_; k++) s += cv[k] * W[(long long)k * NT + c];
    out[idx] = s;
}

__global__ void rope_kernel(float* __restrict__ x, const int* __restrict__ pos, int nh)
{
    int idx = blockIdx.x * blockDim.x + threadIdx.x;
    int total = B_ * S_ * nh * 128;
    if (idx >= total) return;
    int d = idx & 127;
    int h = (idx >> 7) % nh;
    int s = (idx / (128 * nh)) % S_;
    int b = idx / (128 * nh * S_);
    float p = (float)pos[b * S_ + s];
    float ang = p * powf(10000.f, -(float)(2 * d) / 256.f);
    float sn, cs; sincosf(ang, &sn, &cs);
    float* base = x + (((long long)(b * S_ + s) * nh + h) << 8);
    float x1 = base[d], x2 = base[d + 128];
    base[d]       = tf32r(x1 * cs - x2 * sn);
    base[d + 128] = tf32r(x2 * cs + x1 * sn);
}

__global__ void q_to_bhsd(const float* __restrict__ q, float* __restrict__ qt)
{
    long long idx = (long long)blockIdx.x * blockDim.x + threadIdx.x;
    long long total = (long long)B_ * H_ * S_ * DH_;
    if (idx >= total) return;
    int d = idx & 255;
    int s = (idx >> 8) % S_;
    int h = (idx / ((long long)256 * S_)) % H_;
    int b = (int)(idx / ((long long)256 * S_ * H_));
    qt[idx] = q[(((long long)(b * S_ + s) * H_ + h) << 8) + d];   // already rounded by rope
}

__global__ void bhsd_to_bshd(const float* __restrict__ a, float* __restrict__ o)
{
    long long idx = (long long)blockIdx.x * blockDim.x + threadIdx.x;
    long long total = (long long)B_ * H_ * S_ * DH_;
    if (idx >= total) return;
    int d = idx & 255;
    int h = (idx >> 8) % H_;
    int s = (idx / ((long long)256 * H_)) % S_;
    int b = (int)(idx / ((long long)256 * H_ * S_));
    o[idx] = tf32r(a[(((long long)(b * H_ + h) * S_ + s) << 8) + d]);
}

__global__ void softmax_mask(float* __restrict__ logits, const float* __restrict__ mask)
{
    int rowid = blockIdx.x;
    int b = rowid / (H_ * S_);
    int q = rowid % S_;
    float* row = logits + (long long)rowid * S_;
    const float* m = mask + ((long long)b * S_ + q) * S_;
    int t = threadIdx.x;
    float v[4];
    float mx = -1e30f;
#pragma unroll
    for (int j = 0; j < 4; j++) {
        int i = t + j * 256;
        v[j] = -1e30f;
        if (i < S_) { v[j] = row[i] * SCALE_ + m[i]; mx = fmaxf(mx, v[j]); }
    }
    __shared__ float red[256];
    red[t] = mx; __syncthreads();
    for (int s = 128; s > 0; s >>= 1) { if (t < s) red[t] = fmaxf(red[t], red[t + s]); __syncthreads(); }
    mx = red[0]; __syncthreads();
    float sum = 0.f;
#pragma unroll
    for (int j = 0; j < 4; j++) {
        int i = t + j * 256;
        if (i < S_) { v[j] = __expf(v[j] - mx); sum += v[j]; }
    }
    red[t] = sum; __syncthreads();
    for (int s = 128; s > 0; s >>= 1) { if (t < s) red[t] += red[t + s]; __syncthreads(); }
    float inv = 1.f / red[0];
#pragma unroll
    for (int j = 0; j < 4; j++) {
        int i = t + j * 256;
        if (i < S_) row[i] = tf32r(v[j] * inv);
    }
}

__global__ void ew_add(float* __restrict__ y, const float* __restrict__ x, int n)
{
    int i = blockIdx.x * blockDim.x + threadIdx.x;
    if (i < n) y[i] += x[i];
}

__global__ void ew_gate_res(float* __restrict__ y, const float* __restrict__ x,
                            const float* __restrict__ mod, int n)
{
    int i = blockIdx.x * blockDim.x + threadIdx.x;
    if (i >= n) return;
    int b = i / (S_E_ * W_E_);
    int c = i % W_E_;
    float g = mod[(long long)b * 3 * W_E_ + 2 * W_E_ + c];
    y[i] = x[i] + y[i] * g;
}

__global__ void gelu_mul(float* __restrict__ g, const float* __restrict__ u, long long n)
{
    long long i = (long long)blockIdx.x * blockDim.x + threadIdx.x;
    if (i >= n) return;
    float x = g[i];
    float t = 0.5f * x * (1.f + tanhf(0.7978845608028654f * (x + 0.044715f * x * x * x)));
    g[i] = tf32r(t * u[i]);
}

__global__ void ew_final_v(float* __restrict__ out, const float* __restrict__ a,
                           const float* __restrict__ b, int n)
{
    int i = blockIdx.x * blockDim.x + threadIdx.x;
    if (i < n) out[i] = a[i] + b[i];
}

__global__ void ew_final_e(float* __restrict__ out, const float* __restrict__ a,
                           const float* __restrict__ b, const float* __restrict__ mod, int n)
{
    int i = blockIdx.x * blockDim.x + threadIdx.x;
    if (i >= n) return;
    int bb = i / (S_E_ * W_E_);
    int c = i % W_E_;
    float g = mod[(long long)bb * 3 * W_E_ + 2 * W_E_ + c];
    out[i] = a[i] + b[i] * g;
}

// ---------------- host launch ----------------
#define GETSYM(var, sym) do { void* p__; cudaGetSymbolAddress(&p__, sym); var = (float*)p__; } while (0)

extern "C" void kernel_launch(void* const* d_in, const int* in_sizes, int n_in,
                              void* d_out, int out_size)
{
    const float *embeds_vlm, *embeds_exp, *cond, *attn_mask;
    const int* pos;
    const float *vlm_ln1_w, *vlm_ln2_w, *vlm_q_w, *vlm_k_w, *vlm_v_w, *vlm_o_w;
    const float *vlm_gate_w, *vlm_up_w, *vlm_down_w;
    const float *exp_ln1_dw, *exp_ln1_db, *exp_ln2_dw, *exp_ln2_db;
    const float *exp_q_w, *exp_k_w, *exp_v_w, *exp_o_w, *exp_gate_w, *exp_up_w, *exp_down_w;

    if (in_sizes[3] == B_ * S_) {
        embeds_vlm = (const float*)d_in[0];  embeds_exp = (const float*)d_in[1];
        cond       = (const float*)d_in[2];  pos        = (const int*)  d_in[3];
        attn_mask  = (const float*)d_in[4];
        vlm_ln1_w  = (const float*)d_in[5];  vlm_ln2_w  = (const float*)d_in[6];
        vlm_q_w    = (const float*)d_in[7];  vlm_k_w    = (const float*)d_in[8];
        vlm_v_w    = (const float*)d_in[9];  vlm_o_w    = (const float*)d_in[10];
        vlm_gate_w = (const float*)d_in[11]; vlm_up_w   = (const float*)d_in[12];
        vlm_down_w = (const float*)d_in[13];
        exp_ln1_dw = (const float*)d_in[14]; exp_ln1_db = (const float*)d_in[15];
        exp_ln2_dw = (const float*)d_in[16]; exp_ln2_db = (const float*)d_in[17];
        exp_q_w    = (const float*)d_in[18]; exp_k_w    = (const float*)d_in[19];
        exp_v_w    = (const float*)d_in[20]; exp_o_w    = (const float*)d_in[21];
        exp_gate_w = (const float*)d_in[22]; exp_up_w   = (const float*)d_in[23];
        exp_down_w = (const float*)d_in[24];
    } else {
        embeds_vlm = (const float*)d_in[0];  embeds_exp = (const float*)d_in[1];
        cond       = (const float*)d_in[2];
        vlm_ln1_w  = (const float*)d_in[3];  vlm_ln2_w  = (const float*)d_in[4];
        vlm_q_w    = (const float*)d_in[5];  vlm_k_w    = (const float*)d_in[6];
        vlm_v_w    = (const float*)d_in[7];  vlm_o_w    = (const float*)d_in[8];
        vlm_gate_w = (const float*)d_in[9];  vlm_up_w   = (const float*)d_in[10];
        vlm_down_w = (const float*)d_in[11];
        exp_ln1_dw = (const float*)d_in[12]; exp_ln1_db = (const float*)d_in[13];
        exp_ln2_dw = (const float*)d_in[14]; exp_ln2_db = (const float*)d_in[15];
        exp_q_w    = (const float*)d_in[16]; exp_k_w    = (const float*)d_in[17];
        exp_v_w    = (const float*)d_in[18]; exp_o_w    = (const float*)d_in[19];
        exp_gate_w = (const float*)d_in[20]; exp_up_w   = (const float*)d_in[21];
        exp_down_w = (const float*)d_in[22];
        pos        = (const int*)  d_in[23];
        attn_mask  = (const float*)d_in[24];
    }

    float *hv, *he, *mod1, *mod2, *q, *qt, *k, *v, *logits, *attnt, *attn;
    float *hv1, *he1, *mg, *mu, *tmp, *eg, *eu, *etmp, *wb;
    GETSYM(hv, g_hv);   GETSYM(he, g_he);   GETSYM(mod1, g_mod1); GETSYM(mod2, g_mod2);
    GETSYM(q, g_q);     GETSYM(qt, g_qt);   GETSYM(k, g_k);       GETSYM(v, g_v);
    GETSYM(logits, g_logits); GETSYM(attnt, g_attnt); GETSYM(attn, g_attn);
    GETSYM(hv1, g_hv1); GETSYM(he1, g_he1); GETSYM(mg, g_mg);     GETSYM(mu, g_mu);
    GETSYM(tmp, g_tmp); GETSYM(eg, g_eg);   GETSYM(eu, g_eu);     GETSYM(etmp, g_etmp);
    GETSYM(wb, g_wbuf);

    // --- pre-round weights to tf32 ---
    long long wofs = 0;
    auto cvtw = [&](const float* src, long long n) -> const float* {
        float* dst = wb + wofs; wofs += n;
        round4<<<(int)((n / 4 + 255) / 256), 256>>>((const float4*)src, (float4*)dst, (int)(n / 4));
        return dst;
    };
    const float* w_vq = cvtw(vlm_q_w,   (long long)W_V_ * H_ * DH_);
    const float* w_vk = cvtw(vlm_k_w,   (long long)W_V_ * DH_);
    const float* w_vv = cvtw(vlm_v_w,   (long long)W_V_ * DH_);
    const float* w_vo = cvtw(vlm_o_w,   (long long)H_ * DH_ * W_V_);
    const float* w_vg = cvtw(vlm_gate_w,(long long)W_V_ * MLPV_);
    const float* w_vu = cvtw(vlm_up_w,  (long long)W_V_ * MLPV_);
    const float* w_vd = cvtw(vlm_down_w,(long long)MLPV_ * W_V_);
    const float* w_eq = cvtw(exp_q_w,   (long long)W_E_ * H_ * DH_);
    const float* w_ek = cvtw(exp_k_w,   (long long)W_E_ * DH_);
    const float* w_ev = cvtw(exp_v_w,   (long long)W_E_ * DH_);
    const float* w_eo = cvtw(exp_o_w,   (long long)H_ * DH_ * W_E_);
    const float* w_eg = cvtw(exp_gate_w,(long long)W_E_ * MLPE_);
    const float* w_eu = cvtw(exp_up_w,  (long long)W_E_ * MLPE_);
    const float* w_ed = cvtw(exp_down_w,(long long)MLPE_ * W_E_);

    const int SM0 = 4 * (ASTG + 16 * 264) * 4;   // TB=0 smem bytes
    const int SM1 = 4 * (ASTG + 256 * 20) * 4;   // TB=1 smem bytes
    cudaFuncSetAttribute(gemm_cp<0,0>, cudaFuncAttributeMaxDynamicSharedMemorySize, SM0);
    cudaFuncSetAttribute(gemm_cp<0,1>, cudaFuncAttributeMaxDynamicSharedMemorySize, SM0);
    cudaFuncSetAttribute(gemm_cp<1,0>, cudaFuncAttributeMaxDynamicSharedMemorySize, SM1);

    float* out_v = (float*)d_out;
    float* out_e = (float*)d_out + (long long)B_ * S_V_ * W_V_;

    // 1) pre-attention norms + modulation
    rms_scale<<<B_ * S_V_, 256>>>(embeds_vlm, vlm_ln1_w, hv, W_V_);
    modmm<<<(B_ * 3 * W_E_ + 255) / 256, 256>>>(cond, exp_ln1_dw, exp_ln1_db, mod1);
    rms_mod<<<B_ * S_E_, 256>>>(embeds_exp, mod1, he, W_E_, S_E_);

    // 2) QKV projections
    {
        long long sHv = (long long)S_V_ * W_V_, sHe = (long long)S_E_ * W_E_;
        long long sQ = (long long)S_ * H_ * DH_, sK = (long long)S_ * DH_;
        gemm_cp<0,0><<<dim3(8, 6, B_), 256, SM0>>>(hv, w_vq, q, S_V_, H_ * DH_, W_V_, sHv, 0, sQ, 1);
        gemm_cp<0,0><<<dim3(8, 1, B_), 256, SM0>>>(he, w_eq, q + (long long)S_V_ * H_ * DH_, S_E_, H_ * DH_, W_E_, sHe, 0, sQ, 1);
        gemm_cp<0,0><<<dim3(1, 6, B_), 256, SM0>>>(hv, w_vk, k, S_V_, DH_, W_V_, sHv, 0, sK, 1);
        gemm_cp<0,0><<<dim3(1, 1, B_), 256, SM0>>>(he, w_ek, k + S_V_ * DH_, S_E_, DH_, W_E_, sHe, 0, sK, 1);
        gemm_cp<0,1><<<dim3(1, 6, B_), 256, SM0>>>(hv, w_vv, v, S_V_, DH_, W_V_, sHv, 0, sK, 1);
        gemm_cp<0,1><<<dim3(1, 1, B_), 256, SM0>>>(he, w_ev, v + S_V_ * DH_, S_E_, DH_, W_E_, sHe, 0, sK, 1);
    }

    // 3) RoPE (rounds q, k to tf32)
    rope_kernel<<<(B_ * S_ * H_ * 128 + 255) / 256, 256>>>(q, pos, H_);
    rope_kernel<<<(B_ * S_ * 1 * 128 + 255) / 256, 256>>>(k, pos, 1);

    // 4) attention
    {
        long long nq = (long long)B_ * H_ * S_ * DH_;
        q_to_bhsd<<<(int)((nq + 255) / 256), 256>>>(q, qt);
        long long sQ = (long long)S_ * DH_, sKV = (long long)S_ * DH_, sL = (long long)S_ * S_;
        gemm_cp<1,0><<<dim3(4, 7, B_ * H_), 256, SM1>>>(qt, k, logits, S_, S_, DH_, sQ, sKV, sL, H_);
        softmax_mask<<<B_ * H_ * S_, 256>>>(logits, attn_mask);
        gemm_cp<0,0><<<dim3(1, 7, B_ * H_), 256, SM0>>>(logits, v, attnt, S_, DH_, S_, sL, sKV, sQ, H_);
        bhsd_to_bshd<<<(int)((nq + 255) / 256), 256>>>(attnt, attn);
    }

    // 5) output projections + residual
    {
        long long sA = (long long)S_ * H_ * DH_;
        gemm_cp<0,0><<<dim3(8, 6, B_), 256, SM0>>>(attn, w_vo, hv1, S_V_, W_V_, H_ * DH_, sA, 0, (long long)S_V_ * W_V_, 1);
        ew_add<<<(B_ * S_V_ * W_V_ + 255) / 256, 256>>>(hv1, embeds_vlm, B_ * S_V_ * W_V_);
        gemm_cp<0,0><<<dim3(4, 1, B_), 256, SM0>>>(attn + (long long)S_V_ * H_ * DH_, w_eo, he1, S_E_, W_E_, H_ * DH_, sA, 0, (long long)S_E_ * W_E_, 1);
        ew_gate_res<<<(B_ * S_E_ * W_E_ + 255) / 256, 256>>>(he1, embeds_exp, mod1, B_ * S_E_ * W_E_);
    }

    // 6) pre-MLP norms + modulation
    rms_scale<<<B_ * S_V_, 256>>>(hv1, vlm_ln2_w, hv, W_V_);
    modmm<<<(B_ * 3 * W_E_ + 255) / 256, 256>>>(cond, exp_ln2_dw, exp_ln2_db, mod2);
    rms_mod<<<B_ * S_E_, 256>>>(he1, mod2, he, W_E_, S_E_);

    // 7) VLM MLP
    {
        int M = B_ * S_V_;
        gemm_cp<0,0><<<dim3(64, 24, 1), 256, SM0>>>(hv, w_vg, mg, M, MLPV_, W_V_, 0, 0, 0, 1);
        gemm_cp<0,0><<<dim3(64, 24, 1), 256, SM0>>>(hv, w_vu, mu, M, MLPV_, W_V_, 0, 0, 0, 1);
        long long n = (long long)M * MLPV_;
        gelu_mul<<<(int)((n + 255) / 256), 256>>>(mg, mu, n);
        gemm_cp<0,0><<<dim3(8, 24, 1), 256, SM0>>>(mg, w_vd, tmp, M, W_V_, MLPV_, 0, 0, 0, 1);
        ew_final_v<<<(B_ * S_V_ * W_V_ + 255) / 256, 256>>>(out_v, hv1, tmp, B_ * S_V_ * W_V_);
    }

    // 8) expert MLP
    {
        int M = B_ * S_E_;
        gemm_cp<0,0><<<dim3(16, 2, 1), 256, SM0>>>(he, w_eg, eg, M, MLPE_, W_E_, 0, 0, 0, 1);
        gemm_cp<0,0><<<dim3(16, 2, 1), 256, SM0>>>(he, w_eu, eu, M, MLPE_, W_E_, 0, 0, 0, 1);
        long long n = (long long)M * MLPE_;
        gelu_mul<<<(int)((n + 255) / 256), 256>>>(eg, eu, n);
        gemm_cp<0,0><<<dim3(4, 2, 1), 256, SM0>>>(eg, w_ed, etmp, M, W_E_, MLPE_, 0, 0, 0, 1);
        ew_final_e<<<(B_ * S_E_ * W_E_ + 255) / 256, 256>>>(out_e, he1, etmp, mod2, B_ * S_E_ * W_E_);
    }
}

// round 4
// speedup vs baseline: 4.1715x; 1.2186x over previous
#include <cuda_runtime.h>
#include <cuda_bf16.h>
#include <math.h>

#define B_    4
#define S_V_  768
#define S_E_  64
#define S_    832
#define W_V_  2048
#define W_E_  1024
#define H_    8
#define DH_   256
#define MLPV_ 16384
#define MLPE_ 4096
#define EPS_  1e-6f
#define SCALE_ 0.0625f  // 256^-0.5

// ---------------- scratch (device globals; no allocations) ----------------
__device__ float g_hv   [B_*S_V_*W_V_];
__device__ float g_he   [B_*S_E_*W_E_];
__device__ float g_mod1 [B_*3*W_E_];
__device__ float g_mod2 [B_*3*W_E_];
__device__ float g_q    [(long long)B_*S_*H_*DH_];
__device__ float g_qt   [(long long)B_*H_*S_*DH_];
__device__ float g_k    [B_*S_*DH_];
__device__ float g_v    [B_*S_*DH_];
__device__ float g_logits[(long long)B_*H_*S_*S_];
__device__ float g_attnt[(long long)B_*H_*S_*DH_];
__device__ float g_attn [(long long)B_*S_*H_*DH_];
__device__ float g_hv1  [B_*S_V_*W_V_];
__device__ float g_he1  [B_*S_E_*W_E_];
__device__ float g_mg   [(long long)B_*S_V_*MLPV_];
__device__ float g_mu   [(long long)B_*S_V_*MLPV_];
__device__ float g_tmp  [B_*S_V_*W_V_];
__device__ float g_eg   [B_*S_E_*MLPE_];
__device__ float g_eu   [B_*S_E_*MLPE_];
__device__ float g_etmp [B_*S_E_*W_E_];
__device__ float g_wbuf [127401984];   // tf32-rounded weights

// ---------------- tf32 helpers ----------------
__device__ __forceinline__ float tf32r(float x) {
    unsigned u;
    asm("cvt.rna.tf32.f32 %0, %1;" : "=r"(u) : "f"(x));
    return __uint_as_float(u);
}

__device__ __forceinline__ void mma_tf32(float* c, const unsigned* a, const unsigned* b) {
    asm volatile(
        "mma.sync.aligned.m16n8k8.row.col.f32.tf32.tf32.f32 "
        "{%0,%1,%2,%3}, {%4,%5,%6,%7}, {%8,%9}, {%0,%1,%2,%3};\n"
        : "+f"(c[0]), "+f"(c[1]), "+f"(c[2]), "+f"(c[3])
        : "r"(a[0]), "r"(a[1]), "r"(a[2]), "r"(a[3]), "r"(b[0]), "r"(b[1]));
}

// ---------------- cp.async tf32 GEMM, 128x128 tile ----------------
// C(M,N) = A(M,K) * B.  TB==0: B (K,N) row-major. TB==1: B (N,K) row-major.
// Inputs must already be tf32-rounded fp32. RND: round C to tf32 on store.
// 256 thr, 8 warps (2m x 4n) of 64x32 warp tiles, K-tile 16, 4 cp.async stages.
// Requires K%16==0, N%4==0.
#define AST (128*20)
template<int TB, int RND>
__global__ __launch_bounds__(256, 2)
void gemm_cp(const float* __restrict__ A, const float* __restrict__ Bm,
             float* __restrict__ C, int M, int N, int K,
             long long sA, long long sB, long long sC, int bInner)
{
    constexpr int BST = TB ? 128*20 : 16*136;
    extern __shared__ __align__(16) float sm[];
    float* Abase = sm;
    float* Bbase = sm + 4*AST;

    const int z = blockIdx.z;
    A  += (long long)z * sA;
    Bm += (long long)(z / bInner) * sB;
    C  += (long long)z * sC;

    const int tid  = threadIdx.x;
    const int lane = tid & 31;
    const int wid  = tid >> 5;
    const int wm   = (wid & 1) * 64;
    const int wn   = (wid >> 1) * 32;
    const int bm   = blockIdx.y * 128;
    const int bn   = blockIdx.x * 128;
    const int row  = lane >> 2, col = lane & 3;

    unsigned sbase = (unsigned)__cvta_generic_to_shared(sm);

    auto issue = [&](int st) {
        const int ktE  = st * 16;
        const int slot = st & 3;
#pragma unroll
        for (int j = 0; j < 2; j++) {            // A: 128x16
            int id = tid + j * 256;
            int r = id >> 2, kc = (id & 3) << 2;
            int gm = bm + r;
            const float* gp = A + (long long)(gm < M ? gm : M - 1) * K + ktE + kc;
            unsigned dst = sbase + (unsigned)(slot * AST + r * 20 + kc) * 4u;
            int zf = (gm < M) ? 16 : 0;
            asm volatile("cp.async.cg.shared.global [%0], [%1], 16, %2;\n"
                         :: "r"(dst), "l"(gp), "r"(zf));
        }
#pragma unroll
        for (int j = 0; j < 2; j++) {            // B: 16x128 (or 128x16)
            int id = tid + j * 256;
            unsigned dst; const float* gp; int zf;
            if (TB) {
                int n = id >> 2, kc = (id & 3) << 2;
                int gn = bn + n;
                gp  = Bm + (long long)(gn < N ? gn : N - 1) * K + ktE + kc;
                dst = sbase + (unsigned)(4 * AST + slot * BST + n * 20 + kc) * 4u;
                zf  = (gn < N) ? 16 : 0;
            } else {
                int kr = id >> 5, nc = (id & 31) << 2;
                int gn = bn + nc;
                gp  = Bm + (long long)(ktE + kr) * N + (gn < N ? gn : N - 4);
                dst = sbase + (unsigned)(4 * AST + slot * BST + kr * 136 + nc) * 4u;
                zf  = (gn < N) ? 16 : 0;
            }
            asm volatile("cp.async.cg.shared.global [%0], [%1], 16, %2;\n"
                         :: "r"(dst), "l"(gp), "r"(zf));
        }
    };

    float c[4][4][4];
#pragma unroll
    for (int i = 0; i < 4; i++)
#pragma unroll
        for (int j = 0; j < 4; j++)
#pragma unroll
            for (int l = 0; l < 4; l++) c[i][j][l] = 0.f;

    const int nk = K / 16;
#pragma unroll 1
    for (int s = 0; s < 3; s++) {
        issue(s);
        asm volatile("cp.async.commit_group;\n");
    }

#pragma unroll 1
    for (int kt = 0; kt < nk; kt++) {
        asm volatile("cp.async.wait_group 2;\n");
        __syncthreads();
        if (kt + 3 < nk) issue(kt + 3);
        asm volatile("cp.async.commit_group;\n");

        const float* Ab = Abase + (kt & 3) * AST;
        const float* Bb = Bbase + (kt & 3) * BST;
#pragma unroll
        for (int ks = 0; ks < 2; ks++) {
            const int k8 = ks * 8;
            unsigned af[4][4], bf[4][2];
#pragma unroll
            for (int mt = 0; mt < 4; mt++) {
                const float* p = Ab + (wm + mt * 16 + row) * 20 + k8 + col;
                af[mt][0] = __float_as_uint(p[0]);
                af[mt][1] = __float_as_uint(p[8 * 20]);
                af[mt][2] = __float_as_uint(p[4]);
                af[mt][3] = __float_as_uint(p[8 * 20 + 4]);
            }
#pragma unroll
            for (int nt = 0; nt < 4; nt++) {
                int n0 = wn + nt * 8 + row;
                if (TB) {
                    const float* p = Bb + n0 * 20 + k8 + col;
                    bf[nt][0] = __float_as_uint(p[0]);
                    bf[nt][1] = __float_as_uint(p[4]);
                } else {
                    const float* p = Bb + (k8 + col) * 136 + n0;
                    bf[nt][0] = __float_as_uint(p[0]);
                    bf[nt][1] = __float_as_uint(p[4 * 136]);
                }
            }
#pragma unroll
            for (int mt = 0; mt < 4; mt++)
#pragma unroll
                for (int nt = 0; nt < 4; nt++)
                    mma_tf32(c[mt][nt], af[mt], bf[nt]);
        }
    }

#pragma unroll
    for (int mt = 0; mt < 4; mt++) {
#pragma unroll
        for (int nt = 0; nt < 4; nt++) {
            int gm = bm + wm + mt * 16 + row;
            int gn = bn + wn + nt * 8 + col * 2;
            if (gn < N) {
                float2 v0 = make_float2(c[mt][nt][0], c[mt][nt][1]);
                float2 v1 = make_float2(c[mt][nt][2], c[mt][nt][3]);
                if (RND) {
                    v0.x = tf32r(v0.x); v0.y = tf32r(v0.y);
                    v1.x = tf32r(v1.x); v1.y = tf32r(v1.y);
                }
                if (gm < M)     *(float2*)(C + (long long)gm * N + gn) = v0;
                if (gm + 8 < M) *(float2*)(C + (long long)(gm + 8) * N + gn) = v1;
            }
        }
    }
}

// ---------------- fused weight tf32 pre-round ----------------
#define NW 14
struct RoundDesc {
    const float4* src[NW];
    long long dofs[NW];       // dst offset (in floats) into g_wbuf
    int blkStart[NW + 1];     // block range per weight; each block = 4096 floats
};

__global__ void round_many(RoundDesc d, float* __restrict__ wbuf)
{
    int b = blockIdx.x;
    int w = 0;
#pragma unroll
    for (int i = 0; i < NW; i++) if (b >= d.blkStart[i + 1]) w = i + 1;
    int lb = b - d.blkStart[w];
    const float4* s = d.src[w] + (long long)lb * 1024;
    float4* o = (float4*)(wbuf + d.dofs[w]) + (long long)lb * 1024;
    int t = threadIdx.x;
    float4 v[4];
#pragma unroll
    for (int i = 0; i < 4; i++) v[i] = s[t + i * 256];
#pragma unroll
    for (int i = 0; i < 4; i++) {
        v[i].x = tf32r(v[i].x); v[i].y = tf32r(v[i].y);
        v[i].z = tf32r(v[i].z); v[i].w = tf32r(v[i].w);
    }
#pragma unroll
    for (int i = 0; i < 4; i++) o[t + i * 256] = v[i];
}

// ---------------- row kernels ----------------
__device__ __forceinline__ float blockReduceSum(float v) {
    __shared__ float red[256];
    int t = threadIdx.x;
    red[t] = v; __syncthreads();
    for (int s = 128; s > 0; s >>= 1) {
        if (t < s) red[t] += red[t + s];
        __syncthreads();
    }
    return red[0];
}

__global__ void rms_scale(const float* __restrict__ x, const float* __restrict__ w,
                          float* __restrict__ out, int W)
{
    long long base = (long long)blockIdx.x * W;
    float ss = 0.f;
    for (int c = threadIdx.x; c < W; c += 256) { float t = x[base + c]; ss += t * t; }
    float tot = blockReduceSum(ss);
    float inv = rsqrtf(tot / (float)W + EPS_);
    for (int c = threadIdx.x; c < W; c += 256)
        out[base + c] = tf32r(x[base + c] * inv * (1.f + w[c]));
}

__global__ void rms_mod(const float* __restrict__ x, const float* __restrict__ mod,
                        float* __restrict__ out, int W, int rowsPerB)
{
    long long base = (long long)blockIdx.x * W;
    int b = blockIdx.x / rowsPerB;
    const float* m = mod + (long long)b * 3 * W;
    float ss = 0.f;
    for (int c = threadIdx.x; c < W; c += 256) { float t = x[base + c]; ss += t * t; }
    float tot = blockReduceSum(ss);
    float inv = rsqrtf(tot / (float)W + EPS_);
    for (int c = threadIdx.x; c < W; c += 256)
        out[base + c] = tf32r(x[base + c] * inv * (1.f + m[c]) + m[W + c]);
}

__global__ void modmm(const float* __restrict__ cond, const float* __restrict__ W,
                      const float* __restrict__ bias, float* __restrict__ out)
{
    int idx = blockIdx.x * blockDim.x + threadIdx.x;
    int NT = 3 * W_E_;
    if (idx >= B_ * NT) return;
    int b = idx / NT, c = idx % NT;
    float s = bias[c];
    const float* cv = cond + b * W_E_;
    for (int k = 0; k < W_E_; k++) s += cv[k] * W[(long long)k * NT + c];
    out[idx] = s;
}

__global__ void rope_kernel(float* __restrict__ x, const int* __restrict__ pos, int nh)
{
    int idx = blockIdx.x * blockDim.x + threadIdx.x;
    int total = B_ * S_ * nh * 128;
    if (idx >= total) return;
    int d = idx & 127;
    int h = (idx >> 7) % nh;
    int s = (idx / (128 * nh)) % S_;
    int b = idx / (128 * nh * S_);
    float p = (float)pos[b * S_ + s];
    float ang = p * powf(10000.f, -(float)(2 * d) / 256.f);
    float sn, cs; sincosf(ang, &sn, &cs);
    float* base = x + (((long long)(b * S_ + s) * nh + h) << 8);
    float x1 = base[d], x2 = base[d + 128];
    base[d]       = tf32r(x1 * cs - x2 * sn);
    base[d + 128] = tf32r(x2 * cs + x1 * sn);
}

__global__ void q_to_bhsd(const float* __restrict__ q, float* __restrict__ qt)
{
    long long idx = (long long)blockIdx.x * blockDim.x + threadIdx.x;
    long long total = (long long)B_ * H_ * S_ * DH_;
    if (idx >= total) return;
    int d = idx & 255;
    int s = (idx >> 8) % S_;
    int h = (idx / ((long long)256 * S_)) % H_;
    int b = (int)(idx / ((long long)256 * S_ * H_));
    qt[idx] = q[(((long long)(b * S_ + s) * H_ + h) << 8) + d];
}

__global__ void bhsd_to_bshd(const float* __restrict__ a, float* __restrict__ o)
{
    long long idx = (long long)blockIdx.x * blockDim.x + threadIdx.x;
    long long total = (long long)B_ * H_ * S_ * DH_;
    if (idx >= total) return;
    int d = idx & 255;
    int h = (idx >> 8) % H_;
    int s = (idx / ((long long)256 * H_)) % S_;
    int b = (int)(idx / ((long long)256 * H_ * S_));
    o[idx] = tf32r(a[(((long long)(b * H_ + h) * S_ + s) << 8) + d]);
}

__global__ void softmax_mask(float* __restrict__ logits, const float* __restrict__ mask)
{
    int rowid = blockIdx.x;
    int b = rowid / (H_ * S_);
    int q = rowid % S_;
    float* row = logits + (long long)rowid * S_;
    const float* m = mask + ((long long)b * S_ + q) * S_;
    int t = threadIdx.x;
    float v[4];
    float mx = -1e30f;
#pragma unroll
    for (int j = 0; j < 4; j++) {
        int i = t + j * 256;
        v[j] = -1e30f;
        if (i < S_) { v[j] = row[i] * SCALE_ + m[i]; mx = fmaxf(mx, v[j]); }
    }
    __shared__ float red[256];
    red[t] = mx; __syncthreads();
    for (int s = 128; s > 0; s >>= 1) { if (t < s) red[t] = fmaxf(red[t], red[t + s]); __syncthreads(); }
    mx = red[0]; __syncthreads();
    float sum = 0.f;
#pragma unroll
    for (int j = 0; j < 4; j++) {
        int i = t + j * 256;
        if (i < S_) { v[j] = __expf(v[j] - mx); sum += v[j]; }
    }
    red[t] = sum; __syncthreads();
    for (int s = 128; s > 0; s >>= 1) { if (t < s) red[t] += red[t + s]; __syncthreads(); }
    float inv = 1.f / red[0];
#pragma unroll
    for (int j = 0; j < 4; j++) {
        int i = t + j * 256;
        if (i < S_) row[i] = tf32r(v[j] * inv);
    }
}

__global__ void ew_add4(float4* __restrict__ y, const float4* __restrict__ x, int n4)
{
    int i = blockIdx.x * blockDim.x + threadIdx.x;
    if (i >= n4) return;
    float4 a = y[i], b = x[i];
    a.x += b.x; a.y += b.y; a.z += b.z; a.w += b.w;
    y[i] = a;
}

__global__ void ew_gate_res(float* __restrict__ y, const float* __restrict__ x,
                            const float* __restrict__ mod, int n)
{
    int i = blockIdx.x * blockDim.x + threadIdx.x;
    if (i >= n) return;
    int b = i / (S_E_ * W_E_);
    int c = i % W_E_;
    float g = mod[(long long)b * 3 * W_E_ + 2 * W_E_ + c];
    y[i] = x[i] + y[i] * g;
}

__global__ void gelu_mul4(float4* __restrict__ g, const float4* __restrict__ u, long long n4)
{
    long long i = (long long)blockIdx.x * blockDim.x + threadIdx.x;
    if (i >= n4) return;
    float4 a = g[i], b = u[i];
    float r[4] = {a.x, a.y, a.z, a.w};
    float s[4] = {b.x, b.y, b.z, b.w};
#pragma unroll
    for (int j = 0; j < 4; j++) {
        float x = r[j];
        float t = 0.5f * x * (1.f + tanhf(0.7978845608028654f * (x + 0.044715f * x * x * x)));
        r[j] = tf32r(t * s[j]);
    }
    g[i] = make_float4(r[0], r[1], r[2], r[3]);
}

__global__ void ew_final_v(float* __restrict__ out, const float* __restrict__ a,
                           const float* __restrict__ b, int n)
{
    int i = blockIdx.x * blockDim.x + threadIdx.x;
    if (i < n) out[i] = a[i] + b[i];
}

__global__ void ew_final_e(float* __restrict__ out, const float* __restrict__ a,
                           const float* __restrict__ b, const float* __restrict__ mod, int n)
{
    int i = blockIdx.x * blockDim.x + threadIdx.x;
    if (i >= n) return;
    int bb = i / (S_E_ * W_E_);
    int c = i % W_E_;
    float g = mod[(long long)bb * 3 * W_E_ + 2 * W_E_ + c];
    out[i] = a[i] + b[i] * g;
}

// ---------------- host launch ----------------
#define GETSYM(var, sym) do { void* p__; cudaGetSymbolAddress(&p__, sym); var = (float*)p__; } while (0)

extern "C" void kernel_launch(void* const* d_in, const int* in_sizes, int n_in,
                              void* d_out, int out_size)
{
    const float *embeds_vlm, *embeds_exp, *cond, *attn_mask;
    const int* pos;
    const float *vlm_ln1_w, *vlm_ln2_w, *vlm_q_w, *vlm_k_w, *vlm_v_w, *vlm_o_w;
    const float *vlm_gate_w, *vlm_up_w, *vlm_down_w;
    const float *exp_ln1_dw, *exp_ln1_db, *exp_ln2_dw, *exp_ln2_db;
    const float *exp_q_w, *exp_k_w, *exp_v_w, *exp_o_w, *exp_gate_w, *exp_up_w, *exp_down_w;

    if (in_sizes[3] == B_ * S_) {
        embeds_vlm = (const float*)d_in[0];  embeds_exp = (const float*)d_in[1];
        cond       = (const float*)d_in[2];  pos        = (const int*)  d_in[3];
        attn_mask  = (const float*)d_in[4];
        vlm_ln1_w  = (const float*)d_in[5];  vlm_ln2_w  = (const float*)d_in[6];
        vlm_q_w    = (const float*)d_in[7];  vlm_k_w    = (const float*)d_in[8];
        vlm_v_w    = (const float*)d_in[9];  vlm_o_w    = (const float*)d_in[10];
        vlm_gate_w = (const float*)d_in[11]; vlm_up_w   = (const float*)d_in[12];
        vlm_down_w = (const float*)d_in[13];
        exp_ln1_dw = (const float*)d_in[14]; exp_ln1_db = (const float*)d_in[15];
        exp_ln2_dw = (const float*)d_in[16]; exp_ln2_db = (const float*)d_in[17];
        exp_q_w    = (const float*)d_in[18]; exp_k_w    = (const float*)d_in[19];
        exp_v_w    = (const float*)d_in[20]; exp_o_w    = (const float*)d_in[21];
        exp_gate_w = (const float*)d_in[22]; exp_up_w   = (const float*)d_in[23];
        exp_down_w = (const float*)d_in[24];
    } else {
        embeds_vlm = (const float*)d_in[0];  embeds_exp = (const float*)d_in[1];
        cond       = (const float*)d_in[2];
        vlm_ln1_w  = (const float*)d_in[3];  vlm_ln2_w  = (const float*)d_in[4];
        vlm_q_w    = (const float*)d_in[5];  vlm_k_w    = (const float*)d_in[6];
        vlm_v_w    = (const float*)d_in[7];  vlm_o_w    = (const float*)d_in[8];
        vlm_gate_w = (const float*)d_in[9];  vlm_up_w   = (const float*)d_in[10];
        vlm_down_w = (const float*)d_in[11];
        exp_ln1_dw = (const float*)d_in[12]; exp_ln1_db = (const float*)d_in[13];
        exp_ln2_dw = (const float*)d_in[14]; exp_ln2_db = (const float*)d_in[15];
        exp_q_w    = (const float*)d_in[16]; exp_k_w    = (const float*)d_in[17];
        exp_v_w    = (const float*)d_in[18]; exp_v_w    = (const float*)d_in[18];
        exp_o_w    = (const float*)d_in[19];
        exp_gate_w = (const float*)d_in[20]; exp_up_w   = (const float*)d_in[21];
        exp_down_w = (const float*)d_in[22];
        pos        = (const int*)  d_in[23];
        attn_mask  = (const float*)d_in[24];
    }

    float *hv, *he, *mod1, *mod2, *q, *qt, *k, *v, *logits, *attnt, *attn;
    float *hv1, *he1, *mg, *mu, *tmp, *eg, *eu, *etmp, *wb;
    GETSYM(hv, g_hv);   GETSYM(he, g_he);   GETSYM(mod1, g_mod1); GETSYM(mod2, g_mod2);
    GETSYM(q, g_q);     GETSYM(qt, g_qt);   GETSYM(k, g_k);       GETSYM(v, g_v);
    GETSYM(logits, g_logits); GETSYM(attnt, g_attnt); GETSYM(attn, g_attn);
    GETSYM(hv1, g_hv1); GETSYM(he1, g_he1); GETSYM(mg, g_mg);     GETSYM(mu, g_mu);
    GETSYM(tmp, g_tmp); GETSYM(eg, g_eg);   GETSYM(eu, g_eu);     GETSYM(etmp, g_etmp);
    GETSYM(wb, g_wbuf);

    // --- fused weight pre-round: one kernel, 14 weights ---
    const float* srcs[NW] = {vlm_q_w, vlm_k_w, vlm_v_w, vlm_o_w, vlm_gate_w, vlm_up_w, vlm_down_w,
                             exp_q_w, exp_k_w, exp_v_w, exp_o_w, exp_gate_w, exp_up_w, exp_down_w};
    long long cnts[NW] = {
        (long long)W_V_*H_*DH_, (long long)W_V_*DH_, (long long)W_V_*DH_, (long long)H_*DH_*W_V_,
        (long long)W_V_*MLPV_, (long long)W_V_*MLPV_, (long long)MLPV_*W_V_,
        (long long)W_E_*H_*DH_, (long long)W_E_*DH_, (long long)W_E_*DH_, (long long)H_*DH_*W_E_,
        (long long)W_E_*MLPE_, (long long)W_E_*MLPE_, (long long)MLPE_*W_E_};
    RoundDesc rd;
    long long ofs = 0; int blk = 0;
    const float* wptr[NW];
    for (int i = 0; i < NW; i++) {
        rd.src[i] = (const float4*)srcs[i];
        rd.dofs[i] = ofs;
        rd.blkStart[i] = blk;
        wptr[i] = wb + ofs;
        ofs += cnts[i];
        blk += (int)(cnts[i] / 4096);
    }
    rd.blkStart[NW] = blk;
    const float *w_vq = wptr[0], *w_vk = wptr[1], *w_vv = wptr[2], *w_vo = wptr[3];
    const float *w_vg = wptr[4], *w_vu = wptr[5], *w_vd = wptr[6];
    const float *w_eq = wptr[7], *w_ek = wptr[8], *w_ev = wptr[9], *w_eo = wptr[10];
    const float *w_egw = wptr[11], *w_euw = wptr[12], *w_ed = wptr[13];

    const int SM0 = 4 * (AST + 16 * 136) * 4;    // TB=0 smem bytes
    const int SM1 = 4 * (AST + 128 * 20) * 4;    // TB=1 smem bytes
    cudaFuncSetAttribute(gemm_cp<0,0>, cudaFuncAttributeMaxDynamicSharedMemorySize, SM0);
    cudaFuncSetAttribute(gemm_cp<0,1>, cudaFuncAttributeMaxDynamicSharedMemorySize, SM0);
    cudaFuncSetAttribute(gemm_cp<1,0>, cudaFuncAttributeMaxDynamicSharedMemorySize, SM1);

    float* out_v = (float*)d_out;
    float* out_e = (float*)d_out + (long long)B_ * S_V_ * W_V_;

    // launch order chosen so ncu (-s 5 -c 1) captures the VLM Q GEMM:
    // 0 rms_scale, 1 modmm(mod1), 2 rms_mod, 3 modmm(mod2), 4 round_many, 5 Q-vlm GEMM
    rms_scale<<<B_ * S_V_, 256>>>(embeds_vlm, vlm_ln1_w, hv, W_V_);
    modmm<<<(B_ * 3 * W_E_ + 255) / 256, 256>>>(cond, exp_ln1_dw, exp_ln1_db, mod1);
    rms_mod<<<B_ * S_E_, 256>>>(embeds_exp, mod1, he, W_E_, S_E_);
    modmm<<<(B_ * 3 * W_E_ + 255) / 256, 256>>>(cond, exp_ln2_dw, exp_ln2_db, mod2);
    round_many<<<blk, 256>>>(rd, wb);

    // QKV projections
    {
        long long sHv = (long long)S_V_ * W_V_, sHe = (long long)S_E_ * W_E_;
        long long sQ = (long long)S_ * H_ * DH_, sK = (long long)S_ * DH_;
        gemm_cp<0,0><<<dim3(16, 6, B_), 256, SM0>>>(hv, w_vq, q, S_V_, H_ * DH_, W_V_, sHv, 0, sQ, 1);
        gemm_cp<0,0><<<dim3(16, 1, B_), 256, SM0>>>(he, w_eq, q + (long long)S_V_ * H_ * DH_, S_E_, H_ * DH_, W_E_, sHe, 0, sQ, 1);
        gemm_cp<0,0><<<dim3(2, 6, B_), 256, SM0>>>(hv, w_vk, k, S_V_, DH_, W_V_, sHv, 0, sK, 1);
        gemm_cp<0,0><<<dim3(2, 1, B_), 256, SM0>>>(he, w_ek, k + S_V_ * DH_, S_E_, DH_, W_E_, sHe, 0, sK, 1);
        gemm_cp<0,1><<<dim3(2, 6, B_), 256, SM0>>>(hv, w_vv, v, S_V_, DH_, W_V_, sHv, 0, sK, 1);
        gemm_cp<0,1><<<dim3(2, 1, B_), 256, SM0>>>(he, w_ev, v + S_V_ * DH_, S_E_, DH_, W_E_, sHe, 0, sK, 1);
    }

    // RoPE (rounds q, k to tf32)
    rope_kernel<<<(B_ * S_ * H_ * 128 + 255) / 256, 256>>>(q, pos, H_);
    rope_kernel<<<(B_ * S_ * 1 * 128 + 255) / 256, 256>>>(k, pos, 1);

    // attention
    {
        long long nq = (long long)B_ * H_ * S_ * DH_;
        q_to_bhsd<<<(int)((nq + 255) / 256), 256>>>(q, qt);
        long long sQ = (long long)S_ * DH_, sKV = (long long)S_ * DH_, sL = (long long)S_ * S_;
        gemm_cp<1,0><<<dim3(7, 7, B_ * H_), 256, SM1>>>(qt, k, logits, S_, S_, DH_, sQ, sKV, sL, H_);
        softmax_mask<<<B_ * H_ * S_, 256>>>(logits, attn_mask);
        gemm_cp<0,0><<<dim3(2, 7, B_ * H_), 256, SM0>>>(logits, v, attnt, S_, DH_, S_, sL, sKV, sQ, H_);
        bhsd_to_bshd<<<(int)((nq + 255) / 256), 256>>>(attnt, attn);
    }

    // output projections + residual
    {
        long long sA = (long long)S_ * H_ * DH_;
        gemm_cp<0,0><<<dim3(16, 6, B_), 256, SM0>>>(attn, w_vo, hv1, S_V_, W_V_, H_ * DH_, sA, 0, (long long)S_V_ * W_V_, 1);
        ew_add4<<<(B_ * S_V_ * W_V_ / 4 + 255) / 256, 256>>>((float4*)hv1, (const float4*)embeds_vlm, B_ * S_V_ * W_V_ / 4);
        gemm_cp<0,0><<<dim3(8, 1, B_), 256, SM0>>>(attn + (long long)S_V_ * H_ * DH_, w_eo, he1, S_E_, W_E_, H_ * DH_, sA, 0, (long long)S_E_ * W_E_, 1);
        ew_gate_res<<<(B_ * S_E_ * W_E_ + 255) / 256, 256>>>(he1, embeds_exp, mod1, B_ * S_E_ * W_E_);
    }

    // pre-MLP norms
    rms_scale<<<B_ * S_V_, 256>>>(hv1, vlm_ln2_w, hv, W_V_);
    rms_mod<<<B_ * S_E_, 256>>>(he1, mod2, he, W_E_, S_E_);

    // VLM MLP
    {
        int M = B_ * S_V_;
        gemm_cp<0,0><<<dim3(128, 24, 1), 256, SM0>>>(hv, w_vg, mg, M, MLPV_, W_V_, 0, 0, 0, 1);
        gemm_cp<0,0><<<dim3(128, 24, 1), 256, SM0>>>(hv, w_vu, mu, M, MLPV_, W_V_, 0, 0, 0, 1);
        long long n4 = (long long)M * MLPV_ / 4;
        gelu_mul4<<<(int)((n4 + 255) / 256), 256>>>((float4*)mg, (const float4*)mu, n4);
        gemm_cp<0,0><<<dim3(16, 24, 1), 256, SM0>>>(mg, w_vd, tmp, M, W_V_, MLPV_, 0, 0, 0, 1);
        ew_final_v<<<(B_ * S_V_ * W_V_ + 255) / 256, 256>>>(out_v, hv1, tmp, B_ * S_V_ * W_V_);
    }

    // expert MLP
    {
        int M = B_ * S_E_;
        gemm_cp<0,0><<<dim3(32, 2, 1), 256, SM0>>>(he, w_egw, eg, M, MLPE_, W_E_, 0, 0, 0, 1);
        gemm_cp<0,0><<<dim3(32, 2, 1), 256, SM0>>>(he, w_euw, eu, M, MLPE_, W_E_, 0, 0, 0, 1);
        long long n4 = (long long)M * MLPE_ / 4;
        gelu_mul4<<<(int)((n4 + 255) / 256), 256>>>((float4*)eg, (const float4*)eu, n4);
        gemm_cp<0,0><<<dim3(8, 2, 1), 256, SM0>>>(eg, w_ed, etmp, M, W_E_, MLPE_, 0, 0, 0, 1);
        ew_final_e<<<(B_ * S_E_ * W_E_ + 255) / 256, 256>>>(out_e, he1, etmp, mod2, B_ * S_E_ * W_E_);
    }
}

// round 5
// speedup vs baseline: 4.2659x; 1.0226x over previous
#include <cuda_runtime.h>
#include <cuda_bf16.h>
#include <math.h>

#define B_    4
#define S_V_  768
#define S_E_  64
#define S_    832
#define W_V_  2048
#define W_E_  1024
#define H_    8
#define DH_   256
#define MLPV_ 16384
#define MLPE_ 4096
#define EPS_  1e-6f
#define SCALE_ 0.0625f  // 256^-0.5

// ---------------- scratch (device globals; no allocations) ----------------
__device__ float g_hv   [B_*S_V_*W_V_];
__device__ float g_he   [B_*S_E_*W_E_];
__device__ float g_mod1 [B_*3*W_E_];
__device__ float g_mod2 [B_*3*W_E_];
__device__ float g_q    [(long long)B_*S_*H_*DH_];
__device__ float g_qt   [(long long)B_*H_*S_*DH_];
__device__ float g_k    [B_*S_*DH_];
__device__ float g_v    [B_*S_*DH_];
__device__ float g_logits[(long long)B_*H_*S_*S_];
__device__ float g_attnt[(long long)B_*H_*S_*DH_];
__device__ float g_attn [(long long)B_*S_*H_*DH_];
__device__ float g_hv1  [B_*S_V_*W_V_];
__device__ float g_he1  [B_*S_E_*W_E_];
__device__ float g_mg   [(long long)B_*S_V_*MLPV_];
__device__ float g_mu   [(long long)B_*S_V_*MLPV_];
__device__ float g_eg   [B_*S_E_*MLPE_];
__device__ float g_eu   [B_*S_E_*MLPE_];
__device__ float g_wbuf [127401984];   // tf32-rounded weights

// ---------------- tf32 helpers ----------------
__device__ __forceinline__ float tf32r(float x) {
    unsigned u;
    asm("cvt.rna.tf32.f32 %0, %1;" : "=r"(u) : "f"(x));
    return __uint_as_float(u);
}

__device__ __forceinline__ float gelu_t(float x) {
    return 0.5f * x * (1.f + tanhf(0.7978845608028654f * (x + 0.044715f * x * x * x)));
}

__device__ __forceinline__ void mma_tf32(float* c, const unsigned* a, const unsigned* b) {
    asm volatile(
        "mma.sync.aligned.m16n8k8.row.col.f32.tf32.tf32.f32 "
        "{%0,%1,%2,%3}, {%4,%5,%6,%7}, {%8,%9}, {%0,%1,%2,%3};\n"
        : "+f"(c[0]), "+f"(c[1]), "+f"(c[2]), "+f"(c[3])
        : "r"(a[0]), "r"(a[1]), "r"(a[2]), "r"(a[3]), "r"(b[0]), "r"(b[1]));
}

// ---------------- cp.async tf32 GEMM, 128x128 tile ----------------
// C(M,N) = A(M,K) * B.  TB==0: B (K,N) row-major. TB==1: B (N,K) row-major.
// EPI: 0 plain, 1 tf32-round, 2 tf32r(gelu(c)*aux), 3 c+aux,
//      4 aux + c*mod[(z+gm/S_E)*3W_E + 2W_E + gn]  (gated residual)
// aux is indexed like C (offset by z*sC).
#define AST (128*20)
template<int TB, int EPI>
__global__ __launch_bounds__(256, 2)
void gemm_cp(const float* __restrict__ A, const float* __restrict__ Bm,
             float* __restrict__ C, const float* __restrict__ aux,
             const float* __restrict__ modv,
             int M, int N, int K,
             long long sA, long long sB, long long sC, int bInner)
{
    constexpr int BST = TB ? 128*20 : 16*136;
    extern __shared__ __align__(16) float sm[];
    float* Abase = sm;
    float* Bbase = sm + 4*AST;

    const int z = blockIdx.z;
    A  += (long long)z * sA;
    Bm += (long long)(z / bInner) * sB;
    C  += (long long)z * sC;
    if (EPI >= 2) aux += (long long)z * sC;

    const int tid  = threadIdx.x;
    const int lane = tid & 31;
    const int wid  = tid >> 5;
    const int wm   = (wid & 1) * 64;
    const int wn   = (wid >> 1) * 32;
    const int bm   = blockIdx.y * 128;
    const int bn   = blockIdx.x * 128;
    const int row  = lane >> 2, col = lane & 3;

    unsigned sbase = (unsigned)__cvta_generic_to_shared(sm);

    auto issue = [&](int st) {
        const int ktE  = st * 16;
        const int slot = st & 3;
#pragma unroll
        for (int j = 0; j < 2; j++) {            // A: 128x16
            int id = tid + j * 256;
            int r = id >> 2, kc = (id & 3) << 2;
            int gm = bm + r;
            const float* gp = A + (long long)(gm < M ? gm : M - 1) * K + ktE + kc;
            unsigned dst = sbase + (unsigned)(slot * AST + r * 20 + kc) * 4u;
            int zf = (gm < M) ? 16 : 0;
            asm volatile("cp.async.cg.shared.global [%0], [%1], 16, %2;\n"
                         :: "r"(dst), "l"(gp), "r"(zf));
        }
#pragma unroll
        for (int j = 0; j < 2; j++) {            // B: 16x128 (or 128x16)
            int id = tid + j * 256;
            unsigned dst; const float* gp; int zf;
            if (TB) {
                int n = id >> 2, kc = (id & 3) << 2;
                int gn = bn + n;
                gp  = Bm + (long long)(gn < N ? gn : N - 1) * K + ktE + kc;
                dst = sbase + (unsigned)(4 * AST + slot * BST + n * 20 + kc) * 4u;
                zf  = (gn < N) ? 16 : 0;
            } else {
                int kr = id >> 5, nc = (id & 31) << 2;
                int gn = bn + nc;
                gp  = Bm + (long long)(ktE + kr) * N + (gn < N ? gn : N - 4);
                dst = sbase + (unsigned)(4 * AST + slot * BST + kr * 136 + nc) * 4u;
                zf  = (gn < N) ? 16 : 0;
            }
            asm volatile("cp.async.cg.shared.global [%0], [%1], 16, %2;\n"
                         :: "r"(dst), "l"(gp), "r"(zf));
        }
    };

    float c[4][4][4];
#pragma unroll
    for (int i = 0; i < 4; i++)
#pragma unroll
        for (int j = 0; j < 4; j++)
#pragma unroll
            for (int l = 0; l < 4; l++) c[i][j][l] = 0.f;

    const int nk = K / 16;
#pragma unroll 1
    for (int s = 0; s < 3; s++) {
        issue(s);
        asm volatile("cp.async.commit_group;\n");
    }

#pragma unroll 1
    for (int kt = 0; kt < nk; kt++) {
        asm volatile("cp.async.wait_group 2;\n");
        __syncthreads();
        if (kt + 3 < nk) issue(kt + 3);
        asm volatile("cp.async.commit_group;\n");

        const float* Ab = Abase + (kt & 3) * AST;
        const float* Bb = Bbase + (kt & 3) * BST;
#pragma unroll
        for (int ks = 0; ks < 2; ks++) {
            const int k8 = ks * 8;
            unsigned af[4][4], bf[4][2];
#pragma unroll
            for (int mt = 0; mt < 4; mt++) {
                const float* p = Ab + (wm + mt * 16 + row) * 20 + k8 + col;
                af[mt][0] = __float_as_uint(p[0]);
                af[mt][1] = __float_as_uint(p[8 * 20]);
                af[mt][2] = __float_as_uint(p[4]);
                af[mt][3] = __float_as_uint(p[8 * 20 + 4]);
            }
#pragma unroll
            for (int nt = 0; nt < 4; nt++) {
                int n0 = wn + nt * 8 + row;
                if (TB) {
                    const float* p = Bb + n0 * 20 + k8 + col;
                    bf[nt][0] = __float_as_uint(p[0]);
                    bf[nt][1] = __float_as_uint(p[4]);
                } else {
                    const float* p = Bb + (k8 + col) * 136 + n0;
                    bf[nt][0] = __float_as_uint(p[0]);
                    bf[nt][1] = __float_as_uint(p[4 * 136]);
                }
            }
#pragma unroll
            for (int mt = 0; mt < 4; mt++)
#pragma unroll
                for (int nt = 0; nt < 4; nt++)
                    mma_tf32(c[mt][nt], af[mt], bf[nt]);
        }
    }

    // epilogue
    auto epi_store = [&](int gm, int gn, float x0, float x1) {
        long long o = (long long)gm * N + gn;
        float2 r;
        if (EPI == 0) {
            r = make_float2(x0, x1);
        } else if (EPI == 1) {
            r = make_float2(tf32r(x0), tf32r(x1));
        } else if (EPI == 2) {
            float2 u = *(const float2*)(aux + o);
            r = make_float2(tf32r(gelu_t(x0) * u.x), tf32r(gelu_t(x1) * u.y));
        } else if (EPI == 3) {
            float2 u = *(const float2*)(aux + o);
            r = make_float2(x0 + u.x, x1 + u.y);
        } else {
            int bb = z + gm / S_E_;
            float g0 = modv[(long long)bb * 3 * W_E_ + 2 * W_E_ + gn];
            float g1 = modv[(long long)bb * 3 * W_E_ + 2 * W_E_ + gn + 1];
            float2 u = *(const float2*)(aux + o);
            r = make_float2(u.x + x0 * g0, u.y + x1 * g1);
        }
        *(float2*)(C + o) = r;
    };

#pragma unroll
    for (int mt = 0; mt < 4; mt++) {
#pragma unroll
        for (int nt = 0; nt < 4; nt++) {
            int gm = bm + wm + mt * 16 + row;
            int gn = bn + wn + nt * 8 + col * 2;
            if (gn < N) {
                if (gm < M)     epi_store(gm,     gn, c[mt][nt][0], c[mt][nt][1]);
                if (gm + 8 < M) epi_store(gm + 8, gn, c[mt][nt][2], c[mt][nt][3]);
            }
        }
    }
}

// ---------------- weight tf32 pre-round ----------------
__global__ void round4(const float4* __restrict__ s, float4* __restrict__ d, int n4)
{
    int i = blockIdx.x * 256 + threadIdx.x;
    if (i >= n4) return;
    float4 v = s[i];
    v.x = tf32r(v.x); v.y = tf32r(v.y); v.z = tf32r(v.z); v.w = tf32r(v.w);
    d[i] = v;
}

#define NW 13
struct RoundDesc {
    const float4* src[NW];
    long long dofs[NW];
    int blkStart[NW + 1];     // each block = 4096 floats
};

__global__ void round_many(RoundDesc d, float* __restrict__ wbuf)
{
    int b = blockIdx.x;
    int w = 0;
#pragma unroll
    for (int i = 0; i < NW; i++) if (b >= d.blkStart[i + 1]) w = i + 1;
    int lb = b - d.blkStart[w];
    const float4* s = d.src[w] + (long long)lb * 1024;
    float4* o = (float4*)(wbuf + d.dofs[w]) + (long long)lb * 1024;
    int t = threadIdx.x;
    float4 v[4];
#pragma unroll
    for (int i = 0; i < 4; i++) v[i] = s[t + i * 256];
#pragma unroll
    for (int i = 0; i < 4; i++) {
        v[i].x = tf32r(v[i].x); v[i].y = tf32r(v[i].y);
        v[i].z = tf32r(v[i].z); v[i].w = tf32r(v[i].w);
    }
#pragma unroll
    for (int i = 0; i < 4; i++) o[t + i * 256] = v[i];
}

// ---------------- row kernels ----------------
__device__ __forceinline__ float blockReduceSum(float v) {
    __shared__ float red[256];
    int t = threadIdx.x;
    red[t] = v; __syncthreads();
    for (int s = 128; s > 0; s >>= 1) {
        if (t < s) red[t] += red[t + s];
        __syncthreads();
    }
    float r = red[0];
    __syncthreads();
    return r;
}

__global__ void rms_scale(const float* __restrict__ x, const float* __restrict__ w,
                          float* __restrict__ out, int W)
{
    long long base = (long long)blockIdx.x * W;
    float ss = 0.f;
    for (int c = threadIdx.x; c < W; c += 256) { float t = x[base + c]; ss += t * t; }
    float tot = blockReduceSum(ss);
    float inv = rsqrtf(tot / (float)W + EPS_);
    for (int c = threadIdx.x; c < W; c += 256)
        out[base + c] = tf32r(x[base + c] * inv * (1.f + w[c]));
}

__global__ void rms_mod(const float* __restrict__ x, const float* __restrict__ mod,
                        float* __restrict__ out, int W, int rowsPerB)
{
    long long base = (long long)blockIdx.x * W;
    int b = blockIdx.x / rowsPerB;
    const float* m = mod + (long long)b * 3 * W;
    float ss = 0.f;
    for (int c = threadIdx.x; c < W; c += 256) { float t = x[base + c]; ss += t * t; }
    float tot = blockReduceSum(ss);
    float inv = rsqrtf(tot / (float)W + EPS_);
    for (int c = threadIdx.x; c < W; c += 256)
        out[base + c] = tf32r(x[base + c] * inv * (1.f + m[c]) + m[W + c]);
}

// mod = cond @ W + bias, K-split by 4, cond in smem. grid (48, B_), 256 thr.
__global__ void modmm2(const float* __restrict__ cond, const float* __restrict__ W,
                       const float* __restrict__ bias, float* __restrict__ out)
{
    const int NT = 3 * W_E_;
    __shared__ float cs[W_E_];
    __shared__ float part[4][64];
    int bb = blockIdx.y;
    int tid = threadIdx.x;
    for (int i = tid; i < W_E_; i += 256) cs[i] = cond[bb * W_E_ + i];
    __syncthreads();
    int tx = tid & 63, ty = tid >> 6;
    int c = blockIdx.x * 64 + tx;
    const float* Wp = W + (long long)(ty * 256) * NT + c;
    const float* cp = cs + ty * 256;
    float s = 0.f;
#pragma unroll 4
    for (int k = 0; k < 256; k++) s += cp[k] * Wp[(long long)k * NT];
    part[ty][tx] = s;
    __syncthreads();
    if (ty == 0)
        out[(long long)bb * NT + c] = part[0][tx] + part[1][tx] + part[2][tx] + part[3][tx] + bias[c];
}

// RoPE, float4 per thread over half-dim
__global__ void rope4(float* __restrict__ x, const int* __restrict__ pos, int nh)
{
    int idx = blockIdx.x * blockDim.x + threadIdx.x;
    int total = B_ * S_ * nh * 32;
    if (idx >= total) return;
    int d4 = (idx & 31) << 2;
    int h = (idx >> 5) % nh;
    int s = (idx / (32 * nh)) % S_;
    int b = idx / (32 * nh * S_);
    float p = (float)pos[b * S_ + s];
    float* base = x + (((long long)(b * S_ + s) * nh + h) << 8);
    float4 x1 = *(float4*)(base + d4);
    float4 x2 = *(float4*)(base + d4 + 128);
    float r1[4] = {x1.x, x1.y, x1.z, x1.w};
    float r2[4] = {x2.x, x2.y, x2.z, x2.w};
#pragma unroll
    for (int j = 0; j < 4; j++) {
        float ang = p * powf(10000.f, -(float)(2 * (d4 + j)) / 256.f);
        float sn, cs2; sincosf(ang, &sn, &cs2);
        float a = r1[j], bb = r2[j];
        r1[j] = tf32r(a * cs2 - bb * sn);
        r2[j] = tf32r(bb * cs2 + a * sn);
    }
    *(float4*)(base + d4)       = make_float4(r1[0], r1[1], r1[2], r1[3]);
    *(float4*)(base + d4 + 128) = make_float4(r2[0], r2[1], r2[2], r2[3]);
}

__global__ void q_to_bhsd4(const float4* __restrict__ q, float4* __restrict__ qt)
{
    int idx = blockIdx.x * blockDim.x + threadIdx.x;
    int total = B_ * H_ * S_ * 64;
    if (idx >= total) return;
    int d = (idx & 63) << 2;
    int s = (idx >> 6) % S_;
    int h = (idx / (64 * S_)) % H_;
    int b = idx / (64 * S_ * H_);
    qt[idx] = q[((((long long)(b * S_ + s) * H_ + h) << 8) + d) >> 2];
}

__global__ void bhsd_to_bshd4(const float4* __restrict__ a, float4* __restrict__ o)
{
    int idx = blockIdx.x * blockDim.x + threadIdx.x;
    int total = B_ * S_ * H_ * 64;
    if (idx >= total) return;
    int d = (idx & 63) << 2;
    int h = (idx >> 6) % H_;
    int s = (idx / (64 * H_)) % S_;
    int b = idx / (64 * H_ * S_);
    float4 v = a[((((long long)(b * H_ + h) * S_ + s) << 8) + d) >> 2];
    v.x = tf32r(v.x); v.y = tf32r(v.y); v.z = tf32r(v.z); v.w = tf32r(v.w);
    o[idx] = v;
}

// single-pass float4 softmax (row = 832 = 208 float4), grid B*H*S rows
__global__ void softmax4(float* __restrict__ logits, const float* __restrict__ mask)
{
    int rowid = blockIdx.x;
    int b = rowid / (H_ * S_);
    int q = rowid % S_;
    float4* row = (float4*)(logits + (long long)rowid * S_);
    const float4* m = (const float4*)(mask + ((long long)b * S_ + q) * S_);
    int t = threadIdx.x;
    const bool act = t < 208;
    float4 v = make_float4(-1e30f, -1e30f, -1e30f, -1e30f);
    if (act) {
        float4 lv = row[t], mv = m[t];
        v.x = lv.x * SCALE_ + mv.x; v.y = lv.y * SCALE_ + mv.y;
        v.z = lv.z * SCALE_ + mv.z; v.w = lv.w * SCALE_ + mv.w;
    }
    float mx = fmaxf(fmaxf(v.x, v.y), fmaxf(v.z, v.w));
    __shared__ float red[256];
    red[t] = mx; __syncthreads();
    for (int s = 128; s > 0; s >>= 1) { if (t < s) red[t] = fmaxf(red[t], red[t + s]); __syncthreads(); }
    mx = red[0]; __syncthreads();
    float sum = 0.f;
    if (act) {
        v.x = __expf(v.x - mx); v.y = __expf(v.y - mx);
        v.z = __expf(v.z - mx); v.w = __expf(v.w - mx);
        sum = v.x + v.y + v.z + v.w;
    }
    red[t] = sum; __syncthreads();
    for (int s = 128; s > 0; s >>= 1) { if (t < s) red[t] += red[t + s]; __syncthreads(); }
    float inv = 1.f / red[0];
    if (act)
        row[t] = make_float4(tf32r(v.x * inv), tf32r(v.y * inv), tf32r(v.z * inv), tf32r(v.w * inv));
}

// ---------------- host launch ----------------
#define GETSYM(var, sym) do { void* p__; cudaGetSymbolAddress(&p__, sym); var = (float*)p__; } while (0)

extern "C" void kernel_launch(void* const* d_in, const int* in_sizes, int n_in,
                              void* d_out, int out_size)
{
    const float *embeds_vlm, *embeds_exp, *cond, *attn_mask;
    const int* pos;
    const float *vlm_ln1_w, *vlm_ln2_w, *vlm_q_w, *vlm_k_w, *vlm_v_w, *vlm_o_w;
    const float *vlm_gate_w, *vlm_up_w, *vlm_down_w;
    const float *exp_ln1_dw, *exp_ln1_db, *exp_ln2_dw, *exp_ln2_db;
    const float *exp_q_w, *exp_k_w, *exp_v_w, *exp_o_w, *exp_gate_w, *exp_up_w, *exp_down_w;

    if (in_sizes[3] == B_ * S_) {
        embeds_vlm = (const float*)d_in[0];  embeds_exp = (const float*)d_in[1];
        cond       = (const float*)d_in[2];  pos        = (const int*)  d_in[3];
        attn_mask  = (const float*)d_in[4];
        vlm_ln1_w  = (const float*)d_in[5];  vlm_ln2_w  = (const float*)d_in[6];
        vlm_q_w    = (const float*)d_in[7];  vlm_k_w    = (const float*)d_in[8];
        vlm_v_w    = (const float*)d_in[9];  vlm_o_w    = (const float*)d_in[10];
        vlm_gate_w = (const float*)d_in[11]; vlm_up_w   = (const float*)d_in[12];
        vlm_down_w = (const float*)d_in[13];
        exp_ln1_dw = (const float*)d_in[14]; exp_ln1_db = (const float*)d_in[15];
        exp_ln2_dw = (const float*)d_in[16]; exp_ln2_db = (const float*)d_in[17];
        exp_q_w    = (const float*)d_in[18]; exp_k_w    = (const float*)d_in[19];
        exp_v_w    = (const float*)d_in[20]; exp_o_w    = (const float*)d_in[21];
        exp_gate_w = (const float*)d_in[22]; exp_up_w   = (const float*)d_in[23];
        exp_down_w = (const float*)d_in[24];
    } else {
        embeds_vlm = (const float*)d_in[0];  embeds_exp = (const float*)d_in[1];
        cond       = (const float*)d_in[2];
        vlm_ln1_w  = (const float*)d_in[3];  vlm_ln2_w  = (const float*)d_in[4];
        vlm_q_w    = (const float*)d_in[5];  vlm_k_w    = (const float*)d_in[6];
        vlm_v_w    = (const float*)d_in[7];  vlm_o_w    = (const float*)d_in[8];
        vlm_gate_w = (const float*)d_in[9];  vlm_up_w   = (const float*)d_in[10];
        vlm_down_w = (const float*)d_in[11];
        exp_ln1_dw = (const float*)d_in[12]; exp_ln1_db = (const float*)d_in[13];
        exp_ln2_dw = (const float*)d_in[14]; exp_ln2_db = (const float*)d_in[15];
        exp_q_w    = (const float*)d_in[16]; exp_k_w    = (const float*)d_in[17];
        exp_v_w    = (const float*)d_in[18]; exp_o_w    = (const float*)d_in[19];
        exp_gate_w = (const float*)d_in[20]; exp_up_w   = (const float*)d_in[21];
        exp_down_w = (const float*)d_in[22];
        pos        = (const int*)  d_in[23];
        attn_mask  = (const float*)d_in[24];
    }

    float *hv, *he, *mod1, *mod2, *q, *qt, *k, *v, *logits, *attnt, *attn;
    float *hv1, *he1, *mg, *mu, *eg, *eu, *wb;
    GETSYM(hv, g_hv);   GETSYM(he, g_he);   GETSYM(mod1, g_mod1); GETSYM(mod2, g_mod2);
    GETSYM(q, g_q);     GETSYM(qt, g_qt);   GETSYM(k, g_k);       GETSYM(v, g_v);
    GETSYM(logits, g_logits); GETSYM(attnt, g_attnt); GETSYM(attn, g_attn);
    GETSYM(hv1, g_hv1); GETSYM(he1, g_he1); GETSYM(mg, g_mg);     GETSYM(mu, g_mu);
    GETSYM(eg, g_eg);   GETSYM(eu, g_eu);   GETSYM(wb, g_wbuf);

    // weight layout in wbuf: vq first (rounded separately, needed by launch 3)
    const long long n_vq = (long long)W_V_ * H_ * DH_;
    const float* srcs[NW] = {vlm_k_w, vlm_v_w, vlm_o_w, vlm_gate_w, vlm_up_w, vlm_down_w,
                             exp_q_w, exp_k_w, exp_v_w, exp_o_w, exp_gate_w, exp_up_w, exp_down_w};
    long long cnts[NW] = {
        (long long)W_V_*DH_, (long long)W_V_*DH_, (long long)H_*DH_*W_V_,
        (long long)W_V_*MLPV_, (long long)W_V_*MLPV_, (long long)MLPV_*W_V_,
        (long long)W_E_*H_*DH_, (long long)W_E_*DH_, (long long)W_E_*DH_, (long long)H_*DH_*W_E_,
        (long long)W_E_*MLPE_, (long long)W_E_*MLPE_, (long long)MLPE_*W_E_};
    RoundDesc rd;
    long long ofs = n_vq; int blk = 0;
    const float* wptr[NW];
    for (int i = 0; i < NW; i++) {
        rd.src[i] = (const float4*)srcs[i];
        rd.dofs[i] = ofs;
        rd.blkStart[i] = blk;
        wptr[i] = wb + ofs;
        ofs += cnts[i];
        blk += (int)(cnts[i] / 4096);
    }
    rd.blkStart[NW] = blk;
    const float* w_vq = wb;
    const float *w_vk = wptr[0], *w_vv = wptr[1], *w_vo = wptr[2];
    const float *w_vg = wptr[3], *w_vu = wptr[4], *w_vd = wptr[5];
    const float *w_eq = wptr[6], *w_ek = wptr[7], *w_ev = wptr[8], *w_eo = wptr[9];
    const float *w_egw = wptr[10], *w_euw = wptr[11], *w_ed = wptr[12];

    const int SM0 = 4 * (AST + 16 * 136) * 4;    // TB=0 smem bytes
    const int SM1 = 4 * (AST + 128 * 20) * 4;    // TB=1 smem bytes
    cudaFuncSetAttribute(gemm_cp<0,0>, cudaFuncAttributeMaxDynamicSharedMemorySize, SM0);
    cudaFuncSetAttribute(gemm_cp<0,1>, cudaFuncAttributeMaxDynamicSharedMemorySize, SM0);
    cudaFuncSetAttribute(gemm_cp<0,2>, cudaFuncAttributeMaxDynamicSharedMemorySize, SM0);
    cudaFuncSetAttribute(gemm_cp<0,3>, cudaFuncAttributeMaxDynamicSharedMemorySize, SM0);
    cudaFuncSetAttribute(gemm_cp<0,4>, cudaFuncAttributeMaxDynamicSharedMemorySize, SM0);
    cudaFuncSetAttribute(gemm_cp<1,0>, cudaFuncAttributeMaxDynamicSharedMemorySize, SM1);

    float* out_v = (float*)d_out;
    float* out_e = (float*)d_out + (long long)B_ * S_V_ * W_V_;

    long long sHv = (long long)S_V_ * W_V_, sHe = (long long)S_E_ * W_E_;
    long long sQ = (long long)S_ * H_ * DH_, sK = (long long)S_ * DH_;
    long long sL = (long long)S_ * S_;

    // L0: round vq only (critical for launch 3)
    round4<<<(int)((n_vq / 4 + 255) / 256), 256>>>((const float4*)vlm_q_w, (float4*)wb, (int)(n_vq / 4));
    // L1
    rms_scale<<<B_ * S_V_, 256>>>(embeds_vlm, vlm_ln1_w, hv, W_V_);
    // L2
    modmm2<<<dim3(48, B_), 256>>>(cond, exp_ln1_dw, exp_ln1_db, mod1);
    // L3: VLM Q projection (ncu capture target)
    gemm_cp<0,0><<<dim3(16, 6, B_), 256, SM0>>>(hv, w_vq, q, nullptr, nullptr, S_V_, H_ * DH_, W_V_, sHv, 0, sQ, 1);
    // L4: round remaining 13 weights
    round_many<<<blk, 256>>>(rd, wb);
    // L5, L6
    rms_mod<<<B_ * S_E_, 256>>>(embeds_exp, mod1, he, W_E_, S_E_);
    modmm2<<<dim3(48, B_), 256>>>(cond, exp_ln2_dw, exp_ln2_db, mod2);

    // QKV remainder
    gemm_cp<0,0><<<dim3(16, 1, B_), 256, SM0>>>(he, w_eq, q + (long long)S_V_ * H_ * DH_, nullptr, nullptr, S_E_, H_ * DH_, W_E_, sHe, 0, sQ, 1);
    gemm_cp<0,0><<<dim3(2, 6, B_), 256, SM0>>>(hv, w_vk, k, nullptr, nullptr, S_V_, DH_, W_V_, sHv, 0, sK, 1);
    gemm_cp<0,0><<<dim3(2, 1, B_), 256, SM0>>>(he, w_ek, k + S_V_ * DH_, nullptr, nullptr, S_E_, DH_, W_E_, sHe, 0, sK, 1);
    gemm_cp<0,1><<<dim3(2, 6, B_), 256, SM0>>>(hv, w_vv, v, nullptr, nullptr, S_V_, DH_, W_V_, sHv, 0, sK, 1);
    gemm_cp<0,1><<<dim3(2, 1, B_), 256, SM0>>>(he, w_ev, v + S_V_ * DH_, nullptr, nullptr, S_E_, DH_, W_E_, sHe, 0, sK, 1);

    // RoPE
    rope4<<<(B_ * S_ * H_ * 32 + 255) / 256, 256>>>(q, pos, H_);
    rope4<<<(B_ * S_ * 1 * 32 + 255) / 256, 256>>>(k, pos, 1);

    // attention
    {
        int nq4 = B_ * H_ * S_ * 64;
        q_to_bhsd4<<<(nq4 + 255) / 256, 256>>>((const float4*)q, (float4*)qt);
        gemm_cp<1,0><<<dim3(7, 7, B_ * H_), 256, SM1>>>(qt, k, logits, nullptr, nullptr, S_, S_, DH_, sK, sK, sL, H_);
        softmax4<<<B_ * H_ * S_, 256>>>(logits, attn_mask);
        gemm_cp<0,0><<<dim3(2, 7, B_ * H_), 256, SM0>>>(logits, v, attnt, nullptr, nullptr, S_, DH_, S_, sL, sK, sK, H_);
        bhsd_to_bshd4<<<(nq4 + 255) / 256, 256>>>((const float4*)attnt, (float4*)attn);
    }

    // output projections + residuals (fused epilogues)
    {
        long long sA = (long long)S_ * H_ * DH_;
        gemm_cp<0,3><<<dim3(16, 6, B_), 256, SM0>>>(attn, w_vo, hv1, embeds_vlm, nullptr, S_V_, W_V_, H_ * DH_, sA, 0, sHv, 1);
        gemm_cp<0,4><<<dim3(8, 1, B_), 256, SM0>>>(attn + (long long)S_V_ * H_ * DH_, w_eo, he1, embeds_exp, mod1, S_E_, W_E_, H_ * DH_, sA, 0, sHe, 1);
    }

    // pre-MLP norms
    rms_scale<<<B_ * S_V_, 256>>>(hv1, vlm_ln2_w, hv, W_V_);
    rms_mod<<<B_ * S_E_, 256>>>(he1, mod2, he, W_E_, S_E_);

    // VLM MLP (up, then gate with fused gelu*up, then down with fused residual)
    {
        int M = B_ * S_V_;
        gemm_cp<0,0><<<dim3(128, 24, 1), 256, SM0>>>(hv, w_vu, mu, nullptr, nullptr, M, MLPV_, W_V_, 0, 0, 0, 1);
        gemm_cp<0,2><<<dim3(128, 24, 1), 256, SM0>>>(hv, w_vg, mg, mu, nullptr, M, MLPV_, W_V_, 0, 0, 0, 1);
        gemm_cp<0,3><<<dim3(16, 24, 1), 256, SM0>>>(mg, w_vd, out_v, hv1, nullptr, M, W_V_, MLPV_, 0, 0, 0, 1);
    }

    // expert MLP
    {
        int M = B_ * S_E_;
        gemm_cp<0,0><<<dim3(32, 2, 1), 256, SM0>>>(he, w_euw, eu, nullptr, nullptr, M, MLPE_, W_E_, 0, 0, 0, 1);
        gemm_cp<0,2><<<dim3(32, 2, 1), 256, SM0>>>(he, w_egw, eg, eu, nullptr, M, MLPE_, W_E_, 0, 0, 0, 1);
        gemm_cp<0,4><<<dim3(8, 2, 1), 256, SM0>>>(eg, w_ed, out_e, he1, mod2, M, W_E_, MLPE_, 0, 0, 0, 1);
    }
}

// round 6
// speedup vs baseline: 4.3004x; 1.0081x over previous
#include <cuda_runtime.h>
#include <cuda_bf16.h>
#include <math.h>

#define B_    4
#define S_V_  768
#define S_E_  64
#define S_    832
#define W_V_  2048
#define W_E_  1024
#define H_    8
#define DH_   256
#define MLPV_ 16384
#define MLPE_ 4096
#define EPS_  1e-6f
#define SCALE_ 0.0625f  // 256^-0.5

// ---------------- scratch ----------------
__device__ float g_hv   [B_*S_V_*W_V_];
__device__ float g_he   [B_*S_E_*W_E_];
__device__ float g_mod1 [B_*3*W_E_];
__device__ float g_mod2 [B_*3*W_E_];
__device__ float g_q    [(long long)B_*S_*H_*DH_];
__device__ float g_qt   [(long long)B_*H_*S_*DH_];
__device__ float g_k    [B_*S_*DH_];
__device__ float g_v    [B_*S_*DH_];
__device__ float g_logits[(long long)B_*H_*S_*S_];
__device__ float g_attnt[(long long)B_*H_*S_*DH_];
__device__ float g_attn [(long long)B_*S_*H_*DH_];
__device__ float g_hv1  [B_*S_V_*W_V_];
__device__ float g_he1  [B_*S_E_*W_E_];
__device__ float g_mg   [(long long)B_*S_V_*MLPV_];
__device__ float g_mu   [(long long)B_*S_V_*MLPV_];
__device__ float g_eg   [B_*S_E_*MLPE_];
__device__ float g_eu   [B_*S_E_*MLPE_];
__device__ float g_wbuf [127401984];

// ---------------- tf32 helpers ----------------
__device__ __forceinline__ float tf32r(float x) {
    unsigned u;
    asm("cvt.rna.tf32.f32 %0, %1;" : "=r"(u) : "f"(x));
    return __uint_as_float(u);
}

__device__ __forceinline__ float gelu_t(float x) {
    return 0.5f * x * (1.f + tanhf(0.7978845608028654f * (x + 0.044715f * x * x * x)));
}

__device__ __forceinline__ void mma_tf32(float* c, const unsigned* a, const unsigned* b) {
    asm volatile(
        "mma.sync.aligned.m16n8k8.row.col.f32.tf32.tf32.f32 "
        "{%0,%1,%2,%3}, {%4,%5,%6,%7}, {%8,%9}, {%0,%1,%2,%3};\n"
        : "+f"(c[0]), "+f"(c[1]), "+f"(c[2]), "+f"(c[3])
        : "r"(a[0]), "r"(a[1]), "r"(a[2]), "r"(a[3]), "r"(b[0]), "r"(b[1]));
}

// ================= gemm32: TB=0, K-tile 32 (2x16 sub-tiles), 3 stages =================
// C(M,N) = A(M,K) * B(K,N row-major). Requires K%32==0, N%4==0.
// Block 128x128, 8 warps (2m x 4n), warp tile 64x32, 2 CTAs/SM.
// EPI: 0 plain, 2 tf32r(gelu(c)*aux), 3 c+aux, 4 aux + c*mod[..], 1 tf32-round
#define A16 (128*20)
#define B16 (16*136)
#define STG32 (2*A16 + 2*B16)   // 9472 floats per stage
template<int EPI>
__global__ __launch_bounds__(256, 2)
void gemm32(const float* __restrict__ A, const float* __restrict__ Bm,
            float* __restrict__ C, const float* __restrict__ aux,
            const float* __restrict__ modv,
            int M, int N, int K,
            long long sA, long long sB, long long sC, int bInner)
{
    extern __shared__ __align__(16) float sm[];

    const int z = blockIdx.z;
    A  += (long long)z * sA;
    Bm += (long long)(z / bInner) * sB;
    C  += (long long)z * sC;
    if (EPI >= 2) aux += (long long)z * sC;

    const int tid  = threadIdx.x;
    const int lane = tid & 31;
    const int wid  = tid >> 5;
    const int wm   = (wid & 1) * 64;
    const int wn   = (wid >> 1) * 32;
    const int bm   = blockIdx.y * 128;
    const int bn   = blockIdx.x * 128;
    const int row  = lane >> 2, col = lane & 3;

    unsigned sbase = (unsigned)__cvta_generic_to_shared(sm);

    auto issue = [&](int st) {
        const int ktE  = st * 32;
        const unsigned sb = sbase + (unsigned)((st % 3) * STG32) * 4u;
#pragma unroll
        for (int sub = 0; sub < 2; sub++) {
#pragma unroll
            for (int j = 0; j < 2; j++) {        // A: 128 x 16 per sub
                int id = tid + j * 256;
                int r = id >> 2, kc = (id & 3) << 2;
                int gm = bm + r;
                const float* gp = A + (long long)(gm < M ? gm : M - 1) * K + ktE + sub * 16 + kc;
                unsigned dst = sb + (unsigned)(sub * A16 + r * 20 + kc) * 4u;
                int zf = (gm < M) ? 16 : 0;
                asm volatile("cp.async.cg.shared.global [%0], [%1], 16, %2;\n"
                             :: "r"(dst), "l"(gp), "r"(zf));
            }
#pragma unroll
            for (int j = 0; j < 2; j++) {        // B: 16 x 128 per sub
                int id = tid + j * 256;
                int kr = id >> 5, nc = (id & 31) << 2;
                int gn = bn + nc;
                const float* gp = Bm + (long long)(ktE + sub * 16 + kr) * N + (gn < N ? gn : N - 4);
                unsigned dst = sb + (unsigned)(2 * A16 + sub * B16 + kr * 136 + nc) * 4u;
                int zf = (gn < N) ? 16 : 0;
                asm volatile("cp.async.cg.shared.global [%0], [%1], 16, %2;\n"
                             :: "r"(dst), "l"(gp), "r"(zf));
            }
        }
    };

    float c[4][4][4];
#pragma unroll
    for (int i = 0; i < 4; i++)
#pragma unroll
        for (int j = 0; j < 4; j++)
#pragma unroll
            for (int l = 0; l < 4; l++) c[i][j][l] = 0.f;

    const int nk = K / 32;
    issue(0); asm volatile("cp.async.commit_group;\n");
    issue(1); asm volatile("cp.async.commit_group;\n");

#pragma unroll 1
    for (int kt = 0; kt < nk; kt++) {
        asm volatile("cp.async.wait_group 1;\n");
        __syncthreads();
        if (kt + 2 < nk) { issue(kt + 2); }
        asm volatile("cp.async.commit_group;\n");

        const float* Ss = sm + (kt % 3) * STG32;
#pragma unroll
        for (int sub = 0; sub < 2; sub++) {
            const float* Ab = Ss + sub * A16;
            const float* Bb = Ss + 2 * A16 + sub * B16;
#pragma unroll
            for (int ks = 0; ks < 2; ks++) {
                const int k8 = ks * 8;
                unsigned af[4][4], bf[4][2];
#pragma unroll
                for (int mt = 0; mt < 4; mt++) {
                    const float* p = Ab + (wm + mt * 16 + row) * 20 + k8 + col;
                    af[mt][0] = __float_as_uint(p[0]);
                    af[mt][1] = __float_as_uint(p[8 * 20]);
                    af[mt][2] = __float_as_uint(p[4]);
                    af[mt][3] = __float_as_uint(p[8 * 20 + 4]);
                }
#pragma unroll
                for (int nt = 0; nt < 4; nt++) {
                    const float* p = Bb + (k8 + col) * 136 + wn + nt * 8 + row;
                    bf[nt][0] = __float_as_uint(p[0]);
                    bf[nt][1] = __float_as_uint(p[4 * 136]);
                }
#pragma unroll
                for (int mt = 0; mt < 4; mt++)
#pragma unroll
                    for (int nt = 0; nt < 4; nt++)
                        mma_tf32(c[mt][nt], af[mt], bf[nt]);
            }
        }
        __syncthreads();
    }

    auto epi_store = [&](int gm, int gn, float x0, float x1) {
        long long o = (long long)gm * N + gn;
        float2 r;
        if (EPI == 0) {
            r = make_float2(x0, x1);
        } else if (EPI == 1) {
            r = make_float2(tf32r(x0), tf32r(x1));
        } else if (EPI == 2) {
            float2 u = *(const float2*)(aux + o);
            r = make_float2(tf32r(gelu_t(x0) * u.x), tf32r(gelu_t(x1) * u.y));
        } else if (EPI == 3) {
            float2 u = *(const float2*)(aux + o);
            r = make_float2(x0 + u.x, x1 + u.y);
        } else {
            int bb = z + gm / S_E_;
            float g0 = modv[(long long)bb * 3 * W_E_ + 2 * W_E_ + gn];
            float g1 = modv[(long long)bb * 3 * W_E_ + 2 * W_E_ + gn + 1];
            float2 u = *(const float2*)(aux + o);
            r = make_float2(u.x + x0 * g0, u.y + x1 * g1);
        }
        *(float2*)(C + o) = r;
    };

#pragma unroll
    for (int mt = 0; mt < 4; mt++) {
#pragma unroll
        for (int nt = 0; nt < 4; nt++) {
            int gm = bm + wm + mt * 16 + row;
            int gn = bn + wn + nt * 8 + col * 2;
            if (gn < N) {
                if (gm < M)     epi_store(gm,     gn, c[mt][nt][0], c[mt][nt][1]);
                if (gm + 8 < M) epi_store(gm + 8, gn, c[mt][nt][2], c[mt][nt][3]);
            }
        }
    }
}

// ================= gemm_tb1: TB=1 (B (N,K) row-major), K-tile 16, 4 stages (R5 kernel) ===
#define AST (128*20)
__global__ __launch_bounds__(256, 2)
void gemm_tb1(const float* __restrict__ A, const float* __restrict__ Bm,
              float* __restrict__ C, int M, int N, int K,
              long long sA, long long sB, long long sC, int bInner)
{
    constexpr int BST = 128*20;
    extern __shared__ __align__(16) float sm[];
    float* Abase = sm;
    float* Bbase = sm + 4*AST;

    const int z = blockIdx.z;
    A  += (long long)z * sA;
    Bm += (long long)(z / bInner) * sB;
    C  += (long long)z * sC;

    const int tid  = threadIdx.x;
    const int lane = tid & 31;
    const int wid  = tid >> 5;
    const int wm   = (wid & 1) * 64;
    const int wn   = (wid >> 1) * 32;
    const int bm   = blockIdx.y * 128;
    const int bn   = blockIdx.x * 128;
    const int row  = lane >> 2, col = lane & 3;

    unsigned sbase = (unsigned)__cvta_generic_to_shared(sm);

    auto issue = [&](int st) {
        const int ktE  = st * 16;
        const int slot = st & 3;
#pragma unroll
        for (int j = 0; j < 2; j++) {
            int id = tid + j * 256;
            int r = id >> 2, kc = (id & 3) << 2;
            int gm = bm + r;
            const float* gp = A + (long long)(gm < M ? gm : M - 1) * K + ktE + kc;
            unsigned dst = sbase + (unsigned)(slot * AST + r * 20 + kc) * 4u;
            int zf = (gm < M) ? 16 : 0;
            asm volatile("cp.async.cg.shared.global [%0], [%1], 16, %2;\n"
                         :: "r"(dst), "l"(gp), "r"(zf));
        }
#pragma unroll
        for (int j = 0; j < 2; j++) {
            int id = tid + j * 256;
            int n = id >> 2, kc = (id & 3) << 2;
            int gn = bn + n;
            const float* gp = Bm + (long long)(gn < N ? gn : N - 1) * K + ktE + kc;
            unsigned dst = sbase + (unsigned)(4 * AST + slot * BST + n * 20 + kc) * 4u;
            int zf = (gn < N) ? 16 : 0;
            asm volatile("cp.async.cg.shared.global [%0], [%1], 16, %2;\n"
                         :: "r"(dst), "l"(gp), "r"(zf));
        }
    };

    float c[4][4][4];
#pragma unroll
    for (int i = 0; i < 4; i++)
#pragma unroll
        for (int j = 0; j < 4; j++)
#pragma unroll
            for (int l = 0; l < 4; l++) c[i][j][l] = 0.f;

    const int nk = K / 16;
#pragma unroll 1
    for (int s = 0; s < 3; s++) {
        issue(s);
        asm volatile("cp.async.commit_group;\n");
    }

#pragma unroll 1
    for (int kt = 0; kt < nk; kt++) {
        asm volatile("cp.async.wait_group 2;\n");
        __syncthreads();
        if (kt + 3 < nk) issue(kt + 3);
        asm volatile("cp.async.commit_group;\n");

        const float* Ab = Abase + (kt & 3) * AST;
        const float* Bb = Bbase + (kt & 3) * BST;
#pragma unroll
        for (int ks = 0; ks < 2; ks++) {
            const int k8 = ks * 8;
            unsigned af[4][4], bf[4][2];
#pragma unroll
            for (int mt = 0; mt < 4; mt++) {
                const float* p = Ab + (wm + mt * 16 + row) * 20 + k8 + col;
                af[mt][0] = __float_as_uint(p[0]);
                af[mt][1] = __float_as_uint(p[8 * 20]);
                af[mt][2] = __float_as_uint(p[4]);
                af[mt][3] = __float_as_uint(p[8 * 20 + 4]);
            }
#pragma unroll
            for (int nt = 0; nt < 4; nt++) {
                const float* p = Bb + (wn + nt * 8 + row) * 20 + k8 + col;
                bf[nt][0] = __float_as_uint(p[0]);
                bf[nt][1] = __float_as_uint(p[4]);
            }
#pragma unroll
            for (int mt = 0; mt < 4; mt++)
#pragma unroll
                for (int nt = 0; nt < 4; nt++)
                    mma_tf32(c[mt][nt], af[mt], bf[nt]);
        }
    }

#pragma unroll
    for (int mt = 0; mt < 4; mt++) {
#pragma unroll
        for (int nt = 0; nt < 4; nt++) {
            int gm = bm + wm + mt * 16 + row;
            int gn = bn + wn + nt * 8 + col * 2;
            if (gn < N) {
                if (gm < M)
                    *(float2*)(C + (long long)gm * N + gn) = make_float2(c[mt][nt][0], c[mt][nt][1]);
                if (gm + 8 < M)
                    *(float2*)(C + (long long)(gm + 8) * N + gn) = make_float2(c[mt][nt][2], c[mt][nt][3]);
            }
        }
    }
}

// ---------------- weight tf32 pre-round ----------------
__global__ void round4(const float4* __restrict__ s, float4* __restrict__ d, int n4)
{
    int i = blockIdx.x * 256 + threadIdx.x;
    if (i >= n4) return;
    float4 v = s[i];
    v.x = tf32r(v.x); v.y = tf32r(v.y); v.z = tf32r(v.z); v.w = tf32r(v.w);
    d[i] = v;
}

#define NW 13
struct RoundDesc {
    const float4* src[NW];
    long long dofs[NW];
    int blkStart[NW + 1];
};

__global__ void round_many(RoundDesc d, float* __restrict__ wbuf)
{
    int b = blockIdx.x;
    int w = 0;
#pragma unroll
    for (int i = 0; i < NW; i++) if (b >= d.blkStart[i + 1]) w = i + 1;
    int lb = b - d.blkStart[w];
    const float4* s = d.src[w] + (long long)lb * 1024;
    float4* o = (float4*)(wbuf + d.dofs[w]) + (long long)lb * 1024;
    int t = threadIdx.x;
    float4 v[4];
#pragma unroll
    for (int i = 0; i < 4; i++) v[i] = s[t + i * 256];
#pragma unroll
    for (int i = 0; i < 4; i++) {
        v[i].x = tf32r(v[i].x); v[i].y = tf32r(v[i].y);
        v[i].z = tf32r(v[i].z); v[i].w = tf32r(v[i].w);
    }
#pragma unroll
    for (int i = 0; i < 4; i++) o[t + i * 256] = v[i];
}

// ---------------- row kernels ----------------
__device__ __forceinline__ float blockReduceSum(float v) {
    __shared__ float red[256];
    int t = threadIdx.x;
    red[t] = v; __syncthreads();
    for (int s = 128; s > 0; s >>= 1) {
        if (t < s) red[t] += red[t + s];
        __syncthreads();
    }
    float r = red[0];
    __syncthreads();
    return r;
}

__global__ void rms_scale(const float* __restrict__ x, const float* __restrict__ w,
                          float* __restrict__ out, int W)
{
    long long base = (long long)blockIdx.x * W;
    float ss = 0.f;
    for (int c = threadIdx.x; c < W; c += 256) { float t = x[base + c]; ss += t * t; }
    float tot = blockReduceSum(ss);
    float inv = rsqrtf(tot / (float)W + EPS_);
    for (int c = threadIdx.x; c < W; c += 256)
        out[base + c] = tf32r(x[base + c] * inv * (1.f + w[c]));
}

__global__ void rms_mod(const float* __restrict__ x, const float* __restrict__ mod,
                        float* __restrict__ out, int W, int rowsPerB)
{
    long long base = (long long)blockIdx.x * W;
    int b = blockIdx.x / rowsPerB;
    const float* m = mod + (long long)b * 3 * W;
    float ss = 0.f;
    for (int c = threadIdx.x; c < W; c += 256) { float t = x[base + c]; ss += t * t; }
    float tot = blockReduceSum(ss);
    float inv = rsqrtf(tot / (float)W + EPS_);
    for (int c = threadIdx.x; c < W; c += 256)
        out[base + c] = tf32r(x[base + c] * inv * (1.f + m[c]) + m[W + c]);
}

__global__ void modmm2(const float* __restrict__ cond, const float* __restrict__ W,
                       const float* __restrict__ bias, float* __restrict__ out)
{
    const int NT = 3 * W_E_;
    __shared__ float cs[W_E_];
    __shared__ float part[4][64];
    int bb = blockIdx.y;
    int tid = threadIdx.x;
    for (int i = tid; i < W_E_; i += 256) cs[i] = cond[bb * W_E_ + i];
    __syncthreads();
    int tx = tid & 63, ty = tid >> 6;
    int c = blockIdx.x * 64 + tx;
    const float* Wp = W + (long long)(ty * 256) * NT + c;
    const float* cp = cs + ty * 256;
    float s = 0.f;
#pragma unroll 4
    for (int k = 0; k < 256; k++) s += cp[k] * Wp[(long long)k * NT];
    part[ty][tx] = s;
    __syncthreads();
    if (ty == 0)
        out[(long long)bb * NT + c] = part[0][tx] + part[1][tx] + part[2][tx] + part[3][tx] + bias[c];
}

__global__ void rope4(float* __restrict__ x, const int* __restrict__ pos, int nh)
{
    int idx = blockIdx.x * blockDim.x + threadIdx.x;
    int total = B_ * S_ * nh * 32;
    if (idx >= total) return;
    int d4 = (idx & 31) << 2;
    int h = (idx >> 5) % nh;
    int s = (idx / (32 * nh)) % S_;
    int b = idx / (32 * nh * S_);
    float p = (float)pos[b * S_ + s];
    float* base = x + (((long long)(b * S_ + s) * nh + h) << 8);
    float4 x1 = *(float4*)(base + d4);
    float4 x2 = *(float4*)(base + d4 + 128);
    float r1[4] = {x1.x, x1.y, x1.z, x1.w};
    float r2[4] = {x2.x, x2.y, x2.z, x2.w};
#pragma unroll
    for (int j = 0; j < 4; j++) {
        float ang = p * powf(10000.f, -(float)(2 * (d4 + j)) / 256.f);
        float sn, cs2; sincosf(ang, &sn, &cs2);
        float a = r1[j], bb = r2[j];
        r1[j] = tf32r(a * cs2 - bb * sn);
        r2[j] = tf32r(bb * cs2 + a * sn);
    }
    *(float4*)(base + d4)       = make_float4(r1[0], r1[1], r1[2], r1[3]);
    *(float4*)(base + d4 + 128) = make_float4(r2[0], r2[1], r2[2], r2[3]);
}

__global__ void q_to_bhsd4(const float4* __restrict__ q, float4* __restrict__ qt)
{
    int idx = blockIdx.x * blockDim.x + threadIdx.x;
    int total = B_ * H_ * S_ * 64;
    if (idx >= total) return;
    int d = (idx & 63) << 2;
    int s = (idx >> 6) % S_;
    int h = (idx / (64 * S_)) % H_;
    int b = idx / (64 * S_ * H_);
    qt[idx] = q[((((long long)(b * S_ + s) * H_ + h) << 8) + d) >> 2];
}

__global__ void bhsd_to_bshd4(const float4* __restrict__ a, float4* __restrict__ o)
{
    int idx = blockIdx.x * blockDim.x + threadIdx.x;
    int total = B_ * S_ * H_ * 64;
    if (idx >= total) return;
    int d = (idx & 63) << 2;
    int h = (idx >> 6) % H_;
    int s = (idx / (64 * H_)) % S_;
    int b = idx / (64 * H_ * S_);
    float4 v = a[((((long long)(b * H_ + h) * S_ + s) << 8) + d) >> 2];
    v.x = tf32r(v.x); v.y = tf32r(v.y); v.z = tf32r(v.z); v.w = tf32r(v.w);
    o[idx] = v;
}

__global__ void softmax4(float* __restrict__ logits, const float* __restrict__ mask)
{
    int rowid = blockIdx.x;
    int b = rowid / (H_ * S_);
    int q = rowid % S_;
    float4* row = (float4*)(logits + (long long)rowid * S_);
    const float4* m = (const float4*)(mask + ((long long)b * S_ + q) * S_);
    int t = threadIdx.x;
    const bool act = t < 208;
    float4 v = make_float4(-1e30f, -1e30f, -1e30f, -1e30f);
    if (act) {
        float4 lv = row[t], mv = m[t];
        v.x = lv.x * SCALE_ + mv.x; v.y = lv.y * SCALE_ + mv.y;
        v.z = lv.z * SCALE_ + mv.z; v.w = lv.w * SCALE_ + mv.w;
    }
    float mx = fmaxf(fmaxf(v.x, v.y), fmaxf(v.z, v.w));
    __shared__ float red[256];
    red[t] = mx; __syncthreads();
    for (int s = 128; s > 0; s >>= 1) { if (t < s) red[t] = fmaxf(red[t], red[t + s]); __syncthreads(); }
    mx = red[0]; __syncthreads();
    float sum = 0.f;
    if (act) {
        v.x = __expf(v.x - mx); v.y = __expf(v.y - mx);
        v.z = __expf(v.z - mx); v.w = __expf(v.w - mx);
        sum = v.x + v.y + v.z + v.w;
    }
    red[t] = sum; __syncthreads();
    for (int s = 128; s > 0; s >>= 1) { if (t < s) red[t] += red[t + s]; __syncthreads(); }
    float inv = 1.f / red[0];
    if (act)
        row[t] = make_float4(tf32r(v.x * inv), tf32r(v.y * inv), tf32r(v.z * inv), tf32r(v.w * inv));
}

// ---------------- host launch ----------------
#define GETSYM(var, sym) do { void* p__; cudaGetSymbolAddress(&p__, sym); var = (float*)p__; } while (0)

extern "C" void kernel_launch(void* const* d_in, const int* in_sizes, int n_in,
                              void* d_out, int out_size)
{
    const float *embeds_vlm, *embeds_exp, *cond, *attn_mask;
    const int* pos;
    const float *vlm_ln1_w, *vlm_ln2_w, *vlm_q_w, *vlm_k_w, *vlm_v_w, *vlm_o_w;
    const float *vlm_gate_w, *vlm_up_w, *vlm_down_w;
    const float *exp_ln1_dw, *exp_ln1_db, *exp_ln2_dw, *exp_ln2_db;
    const float *exp_q_w, *exp_k_w, *exp_v_w, *exp_o_w, *exp_gate_w, *exp_up_w, *exp_down_w;

    if (in_sizes[3] == B_ * S_) {
        embeds_vlm = (const float*)d_in[0];  embeds_exp = (const float*)d_in[1];
        cond       = (const float*)d_in[2];  pos        = (const int*)  d_in[3];
        attn_mask  = (const float*)d_in[4];
        vlm_ln1_w  = (const float*)d_in[5];  vlm_ln2_w  = (const float*)d_in[6];
        vlm_q_w    = (const float*)d_in[7];  vlm_k_w    = (const float*)d_in[8];
        vlm_v_w    = (const float*)d_in[9];  vlm_o_w    = (const float*)d_in[10];
        vlm_gate_w = (const float*)d_in[11]; vlm_up_w   = (const float*)d_in[12];
        vlm_down_w = (const float*)d_in[13];
        exp_ln1_dw = (const float*)d_in[14]; exp_ln1_db = (const float*)d_in[15];
        exp_ln2_dw = (const float*)d_in[16]; exp_ln2_db = (const float*)d_in[17];
        exp_q_w    = (const float*)d_in[18]; exp_k_w    = (const float*)d_in[19];
        exp_v_w    = (const float*)d_in[20]; exp_o_w    = (const float*)d_in[21];
        exp_gate_w = (const float*)d_in[22]; exp_up_w   = (const float*)d_in[23];
        exp_down_w = (const float*)d_in[24];
    } else {
        embeds_vlm = (const float*)d_in[0];  embeds_exp = (const float*)d_in[1];
        cond       = (const float*)d_in[2];
        vlm_ln1_w  = (const float*)d_in[3];  vlm_ln2_w  = (const float*)d_in[4];
        vlm_q_w    = (const float*)d_in[5];  vlm_k_w    = (const float*)d_in[6];
        vlm_v_w    = (const float*)d_in[7];  vlm_o_w    = (const float*)d_in[8];
        vlm_gate_w = (const float*)d_in[9];  vlm_up_w   = (const float*)d_in[10];
        vlm_down_w = (const float*)d_in[11];
        exp_ln1_dw = (const float*)d_in[12]; exp_ln1_db = (const float*)d_in[13];
        exp_ln2_dw = (const float*)d_in[14]; exp_ln2_db = (const float*)d_in[15];
        exp_q_w    = (const float*)d_in[16]; exp_k_w    = (const float*)d_in[17];
        exp_v_w    = (const float*)d_in[18]; exp_o_w    = (const float*)d_in[19];
        exp_gate_w = (const float*)d_in[20]; exp_up_w   = (const float*)d_in[21];
        exp_down_w = (const float*)d_in[22];
        pos        = (const int*)  d_in[23];
        attn_mask  = (const float*)d_in[24];
    }

    float *hv, *he, *mod1, *mod2, *q, *qt, *k, *v, *logits, *attnt, *attn;
    float *hv1, *he1, *mg, *mu, *eg, *eu, *wb;
    GETSYM(hv, g_hv);   GETSYM(he, g_he);   GETSYM(mod1, g_mod1); GETSYM(mod2, g_mod2);
    GETSYM(q, g_q);     GETSYM(qt, g_qt);   GETSYM(k, g_k);       GETSYM(v, g_v);
    GETSYM(logits, g_logits); GETSYM(attnt, g_attnt); GETSYM(attn, g_attn);
    GETSYM(hv1, g_hv1); GETSYM(he1, g_he1); GETSYM(mg, g_mg);     GETSYM(mu, g_mu);
    GETSYM(eg, g_eg);   GETSYM(eu, g_eu);   GETSYM(wb, g_wbuf);

    const long long n_vq = (long long)W_V_ * H_ * DH_;
    const float* srcs[NW] = {vlm_k_w, vlm_v_w, vlm_o_w, vlm_gate_w, vlm_up_w, vlm_down_w,
                             exp_q_w, exp_k_w, exp_v_w, exp_o_w, exp_gate_w, exp_up_w, exp_down_w};
    long long cnts[NW] = {
        (long long)W_V_*DH_, (long long)W_V_*DH_, (long long)H_*DH_*W_V_,
        (long long)W_V_*MLPV_, (long long)W_V_*MLPV_, (long long)MLPV_*W_V_,
        (long long)W_E_*H_*DH_, (long long)W_E_*DH_, (long long)W_E_*DH_, (long long)H_*DH_*W_E_,
        (long long)W_E_*MLPE_, (long long)W_E_*MLPE_, (long long)MLPE_*W_E_};
    RoundDesc rd;
    long long ofs = n_vq; int blk = 0;
    const float* wptr[NW];
    for (int i = 0; i < NW; i++) {
        rd.src[i] = (const float4*)srcs[i];
        rd.dofs[i] = ofs;
        rd.blkStart[i] = blk;
        wptr[i] = wb + ofs;
        ofs += cnts[i];
        blk += (int)(cnts[i] / 4096);
    }
    rd.blkStart[NW] = blk;
    const float* w_vq = wb;
    const float *w_vk = wptr[0], *w_vv = wptr[1], *w_vo = wptr[2];
    const float *w_vg = wptr[3], *w_vu = wptr[4], *w_vd = wptr[5];
    const float *w_eq = wptr[6], *w_ek = wptr[7], *w_ev = wptr[8], *w_eo = wptr[9];
    const float *w_egw = wptr[10], *w_euw = wptr[11], *w_ed = wptr[12];

    const int SM32 = 3 * STG32 * 4;              // gemm32 smem bytes (111KB)
    const int SM1  = 4 * (AST + 128 * 20) * 4;   // gemm_tb1 smem bytes
    cudaFuncSetAttribute(gemm32<0>, cudaFuncAttributeMaxDynamicSharedMemorySize, SM32);
    cudaFuncSetAttribute(gemm32<1>, cudaFuncAttributeMaxDynamicSharedMemorySize, SM32);
    cudaFuncSetAttribute(gemm32<2>, cudaFuncAttributeMaxDynamicSharedMemorySize, SM32);
    cudaFuncSetAttribute(gemm32<3>, cudaFuncAttributeMaxDynamicSharedMemorySize, SM32);
    cudaFuncSetAttribute(gemm32<4>, cudaFuncAttributeMaxDynamicSharedMemorySize, SM32);
    cudaFuncSetAttribute(gemm_tb1,  cudaFuncAttributeMaxDynamicSharedMemorySize, SM1);

    float* out_v = (float*)d_out;
    float* out_e = (float*)d_out + (long long)B_ * S_V_ * W_V_;

    long long sHv = (long long)S_V_ * W_V_, sHe = (long long)S_E_ * W_E_;
    long long sQ = (long long)S_ * H_ * DH_, sK = (long long)S_ * DH_;
    long long sL = (long long)S_ * S_;

    // L0..L2
    round4<<<(int)((n_vq / 4 + 255) / 256), 256>>>((const float4*)vlm_q_w, (float4*)wb, (int)(n_vq / 4));
    rms_scale<<<B_ * S_V_, 256>>>(embeds_vlm, vlm_ln1_w, hv, W_V_);
    modmm2<<<dim3(48, B_), 256>>>(cond, exp_ln1_dw, exp_ln1_db, mod1);
    // L3: VLM Q projection (ncu capture target)
    gemm32<0><<<dim3(16, 6, B_), 256, SM32>>>(hv, w_vq, q, nullptr, nullptr, S_V_, H_ * DH_, W_V_, sHv, 0, sQ, 1);
    // L4..L6
    round_many<<<blk, 256>>>(rd, wb);
    rms_mod<<<B_ * S_E_, 256>>>(embeds_exp, mod1, he, W_E_, S_E_);
    modmm2<<<dim3(48, B_), 256>>>(cond, exp_ln2_dw, exp_ln2_db, mod2);

    // QKV remainder
    gemm32<0><<<dim3(16, 1, B_), 256, SM32>>>(he, w_eq, q + (long long)S_V_ * H_ * DH_, nullptr, nullptr, S_E_, H_ * DH_, W_E_, sHe, 0, sQ, 1);
    gemm32<0><<<dim3(2, 6, B_), 256, SM32>>>(hv, w_vk, k, nullptr, nullptr, S_V_, DH_, W_V_, sHv, 0, sK, 1);
    gemm32<0><<<dim3(2, 1, B_), 256, SM32>>>(he, w_ek, k + S_V_ * DH_, nullptr, nullptr, S_E_, DH_, W_E_, sHe, 0, sK, 1);
    gemm32<1><<<dim3(2, 6, B_), 256, SM32>>>(hv, w_vv, v, nullptr, nullptr, S_V_, DH_, W_V_, sHv, 0, sK, 1);
    gemm32<1><<<dim3(2, 1, B_), 256, SM32>>>(he, w_ev, v + S_V_ * DH_, nullptr, nullptr, S_E_, DH_, W_E_, sHe, 0, sK, 1);

    // RoPE
    rope4<<<(B_ * S_ * H_ * 32 + 255) / 256, 256>>>(q, pos, H_);
    rope4<<<(B_ * S_ * 1 * 32 + 255) / 256, 256>>>(k, pos, 1);

    // attention
    {
        int nq4 = B_ * H_ * S_ * 64;
        q_to_bhsd4<<<(nq4 + 255) / 256, 256>>>((const float4*)q, (float4*)qt);
        gemm_tb1<<<dim3(7, 7, B_ * H_), 256, SM1>>>(qt, k, logits, S_, S_, DH_, sK, sK, sL, H_);
        softmax4<<<B_ * H_ * S_, 256>>>(logits, attn_mask);
        gemm32<0><<<dim3(2, 7, B_ * H_), 256, SM32>>>(logits, v, attnt, nullptr, nullptr, S_, DH_, S_, sL, sK, sK, H_);
        bhsd_to_bshd4<<<(nq4 + 255) / 256, 256>>>((const float4*)attnt, (float4*)attn);
    }

    // output projections + residuals (fused epilogues)
    {
        long long sA = (long long)S_ * H_ * DH_;
        gemm32<3><<<dim3(16, 6, B_), 256, SM32>>>(attn, w_vo, hv1, embeds_vlm, nullptr, S_V_, W_V_, H_ * DH_, sA, 0, sHv, 1);
        gemm32<4><<<dim3(8, 1, B_), 256, SM32>>>(attn + (long long)S_V_ * H_ * DH_, w_eo, he1, embeds_exp, mod1, S_E_, W_E_, H_ * DH_, sA, 0, sHe, 1);
    }

    // pre-MLP norms
    rms_scale<<<B_ * S_V_, 256>>>(hv1, vlm_ln2_w, hv, W_V_);
    rms_mod<<<B_ * S_E_, 256>>>(he1, mod2, he, W_E_, S_E_);

    // VLM MLP
    {
        int M = B_ * S_V_;
        gemm32<0><<<dim3(128, 24, 1), 256, SM32>>>(hv, w_vu, mu, nullptr, nullptr, M, MLPV_, W_V_, 0, 0, 0, 1);
        gemm32<2><<<dim3(128, 24, 1), 256, SM32>>>(hv, w_vg, mg, mu, nullptr, M, MLPV_, W_V_, 0, 0, 0, 1);
        gemm32<3><<<dim3(16, 24, 1), 256, SM32>>>(mg, w_vd, out_v, hv1, nullptr, M, W_V_, MLPV_, 0, 0, 0, 1);
    }

    // expert MLP
    {
        int M = B_ * S_E_;
        gemm32<0><<<dim3(32, 2, 1), 256, SM32>>>(he, w_euw, eu, nullptr, nullptr, M, MLPE_, W_E_, 0, 0, 0, 1);
        gemm32<2><<<dim3(32, 2, 1), 256, SM32>>>(he, w_egw, eg, eu, nullptr, M, MLPE_, W_E_, 0, 0, 0, 1);
        gemm32<4><<<dim3(8, 2, 1), 256, SM32>>>(eg, w_ed, out_e, he1, mod2, M, W_E_, MLPE_, 0, 0, 0, 1);
    }
}

// round 7
// speedup vs baseline: 8.1414x; 1.8932x over previous
#include <cuda_runtime.h>
#include <cuda_fp16.h>
#include <cuda_bf16.h>
#include <math.h>

#define B_    4
#define S_V_  768
#define S_E_  64
#define S_    832
#define W_V_  2048
#define W_E_  1024
#define H_    8
#define DH_   256
#define MLPV_ 16384
#define MLPE_ 4096
#define EPS_  1e-6f
#define SCALE_ 0.0625f

// ---------------- scratch ----------------
__device__ __half g_hv   [B_*S_V_*W_V_];
__device__ __half g_he   [B_*S_E_*W_E_];
__device__ float  g_mod1 [B_*3*W_E_];
__device__ float  g_mod2 [B_*3*W_E_];
__device__ __half g_q    [(long long)B_*S_*H_*DH_];
__device__ __half g_qt   [(long long)B_*H_*S_*DH_];
__device__ __half g_k    [B_*S_*DH_];
__device__ __half g_v    [B_*S_*DH_];
__device__ float  g_logits[(long long)B_*H_*S_*S_];
__device__ __half g_probs[(long long)B_*H_*S_*S_];
__device__ __half g_attnt[(long long)B_*H_*S_*DH_];
__device__ __half g_attn [(long long)B_*S_*H_*DH_];
__device__ float  g_hv1  [B_*S_V_*W_V_];
__device__ float  g_he1  [B_*S_E_*W_E_];
__device__ __half g_mg   [(long long)B_*S_V_*MLPV_];
__device__ float  g_mu   [(long long)B_*S_V_*MLPV_];
__device__ __half g_eg   [B_*S_E_*MLPE_];
__device__ float  g_eu   [B_*S_E_*MLPE_];
__device__ __half g_wbuf [127401984];

__device__ __forceinline__ float gelu_t(float x) {
    return 0.5f * x * (1.f + tanhf(0.7978845608028654f * (x + 0.044715f * x * x * x)));
}

__device__ __forceinline__ void mma_f16(float* c, const unsigned* a, const unsigned* b) {
    asm volatile(
        "mma.sync.aligned.m16n8k16.row.col.f32.f16.f16.f32 "
        "{%0,%1,%2,%3}, {%4,%5,%6,%7}, {%8,%9}, {%0,%1,%2,%3};\n"
        : "+f"(c[0]), "+f"(c[1]), "+f"(c[2]), "+f"(c[3])
        : "r"(a[0]), "r"(a[1]), "r"(a[2]), "r"(a[3]), "r"(b[0]), "r"(b[1]));
}

// ============ gemm16: fp16 operands, fp32 accum, TB=0 ============
// A (M,K) halfs row-major; B (K,N) halfs row-major. K%32==0, N%8==0.
// Block 128x128, 8 warps (2m x 4n) of 64x32, K-tile 32, 4 cp.async stages.
// smem per stage: A [128][40]h (10240B) + B [32][136]h (8704B) = 18944B
// EPI: 0 plain->fp16, 1 plain->fp32, 2 fp16(gelu(c)*aux), 3 fp32(c+aux),
//      4 fp32(aux + c*mod[(z+gm/S_E)*3W_E+2W_E+gn])
#define ASTB 10240
#define STGB 18944
template<int EPI>
__global__ __launch_bounds__(256, 2)
void gemm16(const __half* __restrict__ A, const __half* __restrict__ Bm,
            void* __restrict__ Cv, const float* __restrict__ aux,
            const float* __restrict__ modv,
            int M, int N, int K,
            long long sA, long long sB, long long sC, int bInner)
{
    extern __shared__ __align__(16) char sm[];

    const int z = blockIdx.z;
    A  += (long long)z * sA;
    Bm += (long long)(z / bInner) * sB;

    const int tid  = threadIdx.x;
    const int lane = tid & 31;
    const int wid  = tid >> 5;
    const int wm   = (wid & 1) * 64;
    const int wn   = (wid >> 1) * 32;
    const int bm   = blockIdx.y * 128;
    const int bn   = blockIdx.x * 128;
    const int row  = lane >> 2, col = lane & 3;

    unsigned sbase = (unsigned)__cvta_generic_to_shared(sm);

    auto issue = [&](int st) {
        const int ktE = st * 32;
        const unsigned sb = sbase + (unsigned)((st & 3) * STGB);
#pragma unroll
        for (int j = 0; j < 2; j++) {            // A: 128 rows x 32 halfs
            int id = tid + j * 256;
            int r = id >> 2, c = id & 3;
            int gm = bm + r;
            const __half* gp = A + (long long)(gm < M ? gm : M - 1) * K + ktE + c * 8;
            unsigned dst = sb + (unsigned)(r * 80 + c * 16);
            int zf = (gm < M) ? 16 : 0;
            asm volatile("cp.async.cg.shared.global [%0], [%1], 16, %2;\n"
                         :: "r"(dst), "l"(gp), "r"(zf));
        }
#pragma unroll
        for (int j = 0; j < 2; j++) {            // B: 32 rows x 128 halfs
            int id = tid + j * 256;
            int kr = id >> 4, c = id & 15;
            int gn = bn + c * 8;
            const __half* gp = Bm + (long long)(ktE + kr) * N + (gn < N ? gn : N - 8);
            unsigned dst = sb + (unsigned)(ASTB + kr * 272 + c * 16);
            int zf = (gn < N) ? 16 : 0;
            asm volatile("cp.async.cg.shared.global [%0], [%1], 16, %2;\n"
                         :: "r"(dst), "l"(gp), "r"(zf));
        }
    };

    float c[4][4][4];
#pragma unroll
    for (int i = 0; i < 4; i++)
#pragma unroll
        for (int j = 0; j < 4; j++)
#pragma unroll
            for (int l = 0; l < 4; l++) c[i][j][l] = 0.f;

    // frag address precompute (within-stage offsets)
    const unsigned aoff = (unsigned)((((lane >> 3) & 1) * 8 + (lane & 7)) * 80 + (lane >> 4) * 16);
    const int l16 = lane & 15;
    const unsigned boff = (unsigned)(ASTB + ((l16 >> 3) * 8 + (l16 & 7)) * 272 + wn * 2);

    const int nk = K / 32;
#pragma unroll 1
    for (int s = 0; s < 3; s++) { issue(s); asm volatile("cp.async.commit_group;\n"); }

#pragma unroll 1
    for (int kt = 0; kt < nk; kt++) {
        asm volatile("cp.async.wait_group 2;\n");
        __syncthreads();
        if (kt + 3 < nk) issue(kt + 3);
        asm volatile("cp.async.commit_group;\n");

        const unsigned stg = sbase + (unsigned)((kt & 3) * STGB);
#pragma unroll
        for (int sub = 0; sub < 2; sub++) {
            unsigned af[4][4], bf[4][2];
#pragma unroll
            for (int mt = 0; mt < 4; mt++) {
                unsigned ad = stg + (unsigned)((wm + mt * 16) * 80 + sub * 32) + aoff;
                asm volatile("ldmatrix.sync.aligned.m8n8.x4.shared.b16 {%0,%1,%2,%3}, [%4];"
                             : "=r"(af[mt][0]), "=r"(af[mt][1]), "=r"(af[mt][2]), "=r"(af[mt][3])
                             : "r"(ad));
            }
#pragma unroll
            for (int nt = 0; nt < 4; nt++) {
                unsigned bd = stg + (unsigned)(sub * 16 * 272 + nt * 16) + boff;
                asm volatile("ldmatrix.sync.aligned.m8n8.x2.trans.shared.b16 {%0,%1}, [%2];"
                             : "=r"(bf[nt][0]), "=r"(bf[nt][1]) : "r"(bd));
            }
#pragma unroll
            for (int mt = 0; mt < 4; mt++)
#pragma unroll
                for (int nt = 0; nt < 4; nt++)
                    mma_f16(c[mt][nt], af[mt], bf[nt]);
        }
    }

    // epilogue
    if (EPI >= 2) aux += (long long)z * sC;
    __half* Ch = (__half*)Cv + (long long)z * sC;
    float*  Cf = (float*)Cv + (long long)z * sC;

    auto epi_store = [&](int gm, int gn, float x0, float x1) {
        long long o = (long long)gm * N + gn;
        if (EPI == 0) {
            *(__half2*)(Ch + o) = __halves2half2(__float2half_rn(x0), __float2half_rn(x1));
        } else if (EPI == 1) {
            *(float2*)(Cf + o) = make_float2(x0, x1);
        } else if (EPI == 2) {
            float2 u = *(const float2*)(aux + o);
            *(__half2*)(Ch + o) = __halves2half2(__float2half_rn(gelu_t(x0) * u.x),
                                                 __float2half_rn(gelu_t(x1) * u.y));
        } else if (EPI == 3) {
            float2 u = *(const float2*)(aux + o);
            *(float2*)(Cf + o) = make_float2(x0 + u.x, x1 + u.y);
        } else {
            int bb = z + gm / S_E_;
            float g0 = modv[(long long)bb * 3 * W_E_ + 2 * W_E_ + gn];
            float g1 = modv[(long long)bb * 3 * W_E_ + 2 * W_E_ + gn + 1];
            float2 u = *(const float2*)(aux + o);
            *(float2*)(Cf + o) = make_float2(u.x + x0 * g0, u.y + x1 * g1);
        }
    };

#pragma unroll
    for (int mt = 0; mt < 4; mt++) {
#pragma unroll
        for (int nt = 0; nt < 4; nt++) {
            int gm = bm + wm + mt * 16 + row;
            int gn = bn + wn + nt * 8 + col * 2;
            if (gn < N) {
                if (gm < M)     epi_store(gm,     gn, c[mt][nt][0], c[mt][nt][1]);
                if (gm + 8 < M) epi_store(gm + 8, gn, c[mt][nt][2], c[mt][nt][3]);
            }
        }
    }
}

// ============ gemm16_tb1: fp16, B (N,K) row-major, fp32 out ============
// smem per stage: A [128][40]h + B [128][40]h = 20480B, 4 stages
#define STG1 20480
__global__ __launch_bounds__(256, 2)
void gemm16_tb1(const __half* __restrict__ A, const __half* __restrict__ Bm,
                float* __restrict__ C, int M, int N, int K,
                long long sA, long long sB, long long sC, int bInner)
{
    extern __shared__ __align__(16) char sm[];

    const int z = blockIdx.z;
    A  += (long long)z * sA;
    Bm += (long long)(z / bInner) * sB;
    C  += (long long)z * sC;

    const int tid  = threadIdx.x;
    const int lane = tid & 31;
    const int wid  = tid >> 5;
    const int wm   = (wid & 1) * 64;
    const int wn   = (wid >> 1) * 32;
    const int bm   = blockIdx.y * 128;
    const int bn   = blockIdx.x * 128;
    const int row  = lane >> 2, col = lane & 3;

    unsigned sbase = (unsigned)__cvta_generic_to_shared(sm);

    auto issue = [&](int st) {
        const int ktE = st * 32;
        const unsigned sb = sbase + (unsigned)((st & 3) * STG1);
#pragma unroll
        for (int j = 0; j < 2; j++) {            // A
            int id = tid + j * 256;
            int r = id >> 2, c = id & 3;
            int gm = bm + r;
            const __half* gp = A + (long long)(gm < M ? gm : M - 1) * K + ktE + c * 8;
            unsigned dst = sb + (unsigned)(r * 80 + c * 16);
            int zf = (gm < M) ? 16 : 0;
            asm volatile("cp.async.cg.shared.global [%0], [%1], 16, %2;\n"
                         :: "r"(dst), "l"(gp), "r"(zf));
        }
#pragma unroll
        for (int j = 0; j < 2; j++) {            // B rows = n
            int id = tid + j * 256;
            int r = id >> 2, c = id & 3;
            int gn = bn + r;
            const __half* gp = Bm + (long long)(gn < N ? gn : N - 1) * K + ktE + c * 8;
            unsigned dst = sb + (unsigned)(ASTB + r * 80 + c * 16);
            int zf = (gn < N) ? 16 : 0;
            asm volatile("cp.async.cg.shared.global [%0], [%1], 16, %2;\n"
                         :: "r"(dst), "l"(gp), "r"(zf));
        }
    };

    float c[4][4][4];
#pragma unroll
    for (int i = 0; i < 4; i++)
#pragma unroll
        for (int j = 0; j < 4; j++)
#pragma unroll
            for (int l = 0; l < 4; l++) c[i][j][l] = 0.f;

    const unsigned aoff = (unsigned)((((lane >> 3) & 1) * 8 + (lane & 7)) * 80 + (lane >> 4) * 16);
    const int l16 = lane & 15;
    const unsigned boff = (unsigned)(ASTB + ((l16 & 7) + wn) * 80 + (l16 >> 3) * 16);

    const int nk = K / 32;
#pragma unroll 1
    for (int s = 0; s < 3; s++) { issue(s); asm volatile("cp.async.commit_group;\n"); }

#pragma unroll 1
    for (int kt = 0; kt < nk; kt++) {
        asm volatile("cp.async.wait_group 2;\n");
        __syncthreads();
        if (kt + 3 < nk) issue(kt + 3);
        asm volatile("cp.async.commit_group;\n");

        const unsigned stg = sbase + (unsigned)((kt & 3) * STG1);
#pragma unroll
        for (int sub = 0; sub < 2; sub++) {
            unsigned af[4][4], bf[4][2];
#pragma unroll
            for (int mt = 0; mt < 4; mt++) {
                unsigned ad = stg + (unsigned)((wm + mt * 16) * 80 + sub * 32) + aoff;
                asm volatile("ldmatrix.sync.aligned.m8n8.x4.shared.b16 {%0,%1,%2,%3}, [%4];"
                             : "=r"(af[mt][0]), "=r"(af[mt][1]), "=r"(af[mt][2]), "=r"(af[mt][3])
                             : "r"(ad));
            }
#pragma unroll
            for (int nt = 0; nt < 4; nt++) {
                unsigned bd = stg + (unsigned)(nt * 8 * 80 + sub * 32) + boff;
                asm volatile("ldmatrix.sync.aligned.m8n8.x2.shared.b16 {%0,%1}, [%2];"
                             : "=r"(bf[nt][0]), "=r"(bf[nt][1]) : "r"(bd));
            }
#pragma unroll
            for (int mt = 0; mt < 4; mt++)
#pragma unroll
                for (int nt = 0; nt < 4; nt++)
                    mma_f16(c[mt][nt], af[mt], bf[nt]);
        }
    }

#pragma unroll
    for (int mt = 0; mt < 4; mt++) {
#pragma unroll
        for (int nt = 0; nt < 4; nt++) {
            int gm = bm + wm + mt * 16 + row;
            int gn = bn + wn + nt * 8 + col * 2;
            if (gn < N) {
                if (gm < M)
                    *(float2*)(C + (long long)gm * N + gn) = make_float2(c[mt][nt][0], c[mt][nt][1]);
                if (gm + 8 < M)
                    *(float2*)(C + (long long)(gm + 8) * N + gn) = make_float2(c[mt][nt][2], c[mt][nt][3]);
            }
        }
    }
}

// ---------------- weight fp16 pre-convert ----------------
__global__ void round4(const float4* __restrict__ s, __half2* __restrict__ d, int n4)
{
    int i = blockIdx.x * 256 + threadIdx.x;
    if (i >= n4) return;
    float4 v = s[i];
    d[i * 2]     = __floats2half2_rn(v.x, v.y);
    d[i * 2 + 1] = __floats2half2_rn(v.z, v.w);
}

#define NW 13
struct RoundDesc {
    const float4* src[NW];
    long long dofs[NW];
    int blkStart[NW + 1];   // each block = 4096 floats
};

__global__ void round_many(RoundDesc d, __half* __restrict__ wbuf)
{
    int b = blockIdx.x;
    int w = 0;
#pragma unroll
    for (int i = 0; i < NW; i++) if (b >= d.blkStart[i + 1]) w = i + 1;
    int lb = b - d.blkStart[w];
    const float4* s = d.src[w] + (long long)lb * 1024;
    __half2* o = (__half2*)(wbuf + d.dofs[w]) + (long long)lb * 2048;
    int t = threadIdx.x;
#pragma unroll
    for (int i = 0; i < 4; i++) {
        float4 v = s[t + i * 256];
        o[(t + i * 256) * 2]     = __floats2half2_rn(v.x, v.y);
        o[(t + i * 256) * 2 + 1] = __floats2half2_rn(v.z, v.w);
    }
}

// ---------------- row kernels ----------------
__device__ __forceinline__ float blockReduceSum(float v) {
    __shared__ float red[256];
    int t = threadIdx.x;
    red[t] = v; __syncthreads();
    for (int s = 128; s > 0; s >>= 1) {
        if (t < s) red[t] += red[t + s];
        __syncthreads();
    }
    float r = red[0];
    __syncthreads();
    return r;
}

__global__ void rms_scale(const float* __restrict__ x, const float* __restrict__ w,
                          __half* __restrict__ out, int W)
{
    long long base = (long long)blockIdx.x * W;
    float ss = 0.f;
    for (int c = threadIdx.x; c < W; c += 256) { float t = x[base + c]; ss += t * t; }
    float tot = blockReduceSum(ss);
    float inv = rsqrtf(tot / (float)W + EPS_);
    for (int c = threadIdx.x; c < W; c += 256)
        out[base + c] = __float2half_rn(x[base + c] * inv * (1.f + w[c]));
}

__global__ void rms_mod(const float* __restrict__ x, const float* __restrict__ mod,
                        __half* __restrict__ out, int W, int rowsPerB)
{
    long long base = (long long)blockIdx.x * W;
    int b = blockIdx.x / rowsPerB;
    const float* m = mod + (long long)b * 3 * W;
    float ss = 0.f;
    for (int c = threadIdx.x; c < W; c += 256) { float t = x[base + c]; ss += t * t; }
    float tot = blockReduceSum(ss);
    float inv = rsqrtf(tot / (float)W + EPS_);
    for (int c = threadIdx.x; c < W; c += 256)
        out[base + c] = __float2half_rn(x[base + c] * inv * (1.f + m[c]) + m[W + c]);
}

__global__ void modmm2(const float* __restrict__ cond, const float* __restrict__ W,
                       const float* __restrict__ bias, float* __restrict__ out)
{
    const int NT = 3 * W_E_;
    __shared__ float cs[W_E_];
    __shared__ float part[4][64];
    int bb = blockIdx.y;
    int tid = threadIdx.x;
    for (int i = tid; i < W_E_; i += 256) cs[i] = cond[bb * W_E_ + i];
    __syncthreads();
    int tx = tid & 63, ty = tid >> 6;
    int c = blockIdx.x * 64 + tx;
    const float* Wp = W + (long long)(ty * 256) * NT + c;
    const float* cp = cs + ty * 256;
    float s = 0.f;
#pragma unroll 4
    for (int k = 0; k < 256; k++) s += cp[k] * Wp[(long long)k * NT];
    part[ty][tx] = s;
    __syncthreads();
    if (ty == 0)
        out[(long long)bb * NT + c] = part[0][tx] + part[1][tx] + part[2][tx] + part[3][tx] + bias[c];
}

// RoPE on fp16 x (B,S,nh,256), 4 halves per thread per half-dim
__global__ void rope4h(__half* __restrict__ x, const int* __restrict__ pos, int nh)
{
    int idx = blockIdx.x * blockDim.x + threadIdx.x;
    int total = B_ * S_ * nh * 32;
    if (idx >= total) return;
    int d4 = (idx & 31) << 2;
    int h = (idx >> 5) % nh;
    int s = (idx / (32 * nh)) % S_;
    int b = idx / (32 * nh * S_);
    float p = (float)pos[b * S_ + s];
    __half* base = x + (((long long)(b * S_ + s) * nh + h) << 8);
    __half2 x1a = *(__half2*)(base + d4),       x1b = *(__half2*)(base + d4 + 2);
    __half2 x2a = *(__half2*)(base + d4 + 128), x2b = *(__half2*)(base + d4 + 130);
    float r1[4] = {__low2float(x1a), __high2float(x1a), __low2float(x1b), __high2float(x1b)};
    float r2[4] = {__low2float(x2a), __high2float(x2a), __low2float(x2b), __high2float(x2b)};
#pragma unroll
    for (int j = 0; j < 4; j++) {
        float ang = p * powf(10000.f, -(float)(2 * (d4 + j)) / 256.f);
        float sn, cs2; sincosf(ang, &sn, &cs2);
        float a = r1[j], bb = r2[j];
        r1[j] = a * cs2 - bb * sn;
        r2[j] = bb * cs2 + a * sn;
    }
    *(__half2*)(base + d4)       = __floats2half2_rn(r1[0], r1[1]);
    *(__half2*)(base + d4 + 2)   = __floats2half2_rn(r1[2], r1[3]);
    *(__half2*)(base + d4 + 128) = __floats2half2_rn(r2[0], r2[1]);
    *(__half2*)(base + d4 + 130) = __floats2half2_rn(r2[2], r2[3]);
}

// (B,S,H,256) -> (B,H,S,256), 8 halves/thread
__global__ void q_to_bhsd8h(const uint4* __restrict__ q, uint4* __restrict__ qt)
{
    int idx = blockIdx.x * blockDim.x + threadIdx.x;
    int total = B_ * H_ * S_ * 32;
    if (idx >= total) return;
    int d = idx & 31;
    int s = (idx >> 5) % S_;
    int h = (idx / (32 * S_)) % H_;
    int b = idx / (32 * S_ * H_);
    qt[idx] = q[(((b * S_ + s) * H_ + h) * 32) + d];
}

// (B,H,S,256) -> (B,S,H,256)
__global__ void bhsd_to_bshd8h(const uint4* __restrict__ a, uint4* __restrict__ o)
{
    int idx = blockIdx.x * blockDim.x + threadIdx.x;
    int total = B_ * S_ * H_ * 32;
    if (idx >= total) return;
    int d = idx & 31;
    int h = (idx >> 5) % H_;
    int s = (idx / (32 * H_)) % S_;
    int b = idx / (32 * H_ * S_);
    o[idx] = a[(((b * H_ + h) * S_ + s) * 32) + d];
}

// softmax: logits fp32 -> probs fp16
__global__ void softmax4h(const float* __restrict__ logits, const float* __restrict__ mask,
                          __half* __restrict__ probs)
{
    int rowid = blockIdx.x;
    int b = rowid / (H_ * S_);
    int q = rowid % S_;
    const float4* row = (const float4*)(logits + (long long)rowid * S_);
    const float4* m = (const float4*)(mask + ((long long)b * S_ + q) * S_);
    __half* prow = probs + (long long)rowid * S_;
    int t = threadIdx.x;
    const bool act = t < 208;
    float4 v = make_float4(-1e30f, -1e30f, -1e30f, -1e30f);
    if (act) {
        float4 lv = row[t], mv = m[t];
        v.x = lv.x * SCALE_ + mv.x; v.y = lv.y * SCALE_ + mv.y;
        v.z = lv.z * SCALE_ + mv.z; v.w = lv.w * SCALE_ + mv.w;
    }
    float mx = fmaxf(fmaxf(v.x, v.y), fmaxf(v.z, v.w));
    __shared__ float red[256];
    red[t] = mx; __syncthreads();
    for (int s = 128; s > 0; s >>= 1) { if (t < s) red[t] = fmaxf(red[t], red[t + s]); __syncthreads(); }
    mx = red[0]; __syncthreads();
    float sum = 0.f;
    if (act) {
        v.x = __expf(v.x - mx); v.y = __expf(v.y - mx);
        v.z = __expf(v.z - mx); v.w = __expf(v.w - mx);
        sum = v.x + v.y + v.z + v.w;
    }
    red[t] = sum; __syncthreads();
    for (int s = 128; s > 0; s >>= 1) { if (t < s) red[t] += red[t + s]; __syncthreads(); }
    float inv = 1.f / red[0];
    if (act) {
        *(__half2*)(prow + t * 4)     = __floats2half2_rn(v.x * inv, v.y * inv);
        *(__half2*)(prow + t * 4 + 2) = __floats2half2_rn(v.z * inv, v.w * inv);
    }
}

// ---------------- host launch ----------------
#define GETSYMF(var, sym) do { void* p__; cudaGetSymbolAddress(&p__, sym); var = (float*)p__; } while (0)
#define GETSYMH(var, sym) do { void* p__; cudaGetSymbolAddress(&p__, sym); var = (__half*)p__; } while (0)

extern "C" void kernel_launch(void* const* d_in, const int* in_sizes, int n_in,
                              void* d_out, int out_size)
{
    const float *embeds_vlm, *embeds_exp, *cond, *attn_mask;
    const int* pos;
    const float *vlm_ln1_w, *vlm_ln2_w, *vlm_q_w, *vlm_k_w, *vlm_v_w, *vlm_o_w;
    const float *vlm_gate_w, *vlm_up_w, *vlm_down_w;
    const float *exp_ln1_dw, *exp_ln1_db, *exp_ln2_dw, *exp_ln2_db;
    const float *exp_q_w, *exp_k_w, *exp_v_w, *exp_o_w, *exp_gate_w, *exp_up_w, *exp_down_w;

    if (in_sizes[3] == B_ * S_) {
        embeds_vlm = (const float*)d_in[0];  embeds_exp = (const float*)d_in[1];
        cond       = (const float*)d_in[2];  pos        = (const int*)  d_in[3];
        attn_mask  = (const float*)d_in[4];
        vlm_ln1_w  = (const float*)d_in[5];  vlm_ln2_w  = (const float*)d_in[6];
        vlm_q_w    = (const float*)d_in[7];  vlm_k_w    = (const float*)d_in[8];
        vlm_v_w    = (const float*)d_in[9];  vlm_o_w    = (const float*)d_in[10];
        vlm_gate_w = (const float*)d_in[11]; vlm_up_w   = (const float*)d_in[12];
        vlm_down_w = (const float*)d_in[13];
        exp_ln1_dw = (const float*)d_in[14]; exp_ln1_db = (const float*)d_in[15];
        exp_ln2_dw = (const float*)d_in[16]; exp_ln2_db = (const float*)d_in[17];
        exp_q_w    = (const float*)d_in[18]; exp_k_w    = (const float*)d_in[19];
        exp_v_w    = (const float*)d_in[20]; exp_o_w    = (const float*)d_in[21];
        exp_gate_w = (const float*)d_in[22]; exp_up_w   = (const float*)d_in[23];
        exp_down_w = (const float*)d_in[24];
    } else {
        embeds_vlm = (const float*)d_in[0];  embeds_exp = (const float*)d_in[1];
        cond       = (const float*)d_in[2];
        vlm_ln1_w  = (const float*)d_in[3];  vlm_ln2_w  = (const float*)d_in[4];
        vlm_q_w    = (const float*)d_in[5];  vlm_k_w    = (const float*)d_in[6];
        vlm_v_w    = (const float*)d_in[7];  vlm_o_w    = (const float*)d_in[8];
        vlm_gate_w = (const float*)d_in[9];  vlm_up_w   = (const float*)d_in[10];
        vlm_down_w = (const float*)d_in[11];
        exp_ln1_dw = (const float*)d_in[12]; exp_ln1_db = (const float*)d_in[13];
        exp_ln2_dw = (const float*)d_in[14]; exp_ln2_db = (const float*)d_in[15];
        exp_q_w    = (const float*)d_in[16]; exp_k_w    = (const float*)d_in[17];
        exp_v_w    = (const float*)d_in[18]; exp_o_w    = (const float*)d_in[19];
        exp_gate_w = (const float*)d_in[20]; exp_up_w   = (const float*)d_in[21];
        exp_down_w = (const float*)d_in[22];
        pos        = (const int*)  d_in[23];
        attn_mask  = (const float*)d_in[24];
    }

    __half *hv, *he, *q, *qt, *k, *v, *probs, *attnt, *attn, *mg, *eg, *wb;
    float *mod1, *mod2, *logits, *hv1, *he1, *mu, *eu;
    GETSYMH(hv, g_hv);   GETSYMH(he, g_he);   GETSYMF(mod1, g_mod1); GETSYMF(mod2, g_mod2);
    GETSYMH(q, g_q);     GETSYMH(qt, g_qt);   GETSYMH(k, g_k);       GETSYMH(v, g_v);
    GETSYMF(logits, g_logits); GETSYMH(probs, g_probs);
    GETSYMH(attnt, g_attnt);   GETSYMH(attn, g_attn);
    GETSYMF(hv1, g_hv1); GETSYMF(he1, g_he1);
    GETSYMH(mg, g_mg);   GETSYMF(mu, g_mu);
    GETSYMH(eg, g_eg);   GETSYMF(eu, g_eu);   GETSYMH(wb, g_wbuf);

    const long long n_vq = (long long)W_V_ * H_ * DH_;
    const float* srcs[NW] = {vlm_k_w, vlm_v_w, vlm_o_w, vlm_gate_w, vlm_up_w, vlm_down_w,
                             exp_q_w, exp_k_w, exp_v_w, exp_o_w, exp_gate_w, exp_up_w, exp_down_w};
    long long cnts[NW] = {
        (long long)W_V_*DH_, (long long)W_V_*DH_, (long long)H_*DH_*W_V_,
        (long long)W_V_*MLPV_, (long long)W_V_*MLPV_, (long long)MLPV_*W_V_,
        (long long)W_E_*H_*DH_, (long long)W_E_*DH_, (long long)W_E_*DH_, (long long)H_*DH_*W_E_,
        (long long)W_E_*MLPE_, (long long)W_E_*MLPE_, (long long)MLPE_*W_E_};
    RoundDesc rd;
    long long ofs = n_vq; int blk = 0;
    const __half* wptr[NW];
    for (int i = 0; i < NW; i++) {
        rd.src[i] = (const float4*)srcs[i];
        rd.dofs[i] = ofs;
        rd.blkStart[i] = blk;
        wptr[i] = wb + ofs;
        ofs += cnts[i];
        blk += (int)(cnts[i] / 4096);
    }
    rd.blkStart[NW] = blk;
    const __half* w_vq = wb;
    const __half *w_vk = wptr[0], *w_vv = wptr[1], *w_vo = wptr[2];
    const __half *w_vg = wptr[3], *w_vu = wptr[4], *w_vd = wptr[5];
    const __half *w_eq = wptr[6], *w_ek = wptr[7], *w_ev = wptr[8], *w_eo = wptr[9];
    const __half *w_egw = wptr[10], *w_euw = wptr[11], *w_ed = wptr[12];

    const int SMG = 4 * STGB;   // 75776 B
    const int SMT = 4 * STG1;   // 81920 B
    cudaFuncSetAttribute(gemm16<0>, cudaFuncAttributeMaxDynamicSharedMemorySize, SMG);
    cudaFuncSetAttribute(gemm16<1>, cudaFuncAttributeMaxDynamicSharedMemorySize, SMG);
    cudaFuncSetAttribute(gemm16<2>, cudaFuncAttributeMaxDynamicSharedMemorySize, SMG);
    cudaFuncSetAttribute(gemm16<3>, cudaFuncAttributeMaxDynamicSharedMemorySize, SMG);
    cudaFuncSetAttribute(gemm16<4>, cudaFuncAttributeMaxDynamicSharedMemorySize, SMG);
    cudaFuncSetAttribute(gemm16_tb1, cudaFuncAttributeMaxDynamicSharedMemorySize, SMT);

    float* out_v = (float*)d_out;
    float* out_e = (float*)d_out + (long long)B_ * S_V_ * W_V_;

    long long sHv = (long long)S_V_ * W_V_, sHe = (long long)S_E_ * W_E_;
    long long sQ = (long long)S_ * H_ * DH_, sK = (long long)S_ * DH_;
    long long sL = (long long)S_ * S_;

    // L0..L2
    round4<<<(int)((n_vq / 4 + 255) / 256), 256>>>((const float4*)vlm_q_w, (__half2*)wb, (int)(n_vq / 4));
    rms_scale<<<B_ * S_V_, 256>>>(embeds_vlm, vlm_ln1_w, hv, W_V_);
    modmm2<<<dim3(48, B_), 256>>>(cond, exp_ln1_dw, exp_ln1_db, mod1);
    // L3: VLM Q projection (ncu target)
    gemm16<0><<<dim3(16, 6, B_), 256, SMG>>>(hv, w_vq, q, nullptr, nullptr, S_V_, H_ * DH_, W_V_, sHv, 0, sQ, 1);
    // L4..L6
    round_many<<<blk, 256>>>(rd, wb);
    rms_mod<<<B_ * S_E_, 256>>>(embeds_exp, mod1, he, W_E_, S_E_);
    modmm2<<<dim3(48, B_), 256>>>(cond, exp_ln2_dw, exp_ln2_db, mod2);

    // QKV remainder
    gemm16<0><<<dim3(16, 1, B_), 256, SMG>>>(he, w_eq, q + (long long)S_V_ * H_ * DH_, nullptr, nullptr, S_E_, H_ * DH_, W_E_, sHe, 0, sQ, 1);
    gemm16<0><<<dim3(2, 6, B_), 256, SMG>>>(hv, w_vk, k, nullptr, nullptr, S_V_, DH_, W_V_, sHv, 0, sK, 1);
    gemm16<0><<<dim3(2, 1, B_), 256, SMG>>>(he, w_ek, k + S_V_ * DH_, nullptr, nullptr, S_E_, DH_, W_E_, sHe, 0, sK, 1);
    gemm16<0><<<dim3(2, 6, B_), 256, SMG>>>(hv, w_vv, v, nullptr, nullptr, S_V_, DH_, W_V_, sHv, 0, sK, 1);
    gemm16<0><<<dim3(2, 1, B_), 256, SMG>>>(he, w_ev, v + S_V_ * DH_, nullptr, nullptr, S_E_, DH_, W_E_, sHe, 0, sK, 1);

    // RoPE
    rope4h<<<(B_ * S_ * H_ * 32 + 255) / 256, 256>>>(q, pos, H_);
    rope4h<<<(B_ * S_ * 1 * 32 + 255) / 256, 256>>>(k, pos, 1);

    // attention
    {
        int nq8 = B_ * H_ * S_ * 32;
        q_to_bhsd8h<<<(nq8 + 255) / 256, 256>>>((const uint4*)q, (uint4*)qt);
        gemm16_tb1<<<dim3(7, 7, B_ * H_), 256, SMT>>>(qt, k, logits, S_, S_, DH_, sK, sK, sL, H_);
        softmax4h<<<B_ * H_ * S_, 256>>>(logits, attn_mask, probs);
        gemm16<0><<<dim3(2, 7, B_ * H_), 256, SMG>>>(probs, v, attnt, nullptr, nullptr, S_, DH_, S_, sL, sK, sK, H_);
        bhsd_to_bshd8h<<<(nq8 + 255) / 256, 256>>>((const uint4*)attnt, (uint4*)attn);
    }

    // output projections + residuals
    {
        long long sA = (long long)S_ * H_ * DH_;
        gemm16<3><<<dim3(16, 6, B_), 256, SMG>>>(attn, w_vo, hv1, embeds_vlm, nullptr, S_V_, W_V_, H_ * DH_, sA, 0, sHv, 1);
        gemm16<4><<<dim3(8, 1, B_), 256, SMG>>>(attn + (long long)S_V_ * H_ * DH_, w_eo, he1, embeds_exp, mod1, S_E_, W_E_, H_ * DH_, sA, 0, sHe, 1);
    }

    // pre-MLP norms
    rms_scale<<<B_ * S_V_, 256>>>(hv1, vlm_ln2_w, hv, W_V_);
    rms_mod<<<B_ * S_E_, 256>>>(he1, mod2, he, W_E_, S_E_);

    // VLM MLP
    {
        int M = B_ * S_V_;
        gemm16<1><<<dim3(128, 24, 1), 256, SMG>>>(hv, w_vu, mu, nullptr, nullptr, M, MLPV_, W_V_, 0, 0, 0, 1);
        gemm16<2><<<dim3(128, 24, 1), 256, SMG>>>(hv, w_vg, mg, mu, nullptr, M, MLPV_, W_V_, 0, 0, 0, 1);
        gemm16<3><<<dim3(16, 24, 1), 256, SMG>>>(mg, w_vd, out_v, hv1, nullptr, M, W_V_, MLPV_, 0, 0, 0, 1);
    }

    // expert MLP
    {
        int M = B_ * S_E_;
        gemm16<1><<<dim3(32, 2, 1), 256, SMG>>>(he, w_euw, eu, nullptr, nullptr, M, MLPE_, W_E_, 0, 0, 0, 1);
        gemm16<2><<<dim3(32, 2, 1), 256, SMG>>>(he, w_egw, eg, eu, nullptr, M, MLPE_, W_E_, 0, 0, 0, 1);
        gemm16<4><<<dim3(8, 2, 1), 256, SMG>>>(eg, w_ed, out_e, he1, mod2, M, W_E_, MLPE_, 0, 0, 0, 1);
    }
}

// round 8
// speedup vs baseline: 8.1448x; 1.0004x over previous
#include <cuda_runtime.h>
#include <cuda_fp16.h>
#include <cuda_bf16.h>
#include <math.h>

#define B_    4
#define S_V_  768
#define S_E_  64
#define S_    832
#define W_V_  2048
#define W_E_  1024
#define H_    8
#define DH_   256
#define MLPV_ 16384
#define MLPE_ 4096
#define EPS_  1e-6f
#define SCALE_ 0.0625f

// ---------------- scratch ----------------
__device__ __half g_hv   [B_*S_V_*W_V_];
__device__ __half g_he   [B_*S_E_*W_E_];
__device__ float  g_mod1 [B_*3*W_E_];
__device__ float  g_mod2 [B_*3*W_E_];
__device__ __half g_q    [(long long)B_*S_*H_*DH_];
__device__ __half g_qt   [(long long)B_*H_*S_*DH_];
__device__ __half g_k    [B_*S_*DH_];
__device__ __half g_v    [B_*S_*DH_];
__device__ float  g_logits[(long long)B_*H_*S_*S_];
__device__ __half g_probs[(long long)B_*H_*S_*S_];
__device__ __half g_attnt[(long long)B_*H_*S_*DH_];
__device__ __half g_attn [(long long)B_*S_*H_*DH_];
__device__ float  g_hv1  [B_*S_V_*W_V_];
__device__ float  g_he1  [B_*S_E_*W_E_];
__device__ __half g_mg   [(long long)B_*S_V_*MLPV_];
__device__ float  g_mu   [(long long)B_*S_V_*MLPV_];
__device__ __half g_eg   [B_*S_E_*MLPE_];
__device__ float  g_eu   [B_*S_E_*MLPE_];
__device__ __half g_wbuf [127401984];

__device__ __forceinline__ float gelu_t(float x) {
    return 0.5f * x * (1.f + tanhf(0.7978845608028654f * (x + 0.044715f * x * x * x)));
}

__device__ __forceinline__ void mma_f16(float* c, const unsigned* a, const unsigned* b) {
    asm volatile(
        "mma.sync.aligned.m16n8k16.row.col.f32.f16.f16.f32 "
        "{%0,%1,%2,%3}, {%4,%5,%6,%7}, {%8,%9}, {%0,%1,%2,%3};\n"
        : "+f"(c[0]), "+f"(c[1]), "+f"(c[2]), "+f"(c[3])
        : "r"(a[0]), "r"(a[1]), "r"(a[2]), "r"(a[3]), "r"(b[0]), "r"(b[1]));
}

// ============ gemm16: fp16 operands, fp32 accum, TB=0 ============
// A (M,K) halfs row-major; B (K,N) halfs row-major. K%32==0, N%8==0.
// Block 128x128, 8 warps (2m x 4n) of 64x32, K-tile 32, 4 cp.async stages.
// smem per stage: A [128][40]h (10240B) + B [32][136]h (8704B) = 18944B
// EPI: 0 plain->fp16, 1 plain->fp32, 2 fp16(gelu(c)*aux), 3 fp32(c+aux),
//      4 fp32(aux + c*mod[(z+gm/S_E)*3W_E+2W_E+gn])
#define ASTB 10240
#define STGB 18944
template<int EPI>
__global__ __launch_bounds__(256, 2)
void gemm16(const __half* __restrict__ A, const __half* __restrict__ Bm,
            void* __restrict__ Cv, const float* __restrict__ aux,
            const float* __restrict__ modv,
            int M, int N, int K,
            long long sA, long long sB, long long sC, int bInner)
{
    extern __shared__ __align__(16) char sm[];

    const int z = blockIdx.z;
    A  += (long long)z * sA;
    Bm += (long long)(z / bInner) * sB;

    const int tid  = threadIdx.x;
    const int lane = tid & 31;
    const int wid  = tid >> 5;
    const int wm   = (wid & 1) * 64;
    const int wn   = (wid >> 1) * 32;
    const int bm   = blockIdx.y * 128;
    const int bn   = blockIdx.x * 128;
    const int row  = lane >> 2, col = lane & 3;

    unsigned sbase = (unsigned)__cvta_generic_to_shared(sm);

    auto issue = [&](int st) {
        const int ktE = st * 32;
        const unsigned sb = sbase + (unsigned)((st & 3) * STGB);
#pragma unroll
        for (int j = 0; j < 2; j++) {            // A: 128 rows x 32 halfs
            int id = tid + j * 256;
            int r = id >> 2, c = id & 3;
            int gm = bm + r;
            const __half* gp = A + (long long)(gm < M ? gm : M - 1) * K + ktE + c * 8;
            unsigned dst = sb + (unsigned)(r * 80 + c * 16);
            int zf = (gm < M) ? 16 : 0;
            asm volatile("cp.async.cg.shared.global [%0], [%1], 16, %2;\n"
                         :: "r"(dst), "l"(gp), "r"(zf));
        }
#pragma unroll
        for (int j = 0; j < 2; j++) {            // B: 32 rows x 128 halfs
            int id = tid + j * 256;
            int kr = id >> 4, c = id & 15;
            int gn = bn + c * 8;
            const __half* gp = Bm + (long long)(ktE + kr) * N + (gn < N ? gn : N - 8);
            unsigned dst = sb + (unsigned)(ASTB + kr * 272 + c * 16);
            int zf = (gn < N) ? 16 : 0;
            asm volatile("cp.async.cg.shared.global [%0], [%1], 16, %2;\n"
                         :: "r"(dst), "l"(gp), "r"(zf));
        }
    };

    float c[4][4][4];
#pragma unroll
    for (int i = 0; i < 4; i++)
#pragma unroll
        for (int j = 0; j < 4; j++)
#pragma unroll
            for (int l = 0; l < 4; l++) c[i][j][l] = 0.f;

    // frag address precompute (within-stage offsets)
    const unsigned aoff = (unsigned)((((lane >> 3) & 1) * 8 + (lane & 7)) * 80 + (lane >> 4) * 16);
    const int l16 = lane & 15;
    const unsigned boff = (unsigned)(ASTB + ((l16 >> 3) * 8 + (l16 & 7)) * 272 + wn * 2);

    const int nk = K / 32;
#pragma unroll 1
    for (int s = 0; s < 3; s++) { issue(s); asm volatile("cp.async.commit_group;\n"); }

#pragma unroll 1
    for (int kt = 0; kt < nk; kt++) {
        asm volatile("cp.async.wait_group 2;\n");
        __syncthreads();
        if (kt + 3 < nk) issue(kt + 3);
        asm volatile("cp.async.commit_group;\n");

        const unsigned stg = sbase + (unsigned)((kt & 3) * STGB);
#pragma unroll
        for (int sub = 0; sub < 2; sub++) {
            unsigned af[4][4], bf[4][2];
#pragma unroll
            for (int mt = 0; mt < 4; mt++) {
                unsigned ad = stg + (unsigned)((wm + mt * 16) * 80 + sub * 32) + aoff;
                asm volatile("ldmatrix.sync.aligned.m8n8.x4.shared.b16 {%0,%1,%2,%3}, [%4];"
                             : "=r"(af[mt][0]), "=r"(af[mt][1]), "=r"(af[mt][2]), "=r"(af[mt][3])
                             : "r"(ad));
            }
#pragma unroll
            for (int nt = 0; nt < 4; nt++) {
                unsigned bd = stg + (unsigned)(sub * 16 * 272 + nt * 16) + boff;
                asm volatile("ldmatrix.sync.aligned.m8n8.x2.trans.shared.b16 {%0,%1}, [%2];"
                             : "=r"(bf[nt][0]), "=r"(bf[nt][1]) : "r"(bd));
            }
#pragma unroll
            for (int mt = 0; mt < 4; mt++)
#pragma unroll
                for (int nt = 0; nt < 4; nt++)
                    mma_f16(c[mt][nt], af[mt], bf[nt]);
        }
    }

    // epilogue
    if (EPI >= 2) aux += (long long)z * sC;
    __half* Ch = (__half*)Cv + (long long)z * sC;
    float*  Cf = (float*)Cv + (long long)z * sC;

    auto epi_store = [&](int gm, int gn, float x0, float x1) {
        long long o = (long long)gm * N + gn;
        if (EPI == 0) {
            *(__half2*)(Ch + o) = __halves2half2(__float2half_rn(x0), __float2half_rn(x1));
        } else if (EPI == 1) {
            *(float2*)(Cf + o) = make_float2(x0, x1);
        } else if (EPI == 2) {
            float2 u = *(const float2*)(aux + o);
            *(__half2*)(Ch + o) = __halves2half2(__float2half_rn(gelu_t(x0) * u.x),
                                                 __float2half_rn(gelu_t(x1) * u.y));
        } else if (EPI == 3) {
            float2 u = *(const float2*)(aux + o);
            *(float2*)(Cf + o) = make_float2(x0 + u.x, x1 + u.y);
        } else {
            int bb = z + gm / S_E_;
            float g0 = modv[(long long)bb * 3 * W_E_ + 2 * W_E_ + gn];
            float g1 = modv[(long long)bb * 3 * W_E_ + 2 * W_E_ + gn + 1];
            float2 u = *(const float2*)(aux + o);
            *(float2*)(Cf + o) = make_float2(u.x + x0 * g0, u.y + x1 * g1);
        }
    };

#pragma unroll
    for (int mt = 0; mt < 4; mt++) {
#pragma unroll
        for (int nt = 0; nt < 4; nt++) {
            int gm = bm + wm + mt * 16 + row;
            int gn = bn + wn + nt * 8 + col * 2;
            if (gn < N) {
                if (gm < M)     epi_store(gm,     gn, c[mt][nt][0], c[mt][nt][1]);
                if (gm + 8 < M) epi_store(gm + 8, gn, c[mt][nt][2], c[mt][nt][3]);
            }
        }
    }
}

// ============ gemm16_tb1: fp16, B (N,K) row-major, fp32 out ============
// smem per stage: A [128][40]h + B [128][40]h = 20480B, 4 stages
#define STG1 20480
__global__ __launch_bounds__(256, 2)
void gemm16_tb1(const __half* __restrict__ A, const __half* __restrict__ Bm,
                float* __restrict__ C, int M, int N, int K,
                long long sA, long long sB, long long sC, int bInner)
{
    extern __shared__ __align__(16) char sm[];

    const int z = blockIdx.z;
    A  += (long long)z * sA;
    Bm += (long long)(z / bInner) * sB;
    C  += (long long)z * sC;

    const int tid  = threadIdx.x;
    const int lane = tid & 31;
    const int wid  = tid >> 5;
    const int wm   = (wid & 1) * 64;
    const int wn   = (wid >> 1) * 32;
    const int bm   = blockIdx.y * 128;
    const int bn   = blockIdx.x * 128;
    const int row  = lane >> 2, col = lane & 3;

    unsigned sbase = (unsigned)__cvta_generic_to_shared(sm);

    auto issue = [&](int st) {
        const int ktE = st * 32;
        const unsigned sb = sbase + (unsigned)((st & 3) * STG1);
#pragma unroll
        for (int j = 0; j < 2; j++) {            // A
            int id = tid + j * 256;
            int r = id >> 2, c = id & 3;
            int gm = bm + r;
            const __half* gp = A + (long long)(gm < M ? gm : M - 1) * K + ktE + c * 8;
            unsigned dst = sb + (unsigned)(r * 80 + c * 16);
            int zf = (gm < M) ? 16 : 0;
            asm volatile("cp.async.cg.shared.global [%0], [%1], 16, %2;\n"
                         :: "r"(dst), "l"(gp), "r"(zf));
        }
#pragma unroll
        for (int j = 0; j < 2; j++) {            // B rows = n
            int id = tid + j * 256;
            int r = id >> 2, c = id & 3;
            int gn = bn + r;
            const __half* gp = Bm + (long long)(gn < N ? gn : N - 1) * K + ktE + c * 8;
            unsigned dst = sb + (unsigned)(ASTB + r * 80 + c * 16);
            int zf = (gn < N) ? 16 : 0;
            asm volatile("cp.async.cg.shared.global [%0], [%1], 16, %2;\n"
                         :: "r"(dst), "l"(gp), "r"(zf));
        }
    };

    float c[4][4][4];
#pragma unroll
    for (int i = 0; i < 4; i++)
#pragma unroll
        for (int j = 0; j < 4; j++)
#pragma unroll
            for (int l = 0; l < 4; l++) c[i][j][l] = 0.f;

    const unsigned aoff = (unsigned)((((lane >> 3) & 1) * 8 + (lane & 7)) * 80 + (lane >> 4) * 16);
    const int l16 = lane & 15;
    const unsigned boff = (unsigned)(ASTB + ((l16 & 7) + wn) * 80 + (l16 >> 3) * 16);

    const int nk = K / 32;
#pragma unroll 1
    for (int s = 0; s < 3; s++) { issue(s); asm volatile("cp.async.commit_group;\n"); }

#pragma unroll 1
    for (int kt = 0; kt < nk; kt++) {
        asm volatile("cp.async.wait_group 2;\n");
        __syncthreads();
        if (kt + 3 < nk) issue(kt + 3);
        asm volatile("cp.async.commit_group;\n");

        const unsigned stg = sbase + (unsigned)((kt & 3) * STG1);
#pragma unroll
        for (int sub = 0; sub < 2; sub++) {
            unsigned af[4][4], bf[4][2];
#pragma unroll
            for (int mt = 0; mt < 4; mt++) {
                unsigned ad = stg + (unsigned)((wm + mt * 16) * 80 + sub * 32) + aoff;
                asm volatile("ldmatrix.sync.aligned.m8n8.x4.shared.b16 {%0,%1,%2,%3}, [%4];"
                             : "=r"(af[mt][0]), "=r"(af[mt][1]), "=r"(af[mt][2]), "=r"(af[mt][3])
                             : "r"(ad));
            }
#pragma unroll
            for (int nt = 0; nt < 4; nt++) {
                unsigned bd = stg + (unsigned)(nt * 8 * 80 + sub * 32) + boff;
                asm volatile("ldmatrix.sync.aligned.m8n8.x2.shared.b16 {%0,%1}, [%2];"
                             : "=r"(bf[nt][0]), "=r"(bf[nt][1]) : "r"(bd));
            }
#pragma unroll
            for (int mt = 0; mt < 4; mt++)
#pragma unroll
                for (int nt = 0; nt < 4; nt++)
                    mma_f16(c[mt][nt], af[mt], bf[nt]);
        }
    }

#pragma unroll
    for (int mt = 0; mt < 4; mt++) {
#pragma unroll
        for (int nt = 0; nt < 4; nt++) {
            int gm = bm + wm + mt * 16 + row;
            int gn = bn + wn + nt * 8 + col * 2;
            if (gn < N) {
                if (gm < M)
                    *(float2*)(C + (long long)gm * N + gn) = make_float2(c[mt][nt][0], c[mt][nt][1]);
                if (gm + 8 < M)
                    *(float2*)(C + (long long)(gm + 8) * N + gn) = make_float2(c[mt][nt][2], c[mt][nt][3]);
            }
        }
    }
}

// ---------------- weight fp16 pre-convert ----------------
__global__ void round4(const float4* __restrict__ s, __half2* __restrict__ d, int n4)
{
    int i = blockIdx.x * 256 + threadIdx.x;
    if (i >= n4) return;
    float4 v = s[i];
    d[i * 2]     = __floats2half2_rn(v.x, v.y);
    d[i * 2 + 1] = __floats2half2_rn(v.z, v.w);
}

#define NW 13
struct RoundDesc {
    const float4* src[NW];
    long long dofs[NW];
    int blkStart[NW + 1];   // each block = 4096 floats
};

__global__ void round_many(RoundDesc d, __half* __restrict__ wbuf)
{
    int b = blockIdx.x;
    int w = 0;
#pragma unroll
    for (int i = 0; i < NW; i++) if (b >= d.blkStart[i + 1]) w = i + 1;
    int lb = b - d.blkStart[w];
    const float4* s = d.src[w] + (long long)lb * 1024;
    __half2* o = (__half2*)(wbuf + d.dofs[w]) + (long long)lb * 2048;
    int t = threadIdx.x;
#pragma unroll
    for (int i = 0; i < 4; i++) {
        float4 v = s[t + i * 256];
        o[(t + i * 256) * 2]     = __floats2half2_rn(v.x, v.y);
        o[(t + i * 256) * 2 + 1] = __floats2half2_rn(v.z, v.w);
    }
}

// ---------------- row kernels ----------------
__device__ __forceinline__ float blockReduceSum(float v) {
    __shared__ float red[256];
    int t = threadIdx.x;
    red[t] = v; __syncthreads();
    for (int s = 128; s > 0; s >>= 1) {
        if (t < s) red[t] += red[t + s];
        __syncthreads();
    }
    float r = red[0];
    __syncthreads();
    return r;
}

__global__ void rms_scale(const float* __restrict__ x, const float* __restrict__ w,
                          __half* __restrict__ out, int W)
{
    long long base = (long long)blockIdx.x * W;
    float ss = 0.f;
    for (int c = threadIdx.x; c < W; c += 256) { float t = x[base + c]; ss += t * t; }
    float tot = blockReduceSum(ss);
    float inv = rsqrtf(tot / (float)W + EPS_);
    for (int c = threadIdx.x; c < W; c += 256)
        out[base + c] = __float2half_rn(x[base + c] * inv * (1.f + w[c]));
}

__global__ void rms_mod(const float* __restrict__ x, const float* __restrict__ mod,
                        __half* __restrict__ out, int W, int rowsPerB)
{
    long long base = (long long)blockIdx.x * W;
    int b = blockIdx.x / rowsPerB;
    const float* m = mod + (long long)b * 3 * W;
    float ss = 0.f;
    for (int c = threadIdx.x; c < W; c += 256) { float t = x[base + c]; ss += t * t; }
    float tot = blockReduceSum(ss);
    float inv = rsqrtf(tot / (float)W + EPS_);
    for (int c = threadIdx.x; c < W; c += 256)
        out[base + c] = __float2half_rn(x[base + c] * inv * (1.f + m[c]) + m[W + c]);
}

__global__ void modmm2(const float* __restrict__ cond, const float* __restrict__ W,
                       const float* __restrict__ bias, float* __restrict__ out)
{
    const int NT = 3 * W_E_;
    __shared__ float cs[W_E_];
    __shared__ float part[4][64];
    int bb = blockIdx.y;
    int tid = threadIdx.x;
    for (int i = tid; i < W_E_; i += 256) cs[i] = cond[bb * W_E_ + i];
    __syncthreads();
    int tx = tid & 63, ty = tid >> 6;
    int c = blockIdx.x * 64 + tx;
    const float* Wp = W + (long long)(ty * 256) * NT + c;
    const float* cp = cs + ty * 256;
    float s = 0.f;
#pragma unroll 4
    for (int k = 0; k < 256; k++) s += cp[k] * Wp[(long long)k * NT];
    part[ty][tx] = s;
    __syncthreads();
    if (ty == 0)
        out[(long long)bb * NT + c] = part[0][tx] + part[1][tx] + part[2][tx] + part[3][tx] + bias[c];
}

// RoPE on fp16 x (B,S,nh,256), 4 halves per thread per half-dim
__global__ void rope4h(__half* __restrict__ x, const int* __restrict__ pos, int nh)
{
    int idx = blockIdx.x * blockDim.x + threadIdx.x;
    int total = B_ * S_ * nh * 32;
    if (idx >= total) return;
    int d4 = (idx & 31) << 2;
    int h = (idx >> 5) % nh;
    int s = (idx / (32 * nh)) % S_;
    int b = idx / (32 * nh * S_);
    float p = (float)pos[b * S_ + s];
    __half* base = x + (((long long)(b * S_ + s) * nh + h) << 8);
    __half2 x1a = *(__half2*)(base + d4),       x1b = *(__half2*)(base + d4 + 2);
    __half2 x2a = *(__half2*)(base + d4 + 128), x2b = *(__half2*)(base + d4 + 130);
    float r1[4] = {__low2float(x1a), __high2float(x1a), __low2float(x1b), __high2float(x1b)};
    float r2[4] = {__low2float(x2a), __high2float(x2a), __low2float(x2b), __high2float(x2b)};
#pragma unroll
    for (int j = 0; j < 4; j++) {
        float ang = p * powf(10000.f, -(float)(2 * (d4 + j)) / 256.f);
        float sn, cs2; sincosf(ang, &sn, &cs2);
        float a = r1[j], bb = r2[j];
        r1[j] = a * cs2 - bb * sn;
        r2[j] = bb * cs2 + a * sn;
    }
    *(__half2*)(base + d4)       = __floats2half2_rn(r1[0], r1[1]);
    *(__half2*)(base + d4 + 2)   = __floats2half2_rn(r1[2], r1[3]);
    *(__half2*)(base + d4 + 128) = __floats2half2_rn(r2[0], r2[1]);
    *(__half2*)(base + d4 + 130) = __floats2half2_rn(r2[2], r2[3]);
}

// (B,S,H,256) -> (B,H,S,256), 8 halves/thread
__global__ void q_to_bhsd8h(const uint4* __restrict__ q, uint4* __restrict__ qt)
{
    int idx = blockIdx.x * blockDim.x + threadIdx.x;
    int total = B_ * H_ * S_ * 32;
    if (idx >= total) return;
    int d = idx & 31;
    int s = (idx >> 5) % S_;
    int h = (idx / (32 * S_)) % H_;
    int b = idx / (32 * S_ * H_);
    qt[idx] = q[(((b * S_ + s) * H_ + h) * 32) + d];
}

// (B,H,S,256) -> (B,S,H,256)
__global__ void bhsd_to_bshd8h(const uint4* __restrict__ a, uint4* __restrict__ o)
{
    int idx = blockIdx.x * blockDim.x + threadIdx.x;
    int total = B_ * S_ * H_ * 32;
    if (idx >= total) return;
    int d = idx & 31;
    int h = (idx >> 5) % H_;
    int s = (idx / (32 * H_)) % S_;
    int b = idx / (32 * H_ * S_);
    o[idx] = a[(((b * H_ + h) * S_ + s) * 32) + d];
}

// softmax: logits fp32 -> probs fp16
__global__ void softmax4h(const float* __restrict__ logits, const float* __restrict__ mask,
                          __half* __restrict__ probs)
{
    int rowid = blockIdx.x;
    int b = rowid / (H_ * S_);
    int q = rowid % S_;
    const float4* row = (const float4*)(logits + (long long)rowid * S_);
    const float4* m = (const float4*)(mask + ((long long)b * S_ + q) * S_);
    __half* prow = probs + (long long)rowid * S_;
    int t = threadIdx.x;
    const bool act = t < 208;
    float4 v = make_float4(-1e30f, -1e30f, -1e30f, -1e30f);
    if (act) {
        float4 lv = row[t], mv = m[t];
        v.x = lv.x * SCALE_ + mv.x; v.y = lv.y * SCALE_ + mv.y;
        v.z = lv.z * SCALE_ + mv.z; v.w = lv.w * SCALE_ + mv.w;
    }
    float mx = fmaxf(fmaxf(v.x, v.y), fmaxf(v.z, v.w));
    __shared__ float red[256];
    red[t] = mx; __syncthreads();
    for (int s = 128; s > 0; s >>= 1) { if (t < s) red[t] = fmaxf(red[t], red[t + s]); __syncthreads(); }
    mx = red[0]; __syncthreads();
    float sum = 0.f;
    if (act) {
        v.x = __expf(v.x - mx); v.y = __expf(v.y - mx);
        v.z = __expf(v.z - mx); v.w = __expf(v.w - mx);
        sum = v.x + v.y + v.z + v.w;
    }
    red[t] = sum; __syncthreads();
    for (int s = 128; s > 0; s >>= 1) { if (t < s) red[t] += red[t + s]; __syncthreads(); }
    float inv = 1.f / red[0];
    if (act) {
        *(__half2*)(prow + t * 4)     = __floats2half2_rn(v.x * inv, v.y * inv);
        *(__half2*)(prow + t * 4 + 2) = __floats2half2_rn(v.z * inv, v.w * inv);
    }
}

// ---------------- host launch ----------------
#define GETSYMF(var, sym) do { void* p__; cudaGetSymbolAddress(&p__, sym); var = (float*)p__; } while (0)
#define GETSYMH(var, sym) do { void* p__; cudaGetSymbolAddress(&p__, sym); var = (__half*)p__; } while (0)

extern "C" void kernel_launch(void* const* d_in, const int* in_sizes, int n_in,
                              void* d_out, int out_size)
{
    const float *embeds_vlm, *embeds_exp, *cond, *attn_mask;
    const int* pos;
    const float *vlm_ln1_w, *vlm_ln2_w, *vlm_q_w, *vlm_k_w, *vlm_v_w, *vlm_o_w;
    const float *vlm_gate_w, *vlm_up_w, *vlm_down_w;
    const float *exp_ln1_dw, *exp_ln1_db, *exp_ln2_dw, *exp_ln2_db;
    const float *exp_q_w, *exp_k_w, *exp_v_w, *exp_o_w, *exp_gate_w, *exp_up_w, *exp_down_w;

    if (in_sizes[3] == B_ * S_) {
        embeds_vlm = (const float*)d_in[0];  embeds_exp = (const float*)d_in[1];
        cond       = (const float*)d_in[2];  pos        = (const int*)  d_in[3];
        attn_mask  = (const float*)d_in[4];
        vlm_ln1_w  = (const float*)d_in[5];  vlm_ln2_w  = (const float*)d_in[6];
        vlm_q_w    = (const float*)d_in[7];  vlm_k_w    = (const float*)d_in[8];
        vlm_v_w    = (const float*)d_in[9];  vlm_o_w    = (const float*)d_in[10];
        vlm_gate_w = (const float*)d_in[11]; vlm_up_w   = (const float*)d_in[12];
        vlm_down_w = (const float*)d_in[13];
        exp_ln1_dw = (const float*)d_in[14]; exp_ln1_db = (const float*)d_in[15];
        exp_ln2_dw = (const float*)d_in[16]; exp_ln2_db = (const float*)d_in[17];
        exp_q_w    = (const float*)d_in[18]; exp_k_w    = (const float*)d_in[19];
        exp_v_w    = (const float*)d_in[20]; exp_o_w    = (const float*)d_in[21];
        exp_gate_w = (const float*)d_in[22]; exp_up_w   = (const float*)d_in[23];
        exp_down_w = (const float*)d_in[24];
    } else {
        embeds_vlm = (const float*)d_in[0];  embeds_exp = (const float*)d_in[1];
        cond       = (const float*)d_in[2];
        vlm_ln1_w  = (const float*)d_in[3];  vlm_ln2_w  = (const float*)d_in[4];
        vlm_q_w    = (const float*)d_in[5];  vlm_k_w    = (const float*)d_in[6];
        vlm_v_w    = (const float*)d_in[7];  vlm_o_w    = (const float*)d_in[8];
        vlm_gate_w = (const float*)d_in[9];  vlm_up_w   = (const float*)d_in[10];
        vlm_down_w = (const float*)d_in[11];
        exp_ln1_dw = (const float*)d_in[12]; exp_ln1_db = (const float*)d_in[13];
        exp_ln2_dw = (const float*)d_in[14]; exp_ln2_db = (const float*)d_in[15];
        exp_q_w    = (const float*)d_in[16]; exp_k_w    = (const float*)d_in[17];
        exp_v_w    = (const float*)d_in[18]; exp_o_w    = (const float*)d_in[19];
        exp_gate_w = (const float*)d_in[20]; exp_up_w   = (const float*)d_in[21];
        exp_down_w = (const float*)d_in[22];
        pos        = (const int*)  d_in[23];
        attn_mask  = (const float*)d_in[24];
    }

    __half *hv, *he, *q, *qt, *k, *v, *probs, *attnt, *attn, *mg, *eg, *wb;
    float *mod1, *mod2, *logits, *hv1, *he1, *mu, *eu;
    GETSYMH(hv, g_hv);   GETSYMH(he, g_he);   GETSYMF(mod1, g_mod1); GETSYMF(mod2, g_mod2);
    GETSYMH(q, g_q);     GETSYMH(qt, g_qt);   GETSYMH(k, g_k);       GETSYMH(v, g_v);
    GETSYMF(logits, g_logits); GETSYMH(probs, g_probs);
    GETSYMH(attnt, g_attnt);   GETSYMH(attn, g_attn);
    GETSYMF(hv1, g_hv1); GETSYMF(he1, g_he1);
    GETSYMH(mg, g_mg);   GETSYMF(mu, g_mu);
    GETSYMH(eg, g_eg);   GETSYMF(eu, g_eu);   GETSYMH(wb, g_wbuf);

    const long long n_vq = (long long)W_V_ * H_ * DH_;
    const float* srcs[NW] = {vlm_k_w, vlm_v_w, vlm_o_w, vlm_gate_w, vlm_up_w, vlm_down_w,
                             exp_q_w, exp_k_w, exp_v_w, exp_o_w, exp_gate_w, exp_up_w, exp_down_w};
    long long cnts[NW] = {
        (long long)W_V_*DH_, (long long)W_V_*DH_, (long long)H_*DH_*W_V_,
        (long long)W_V_*MLPV_, (long long)W_V_*MLPV_, (long long)MLPV_*W_V_,
        (long long)W_E_*H_*DH_, (long long)W_E_*DH_, (long long)W_E_*DH_, (long long)H_*DH_*W_E_,
        (long long)W_E_*MLPE_, (long long)W_E_*MLPE_, (long long)MLPE_*W_E_};
    RoundDesc rd;
    long long ofs = n_vq; int blk = 0;
    const __half* wptr[NW];
    for (int i = 0; i < NW; i++) {
        rd.src[i] = (const float4*)srcs[i];
        rd.dofs[i] = ofs;
        rd.blkStart[i] = blk;
        wptr[i] = wb + ofs;
        ofs += cnts[i];
        blk += (int)(cnts[i] / 4096);
    }
    rd.blkStart[NW] = blk;
    const __half* w_vq = wb;
    const __half *w_vk = wptr[0], *w_vv = wptr[1], *w_vo = wptr[2];
    const __half *w_vg = wptr[3], *w_vu = wptr[4], *w_vd = wptr[5];
    const __half *w_eq = wptr[6], *w_ek = wptr[7], *w_ev = wptr[8], *w_eo = wptr[9];
    const __half *w_egw = wptr[10], *w_euw = wptr[11], *w_ed = wptr[12];

    const int SMG = 4 * STGB;   // 75776 B
    const int SMT = 4 * STG1;   // 81920 B
    cudaFuncSetAttribute(gemm16<0>, cudaFuncAttributeMaxDynamicSharedMemorySize, SMG);
    cudaFuncSetAttribute(gemm16<1>, cudaFuncAttributeMaxDynamicSharedMemorySize, SMG);
    cudaFuncSetAttribute(gemm16<2>, cudaFuncAttributeMaxDynamicSharedMemorySize, SMG);
    cudaFuncSetAttribute(gemm16<3>, cudaFuncAttributeMaxDynamicSharedMemorySize, SMG);
    cudaFuncSetAttribute(gemm16<4>, cudaFuncAttributeMaxDynamicSharedMemorySize, SMG);
    cudaFuncSetAttribute(gemm16_tb1, cudaFuncAttributeMaxDynamicSharedMemorySize, SMT);

    float* out_v = (float*)d_out;
    float* out_e = (float*)d_out + (long long)B_ * S_V_ * W_V_;

    long long sHv = (long long)S_V_ * W_V_, sHe = (long long)S_E_ * W_E_;
    long long sQ = (long long)S_ * H_ * DH_, sK = (long long)S_ * DH_;
    long long sL = (long long)S_ * S_;

    // L0..L2
    round4<<<(int)((n_vq / 4 + 255) / 256), 256>>>((const float4*)vlm_q_w, (__half2*)wb, (int)(n_vq / 4));
    rms_scale<<<B_ * S_V_, 256>>>(embeds_vlm, vlm_ln1_w, hv, W_V_);
    modmm2<<<dim3(48, B_), 256>>>(cond, exp_ln1_dw, exp_ln1_db, mod1);
    // L3: VLM Q projection (ncu target)
    gemm16<0><<<dim3(16, 6, B_), 256, SMG>>>(hv, w_vq, q, nullptr, nullptr, S_V_, H_ * DH_, W_V_, sHv, 0, sQ, 1);
    // L4..L6
    round_many<<<blk, 256>>>(rd, wb);
    rms_mod<<<B_ * S_E_, 256>>>(embeds_exp, mod1, he, W_E_, S_E_);
    modmm2<<<dim3(48, B_), 256>>>(cond, exp_ln2_dw, exp_ln2_db, mod2);

    // QKV remainder
    gemm16<0><<<dim3(16, 1, B_), 256, SMG>>>(he, w_eq, q + (long long)S_V_ * H_ * DH_, nullptr, nullptr, S_E_, H_ * DH_, W_E_, sHe, 0, sQ, 1);
    gemm16<0><<<dim3(2, 6, B_), 256, SMG>>>(hv, w_vk, k, nullptr, nullptr, S_V_, DH_, W_V_, sHv, 0, sK, 1);
    gemm16<0><<<dim3(2, 1, B_), 256, SMG>>>(he, w_ek, k + S_V_ * DH_, nullptr, nullptr, S_E_, DH_, W_E_, sHe, 0, sK, 1);
    gemm16<0><<<dim3(2, 6, B_), 256, SMG>>>(hv, w_vv, v, nullptr, nullptr, S_V_, DH_, W_V_, sHv, 0, sK, 1);
    gemm16<0><<<dim3(2, 1, B_), 256, SMG>>>(he, w_ev, v + S_V_ * DH_, nullptr, nullptr, S_E_, DH_, W_E_, sHe, 0, sK, 1);

    // RoPE
    rope4h<<<(B_ * S_ * H_ * 32 + 255) / 256, 256>>>(q, pos, H_);
    rope4h<<<(B_ * S_ * 1 * 32 + 255) / 256, 256>>>(k, pos, 1);

    // attention
    {
        int nq8 = B_ * H_ * S_ * 32;
        q_to_bhsd8h<<<(nq8 + 255) / 256, 256>>>((const uint4*)q, (uint4*)qt);
        gemm16_tb1<<<dim3(7, 7, B_ * H_), 256, SMT>>>(qt, k, logits, S_, S_, DH_, sK, sK, sL, H_);
        softmax4h<<<B_ * H_ * S_, 256>>>(logits, attn_mask, probs);
        gemm16<0><<<dim3(2, 7, B_ * H_), 256, SMG>>>(probs, v, attnt, nullptr, nullptr, S_, DH_, S_, sL, sK, sK, H_);
        bhsd_to_bshd8h<<<(nq8 + 255) / 256, 256>>>((const uint4*)attnt, (uint4*)attn);
    }

    // output projections + residuals
    {
        long long sA = (long long)S_ * H_ * DH_;
        gemm16<3><<<dim3(16, 6, B_), 256, SMG>>>(attn, w_vo, hv1, embeds_vlm, nullptr, S_V_, W_V_, H_ * DH_, sA, 0, sHv, 1);
        gemm16<4><<<dim3(8, 1, B_), 256, SMG>>>(attn + (long long)S_V_ * H_ * DH_, w_eo, he1, embeds_exp, mod1, S_E_, W_E_, H_ * DH_, sA, 0, sHe, 1);
    }

    // pre-MLP norms
    rms_scale<<<B_ * S_V_, 256>>>(hv1, vlm_ln2_w, hv, W_V_);
    rms_mod<<<B_ * S_E_, 256>>>(he1, mod2, he, W_E_, S_E_);

    // VLM MLP
    {
        int M = B_ * S_V_;
        gemm16<1><<<dim3(128, 24, 1), 256, SMG>>>(hv, w_vu, mu, nullptr, nullptr, M, MLPV_, W_V_, 0, 0, 0, 1);
        gemm16<2><<<dim3(128, 24, 1), 256, SMG>>>(hv, w_vg, mg, mu, nullptr, M, MLPV_, W_V_, 0, 0, 0, 1);
        gemm16<3><<<dim3(16, 24, 1), 256, SMG>>>(mg, w_vd, out_v, hv1, nullptr, M, W_V_, MLPV_, 0, 0, 0, 1);
    }

    // expert MLP
    {
        int M = B_ * S_E_;
        gemm16<1><<<dim3(32, 2, 1), 256, SMG>>>(he, w_euw, eu, nullptr, nullptr, M, MLPE_, W_E_, 0, 0, 0, 1);
        gemm16<2><<<dim3(32, 2, 1), 256, SMG>>>(he, w_egw, eg, eu, nullptr, M, MLPE_, W_E_, 0, 0, 0, 1);
        gemm16<4><<<dim3(8, 2, 1), 256, SMG>>>(eg, w_ed, out_e, he1, mod2, M, W_E_, MLPE_, 0, 0, 0, 1);
    }
}